// round 1
// baseline (speedup 1.0000x reference)
#include <cuda_runtime.h>
#include <math.h>

#define B_  4
#define NQ_ 100
#define HW_ 4096
#define D_  1024
#define H_  16
#define HD_ 64
#define NEG_ (-1e9f)

// ---------------- scratch (device globals; no runtime allocation) ----------------
__device__ float g_qn [B_ * NQ_ * D_];          // 400 x 1024
__device__ float g_kvn[B_ * HW_ * D_];          // 16384 x 1024
__device__ float g_qp [B_ * NQ_ * D_];          // 400 x 1024
__device__ float g_kvp[(size_t)B_ * HW_ * 2 * D_]; // 16384 x 2048 (k | v)
__device__ float g_ctx[B_ * NQ_ * D_];          // 400 x 1024
__device__ int   g_has[B_ * NQ_];               // per (b,q): any allowed key

// ---------------- layernorm: one block per row, D=1024, 256 threads ----------------
__global__ __launch_bounds__(256) void ln_kernel(
    const float* __restrict__ x, const float* __restrict__ g,
    const float* __restrict__ b, float* __restrict__ y)
{
    __shared__ float red[32];
    int row = blockIdx.x;
    int tid = threadIdx.x;
    const float* xr = x + (size_t)row * D_;

    float v[4];
#pragma unroll
    for (int i = 0; i < 4; i++) v[i] = xr[tid + 256 * i];

    // --- mean ---
    float s = v[0] + v[1] + v[2] + v[3];
#pragma unroll
    for (int o = 16; o > 0; o >>= 1) s += __shfl_xor_sync(0xffffffffu, s, o);
    if ((tid & 31) == 0) red[tid >> 5] = s;
    __syncthreads();
    float t = (tid < 8) ? red[tid] : 0.f;
    if (tid < 32) {
#pragma unroll
        for (int o = 4; o > 0; o >>= 1) t += __shfl_xor_sync(0xffffffffu, t, o);
        if (tid == 0) red[0] = t;
    }
    __syncthreads();
    float mu = red[0] * (1.0f / D_);
    __syncthreads();

    // --- variance of (x - mu) ---
    float sq = 0.f;
#pragma unroll
    for (int i = 0; i < 4; i++) { float d = v[i] - mu; sq += d * d; }
#pragma unroll
    for (int o = 16; o > 0; o >>= 1) sq += __shfl_xor_sync(0xffffffffu, sq, o);
    if ((tid & 31) == 0) red[tid >> 5] = sq;
    __syncthreads();
    float t2 = (tid < 8) ? red[tid] : 0.f;
    if (tid < 32) {
#pragma unroll
        for (int o = 4; o > 0; o >>= 1) t2 += __shfl_xor_sync(0xffffffffu, t2, o);
        if (tid == 0) red[0] = t2;
    }
    __syncthreads();
    float var = red[0] * (1.0f / D_);
    float inv = rsqrtf(var + 1e-5f);

    float* yr = y + (size_t)row * D_;
#pragma unroll
    for (int i = 0; i < 4; i++) {
        int c = tid + 256 * i;
        yr[c] = (v[i] - mu) * inv * g[c] + b[c];
    }
}

// ---------------- has_any: OR-reduce one mask row per block ----------------
__global__ __launch_bounds__(256) void has_kernel(
    const int* __restrict__ mask, int* __restrict__ has)
{
    int row = blockIdx.x;  // b*NQ + q
    int tid = threadIdx.x;
    const int* mr = mask + (size_t)row * HW_;
    int any = 0;
#pragma unroll
    for (int i = 0; i < HW_ / 256; i++) any |= mr[tid + 256 * i];
    int r = __syncthreads_or(any);
    if (tid == 0) has[row] = (r != 0);
}

// ---------------- SGEMM: C[m,n] = sum_k A[m,k]*W[n,k] + bias[n] ----------------
// A: [M,K] row-major, W: [N,K] row-major, C: [M,N]. BM=BN=128, BK=8, 256 thr, 8x8/thr.
__global__ __launch_bounds__(256) void gemm_bias(
    const float* __restrict__ A, const float* __restrict__ W,
    const float* __restrict__ bias, float* __restrict__ C,
    int M, int N, int K)
{
    __shared__ float As[8][128];
    __shared__ float Bs[8][128];

    int tid = threadIdx.x;
    int tx = tid & 15;       // 0..15 -> N sub-tile
    int ty = tid >> 4;       // 0..15 -> M sub-tile
    int row0 = blockIdx.y * 128;
    int col0 = blockIdx.x * 128;

    int la_row = tid >> 1;          // 0..127
    int la_seg = (tid & 1) * 4;     // 0 or 4

    float acc[8][8];
#pragma unroll
    for (int i = 0; i < 8; i++)
#pragma unroll
        for (int j = 0; j < 8; j++) acc[i][j] = 0.f;

    const float* Wp = W + (size_t)(col0 + la_row) * K + la_seg;

    for (int k0 = 0; k0 < K; k0 += 8) {
        // load A tile (guard M)
        int ar = row0 + la_row;
        float4 av = make_float4(0.f, 0.f, 0.f, 0.f);
        if (ar < M) av = *(const float4*)(A + (size_t)ar * K + k0 + la_seg);
        As[la_seg + 0][la_row] = av.x;
        As[la_seg + 1][la_row] = av.y;
        As[la_seg + 2][la_row] = av.z;
        As[la_seg + 3][la_row] = av.w;
        // load W tile (N is always a multiple of 128 here)
        float4 wv = *(const float4*)(Wp + k0);
        Bs[la_seg + 0][la_row] = wv.x;
        Bs[la_seg + 1][la_row] = wv.y;
        Bs[la_seg + 2][la_row] = wv.z;
        Bs[la_seg + 3][la_row] = wv.w;
        __syncthreads();

#pragma unroll
        for (int k = 0; k < 8; k++) {
            float4 a0 = *(const float4*)&As[k][ty * 8];
            float4 a1 = *(const float4*)&As[k][ty * 8 + 4];
            float4 b0 = *(const float4*)&Bs[k][tx * 8];
            float4 b1 = *(const float4*)&Bs[k][tx * 8 + 4];
            float ar8[8] = {a0.x, a0.y, a0.z, a0.w, a1.x, a1.y, a1.z, a1.w};
            float br8[8] = {b0.x, b0.y, b0.z, b0.w, b1.x, b1.y, b1.z, b1.w};
#pragma unroll
            for (int i = 0; i < 8; i++)
#pragma unroll
                for (int j = 0; j < 8; j++) acc[i][j] += ar8[i] * br8[j];
        }
        __syncthreads();
    }

    int c0 = col0 + tx * 8;
    float4 bb0 = *(const float4*)&bias[c0];
    float4 bb1 = *(const float4*)&bias[c0 + 4];
#pragma unroll
    for (int i = 0; i < 8; i++) {
        int r = row0 + ty * 8 + i;
        if (r < M) {
            float4 o0 = make_float4(acc[i][0] + bb0.x, acc[i][1] + bb0.y,
                                    acc[i][2] + bb0.z, acc[i][3] + bb0.w);
            float4 o1 = make_float4(acc[i][4] + bb1.x, acc[i][5] + bb1.y,
                                    acc[i][6] + bb1.z, acc[i][7] + bb1.w);
            *(float4*)(C + (size_t)r * N + c0)     = o0;
            *(float4*)(C + (size_t)r * N + c0 + 4) = o1;
        }
    }
}

// ---------------- flash attention ----------------
// grid: (B*H, 4 q-tiles of 25). 128 threads. Key tile = 128.
// kvp layout: row = b*HW + k, cols [h*64 .. ] = K-proj, [1024 + h*64 ..] = V-proj.
#define QT 25
#define KT 128
#define KPAD 65
#define SPAD 129

__global__ __launch_bounds__(128) void attn_kernel(
    const float* __restrict__ qp, const float* __restrict__ kvp,
    const int* __restrict__ mask, const int* __restrict__ has_any,
    float* __restrict__ ctx)
{
    extern __shared__ float sm[];
    float* q_s  = sm;                       // QT * 64
    float* k_s  = q_s + QT * 64;            // KT * KPAD
    float* v_s  = k_s + KT * KPAD;          // KT * 64
    float* s_s  = v_s + KT * 64;            // QT * SPAD
    float* m_s  = s_s + QT * SPAD;          // QT running max
    float* l_s  = m_s + QT;                 // QT running sum
    float* al_s = l_s + QT;                 // QT alpha

    int bh = blockIdx.x;
    int b = bh >> 4;
    int h = bh & 15;
    int q0 = blockIdx.y * QT;
    int tid = threadIdx.x;

    // load Q tile: QT rows x 64
    for (int i = tid; i < QT * 16; i += 128) {
        int qr = i >> 4, seg = (i & 15) * 4;
        float4 v = *(const float4*)(qp + ((size_t)(b * NQ_ + q0 + qr) * D_) + h * HD_ + seg);
        *(float4*)&q_s[qr * 64 + seg] = v;
    }
    if (tid < QT) { m_s[tid] = -INFINITY; l_s[tid] = 0.f; }
    __syncthreads();

    // ctx ownership: qg = tid/16 (8 groups), d0 = (tid%16)*4
    int qg = tid >> 4;
    int d0 = (tid & 15) * 4;
    float acc[4][4];
#pragma unroll
    for (int qi = 0; qi < 4; qi++)
#pragma unroll
        for (int j = 0; j < 4; j++) acc[qi][j] = 0.f;

    for (int k0 = 0; k0 < HW_; k0 += KT) {
        // load K/V tiles
        for (int i = tid; i < KT * 16; i += 128) {
            int kr = i >> 4, seg = (i & 15) * 4;
            const float* base = kvp + ((size_t)(b * HW_ + k0 + kr) * (2 * D_)) + h * HD_ + seg;
            float4 kk = *(const float4*)base;
            k_s[kr * KPAD + seg + 0] = kk.x;
            k_s[kr * KPAD + seg + 1] = kk.y;
            k_s[kr * KPAD + seg + 2] = kk.z;
            k_s[kr * KPAD + seg + 3] = kk.w;
            float4 vv = *(const float4*)(base + D_);
            *(float4*)&v_s[kr * 64 + seg] = vv;
        }
        __syncthreads();

        // scores: thread t owns key column k0+t
        {
            float kreg[64];
#pragma unroll
            for (int d = 0; d < 64; d++) kreg[d] = k_s[tid * KPAD + d];
            const int* mrow = mask + (size_t)(b * NQ_ + q0) * HW_ + k0 + tid;
            for (int q = 0; q < QT; q++) {
                float d0a = 0.f, d1a = 0.f, d2a = 0.f, d3a = 0.f;
#pragma unroll
                for (int s16 = 0; s16 < 16; s16 += 4) {
                    float4 qa = *(const float4*)&q_s[q * 64 + s16 * 4];
                    d0a += qa.x * kreg[s16 * 4 + 0]; d0a += qa.y * kreg[s16 * 4 + 1];
                    d0a += qa.z * kreg[s16 * 4 + 2]; d0a += qa.w * kreg[s16 * 4 + 3];
                    float4 qb = *(const float4*)&q_s[q * 64 + s16 * 4 + 4];
                    d1a += qb.x * kreg[s16 * 4 + 4]; d1a += qb.y * kreg[s16 * 4 + 5];
                    d1a += qb.z * kreg[s16 * 4 + 6]; d1a += qb.w * kreg[s16 * 4 + 7];
                    float4 qc = *(const float4*)&q_s[q * 64 + s16 * 4 + 8];
                    d2a += qc.x * kreg[s16 * 4 + 8];  d2a += qc.y * kreg[s16 * 4 + 9];
                    d2a += qc.z * kreg[s16 * 4 + 10]; d2a += qc.w * kreg[s16 * 4 + 11];
                    float4 qd = *(const float4*)&q_s[q * 64 + s16 * 4 + 12];
                    d3a += qd.x * kreg[s16 * 4 + 12]; d3a += qd.y * kreg[s16 * 4 + 13];
                    d3a += qd.z * kreg[s16 * 4 + 14]; d3a += qd.w * kreg[s16 * 4 + 15];
                }
                float dot = (d0a + d1a) + (d2a + d3a);
                float sc = dot * 0.125f;  // 1/sqrt(64)
                int gq = b * NQ_ + q0 + q;
                int mval = mrow[(size_t)q * HW_];
                if (has_any[gq] && !mval) sc = NEG_;
                s_s[q * SPAD + tid] = sc;
            }
        }
        __syncthreads();

        // online softmax: one row per thread (threads 0..QT-1)
        if (tid < QT) {
            int q = tid;
            float mold = m_s[q];
            float mt = mold;
#pragma unroll 8
            for (int k = 0; k < KT; k++) mt = fmaxf(mt, s_s[q * SPAD + k]);
            float alpha = __expf(mold - mt);
            float sum = 0.f;
#pragma unroll 8
            for (int k = 0; k < KT; k++) {
                float e = __expf(s_s[q * SPAD + k] - mt);
                s_s[q * SPAD + k] = e;
                sum += e;
            }
            m_s[q] = mt;
            l_s[q] = l_s[q] * alpha + sum;
            al_s[q] = alpha;
        }
        __syncthreads();

        // rescale + accumulate ctx
#pragma unroll
        for (int qi = 0; qi < 4; qi++) {
            int q = qg + qi * 8;
            if (q < QT) {
                float a = al_s[q];
#pragma unroll
                for (int j = 0; j < 4; j++) acc[qi][j] *= a;
            }
        }
        for (int k = 0; k < KT; k++) {
            float4 vv = *(const float4*)&v_s[k * 64 + d0];
#pragma unroll
            for (int qi = 0; qi < 4; qi++) {
                int q = qg + qi * 8;
                if (q < QT) {
                    float p = s_s[q * SPAD + k];
                    acc[qi][0] += p * vv.x;
                    acc[qi][1] += p * vv.y;
                    acc[qi][2] += p * vv.z;
                    acc[qi][3] += p * vv.w;
                }
            }
        }
        __syncthreads();
    }

    // epilogue
#pragma unroll
    for (int qi = 0; qi < 4; qi++) {
        int q = qg + qi * 8;
        if (q < QT) {
            float inv = 1.f / l_s[q];
            float* dst = ctx + ((size_t)(b * NQ_ + q0 + q) * D_) + h * HD_ + d0;
            float4 o = make_float4(acc[qi][0] * inv, acc[qi][1] * inv,
                                   acc[qi][2] * inv, acc[qi][3] * inv);
            *(float4*)dst = o;
        }
    }
}

// ---------------- launch ----------------
extern "C" void kernel_launch(void* const* d_in, const int* in_sizes, int n_in,
                              void* d_out, int out_size)
{
    const float* q    = (const float*)d_in[0];
    const float* kv   = (const float*)d_in[1];
    const int*   mask = (const int*)  d_in[2];
    const float* ipw  = (const float*)d_in[3];
    const float* ipb  = (const float*)d_in[4];
    const float* ow   = (const float*)d_in[5];
    const float* ob   = (const float*)d_in[6];
    const float* gq   = (const float*)d_in[7];
    const float* bq   = (const float*)d_in[8];
    const float* gkv  = (const float*)d_in[9];
    const float* bkv  = (const float*)d_in[10];
    float* out = (float*)d_out;

    float *p_qn, *p_kvn, *p_qp, *p_kvp, *p_ctx;
    int* p_has;
    cudaGetSymbolAddress((void**)&p_qn,  g_qn);
    cudaGetSymbolAddress((void**)&p_kvn, g_kvn);
    cudaGetSymbolAddress((void**)&p_qp,  g_qp);
    cudaGetSymbolAddress((void**)&p_kvp, g_kvp);
    cudaGetSymbolAddress((void**)&p_ctx, g_ctx);
    cudaGetSymbolAddress((void**)&p_has, g_has);

    // layernorms
    ln_kernel<<<B_ * NQ_, 256>>>(q, gq, bq, p_qn);
    ln_kernel<<<B_ * HW_, 256>>>(kv, gkv, bkv, p_kvn);
    has_kernel<<<B_ * NQ_, 256>>>(mask, p_has);

    // projections
    gemm_bias<<<dim3(1024 / 128, (B_ * NQ_ + 127) / 128), 256>>>(
        p_qn, ipw, ipb, p_qp, B_ * NQ_, D_, D_);
    gemm_bias<<<dim3(2048 / 128, (B_ * HW_) / 128), 256>>>(
        p_kvn, ipw + (size_t)D_ * D_, ipb + D_, p_kvp, B_ * HW_, 2 * D_, D_);

    // attention
    size_t attn_smem = (QT * 64 + KT * KPAD + KT * 64 + QT * SPAD + 3 * QT) * sizeof(float);
    cudaFuncSetAttribute(attn_kernel, cudaFuncAttributeMaxDynamicSharedMemorySize,
                         (int)attn_smem);
    attn_kernel<<<dim3(B_ * H_, NQ_ / QT), 128, attn_smem>>>(
        p_qp, p_kvp, mask, p_has, p_ctx);

    // output projection
    gemm_bias<<<dim3(1024 / 128, (B_ * NQ_ + 127) / 128), 256>>>(
        p_ctx, ow, ob, out, B_ * NQ_, D_, D_);
}

// round 4
// speedup vs baseline: 1.9712x; 1.9712x over previous
#include <cuda_runtime.h>
#include <cuda_bf16.h>
#include <math.h>
#include <stdint.h>

#define B_  4
#define NQ_ 100
#define HW_ 4096
#define D_  1024
#define H_  16
#define HD_ 64
#define NEG_ (-1e9f)

// ---------------- scratch (device globals; no runtime allocation) ----------------
__device__ __nv_bfloat16 g_qn_hi [400  * 1024];
__device__ __nv_bfloat16 g_qn_lo [400  * 1024];
__device__ __nv_bfloat16 g_kvn_hi[16384 * 1024];
__device__ __nv_bfloat16 g_kvn_lo[16384 * 1024];
__device__ __nv_bfloat16 g_w_hi  [3072 * 1024];
__device__ __nv_bfloat16 g_w_lo  [3072 * 1024];
__device__ __nv_bfloat16 g_ow_hi [1024 * 1024];
__device__ __nv_bfloat16 g_ow_lo [1024 * 1024];
__device__ __nv_bfloat16 g_cx_hi [400  * 1024];
__device__ __nv_bfloat16 g_cx_lo [400  * 1024];
__device__ float g_qp [400 * 1024];
__device__ float g_kvp[(size_t)16384 * 2048];   // per row: [K proj 1024 | V proj 1024]
__device__ float g_ctx[400 * 1024];
__device__ int   g_has[400];

// ---------------- helpers ----------------
__device__ __forceinline__ uint32_t smem_u32(const void* p) {
    uint32_t a;
    asm("{ .reg .u64 t; cvta.to.shared.u64 t, %1; cvt.u32.u64 %0, t; }" : "=r"(a) : "l"(p));
    return a;
}
__device__ __forceinline__ void cp16(uint32_t dst, const void* src, int nbytes) {
    asm volatile("cp.async.cg.shared.global [%0], [%1], 16, %2;"
                 :: "r"(dst), "l"(src), "r"(nbytes));
}
#define CP_COMMIT() asm volatile("cp.async.commit_group;" ::: "memory")
#define CP_WAIT1()  asm volatile("cp.async.wait_group 1;" ::: "memory")
#define CP_WAIT0()  asm volatile("cp.async.wait_group 0;" ::: "memory")

#define LDMX4(r0, r1, r2, r3, addr) \
    asm volatile("ldmatrix.sync.aligned.m8n8.x4.shared.b16 {%0,%1,%2,%3}, [%4];" \
                 : "=r"(r0), "=r"(r1), "=r"(r2), "=r"(r3) : "r"(addr))

#define MMA16816(c, a, b) \
    asm volatile("mma.sync.aligned.m16n8k16.row.col.f32.bf16.bf16.f32 " \
                 "{%0,%1,%2,%3}, {%4,%5,%6,%7}, {%8,%9}, {%0,%1,%2,%3};" \
                 : "+f"((c)[0]), "+f"((c)[1]), "+f"((c)[2]), "+f"((c)[3]) \
                 : "r"((a)[0]), "r"((a)[1]), "r"((a)[2]), "r"((a)[3]), \
                   "r"((b)[0]), "r"((b)[1]))

// ---------------- layernorm + bf16 hi/lo split: one block per row ----------------
__global__ __launch_bounds__(256) void ln_split_kernel(
    const float* __restrict__ x, const float* __restrict__ g,
    const float* __restrict__ b,
    __nv_bfloat16* __restrict__ hi, __nv_bfloat16* __restrict__ lo)
{
    __shared__ float red[32];
    int row = blockIdx.x;
    int tid = threadIdx.x;
    const float* xr = x + (size_t)row * D_;

    float v[4];
#pragma unroll
    for (int i = 0; i < 4; i++) v[i] = xr[tid + 256 * i];

    float s = v[0] + v[1] + v[2] + v[3];
#pragma unroll
    for (int o = 16; o > 0; o >>= 1) s += __shfl_xor_sync(0xffffffffu, s, o);
    if ((tid & 31) == 0) red[tid >> 5] = s;
    __syncthreads();
    float t = (tid < 8) ? red[tid] : 0.f;
    if (tid < 32) {
#pragma unroll
        for (int o = 4; o > 0; o >>= 1) t += __shfl_xor_sync(0xffffffffu, t, o);
        if (tid == 0) red[0] = t;
    }
    __syncthreads();
    float mu = red[0] * (1.0f / D_);
    __syncthreads();

    float sq = 0.f;
#pragma unroll
    for (int i = 0; i < 4; i++) { float d = v[i] - mu; sq += d * d; }
#pragma unroll
    for (int o = 16; o > 0; o >>= 1) sq += __shfl_xor_sync(0xffffffffu, sq, o);
    if ((tid & 31) == 0) red[tid >> 5] = sq;
    __syncthreads();
    float t2 = (tid < 8) ? red[tid] : 0.f;
    if (tid < 32) {
#pragma unroll
        for (int o = 4; o > 0; o >>= 1) t2 += __shfl_xor_sync(0xffffffffu, t2, o);
        if (tid == 0) red[0] = t2;
    }
    __syncthreads();
    float var = red[0] * (1.0f / D_);
    float inv = rsqrtf(var + 1e-5f);

#pragma unroll
    for (int i = 0; i < 4; i++) {
        int c = tid + 256 * i;
        float y = (v[i] - mu) * inv * g[c] + b[c];
        __nv_bfloat16 h = __float2bfloat16(y);
        hi[(size_t)row * D_ + c] = h;
        lo[(size_t)row * D_ + c] = __float2bfloat16(y - __bfloat162float(h));
    }
}

// ---------------- fp32 -> bf16 hi/lo split ----------------
__global__ __launch_bounds__(256) void split_kernel(
    const float* __restrict__ x,
    __nv_bfloat16* __restrict__ hi, __nv_bfloat16* __restrict__ lo, int n4)
{
    int i = blockIdx.x * 256 + threadIdx.x;
    if (i >= n4) return;
    float4 v = ((const float4*)x)[i];
    __nv_bfloat16 h0 = __float2bfloat16(v.x);
    __nv_bfloat16 h1 = __float2bfloat16(v.y);
    __nv_bfloat16 h2 = __float2bfloat16(v.z);
    __nv_bfloat16 h3 = __float2bfloat16(v.w);
    __nv_bfloat162 hp0; hp0.x = h0; hp0.y = h1;
    __nv_bfloat162 hp1; hp1.x = h2; hp1.y = h3;
    __nv_bfloat162 lp0;
    lp0.x = __float2bfloat16(v.x - __bfloat162float(h0));
    lp0.y = __float2bfloat16(v.y - __bfloat162float(h1));
    __nv_bfloat162 lp1;
    lp1.x = __float2bfloat16(v.z - __bfloat162float(h2));
    lp1.y = __float2bfloat16(v.w - __bfloat162float(h3));
    ((__nv_bfloat162*)hi)[i * 2]     = hp0;
    ((__nv_bfloat162*)hi)[i * 2 + 1] = hp1;
    ((__nv_bfloat162*)lo)[i * 2]     = lp0;
    ((__nv_bfloat162*)lo)[i * 2 + 1] = lp1;
}

// ---------------- has_any: OR-reduce one mask row per block ----------------
__global__ __launch_bounds__(256) void has_kernel(
    const int* __restrict__ mask, int* __restrict__ has)
{
    int row = blockIdx.x;
    int tid = threadIdx.x;
    const int* mr = mask + (size_t)row * HW_;
    int any = 0;
#pragma unroll
    for (int i = 0; i < HW_ / 256; i++) any |= mr[tid + 256 * i];
    int r = __syncthreads_or(any);
    if (tid == 0) has[row] = (r != 0);
}

// ---------------- mma.sync GEMM: C[m,n] = sum_k A[m,k]*W[n,k] + bias[n] ----------------
// A,W pre-split into bf16 hi/lo, K = 1024. 3 passes (hh + hl + lh) fused in k-loop.
// BM=128, BN=128, BK=32. 8 warps (4 along M x 2 along N), warp tile 32x64.
#define GLD   40                        // padded smem row length (bf16 elems)
#define G_ARR (128 * GLD * 2)           // 10240 bytes per array
#define G_BUF (4 * G_ARR)               // Ahi, Alo, Bhi, Blo
#define GEMM_SMEM (2 * G_BUF)           // 81920
#define NCHUNK 32                       // 1024 / 32

__global__ __launch_bounds__(256) void gemm_mma(
    const __nv_bfloat16* __restrict__ Ahi, const __nv_bfloat16* __restrict__ Alo,
    const __nv_bfloat16* __restrict__ Bhi, const __nv_bfloat16* __restrict__ Blo,
    const float* __restrict__ bias, float* __restrict__ C, int M, int Ntot)
{
    extern __shared__ char sm[];
    uint32_t smb = smem_u32(sm);
    int tid = threadIdx.x;
    int wid = tid >> 5, lane = tid & 31;
    int wm = wid & 3, wn = wid >> 2;       // warp grid 4 x 2
    int row0 = blockIdx.y * 128;
    int col0 = blockIdx.x * 128;

    float acc[2][8][4];
#pragma unroll
    for (int a = 0; a < 2; a++)
#pragma unroll
        for (int b = 0; b < 8; b++)
#pragma unroll
            for (int c = 0; c < 4; c++) acc[a][b][c] = 0.f;

    // per-thread load coords: 2 iters x (row = idx/4, 16B seg = idx%4)
    int r_a = tid >> 2, seg = (tid & 3);

    // ---- chunk loader (cp.async) ----
    auto load_chunk = [&](int c, int buf) {
        uint32_t base = smb + buf * G_BUF;
#pragma unroll
        for (int it = 0; it < 2; it++) {
            int r = r_a + it * 64;
            int gr = row0 + r;
            uint32_t dst = base + (uint32_t)(r * 80 + seg * 16);
            int nb = (gr < M) ? 16 : 0;
            const __nv_bfloat16* sh = Ahi + (size_t)gr * 1024 + c * 32 + seg * 8;
            const __nv_bfloat16* sl = Alo + (size_t)gr * 1024 + c * 32 + seg * 8;
            cp16(dst, sh, nb);
            cp16(dst + G_ARR, sl, nb);
        }
#pragma unroll
        for (int it = 0; it < 2; it++) {
            int r = r_a + it * 64;
            int gr = col0 + r;
            uint32_t dst = base + 2 * G_ARR + (uint32_t)(r * 80 + seg * 16);
            cp16(dst,         Bhi + (size_t)gr * 1024 + c * 32 + seg * 8, 16);
            cp16(dst + G_ARR, Blo + (size_t)gr * 1024 + c * 32 + seg * 8, 16);
        }
    };

    load_chunk(0, 0);
    CP_COMMIT();

    for (int c = 0; c < NCHUNK; c++) {
        if (c + 1 < NCHUNK) {
            load_chunk(c + 1, (c + 1) & 1);
            CP_COMMIT();
            CP_WAIT1();
        } else {
            CP_WAIT0();
        }
        __syncthreads();

        uint32_t aBase = smb + (c & 1) * G_BUF;
        uint32_t bBase = aBase + 2 * G_ARR;
        int g = lane >> 3, ln = lane & 7;

#pragma unroll
        for (int s = 0; s < 2; s++) {
            int kc = s * 16;
            uint32_t ah[2][4], al[2][4], bh[8][2], bl[8][2];
#pragma unroll
            for (int mt = 0; mt < 2; mt++) {
                int row = wm * 32 + mt * 16 + (g & 1) * 8 + ln;
                int col = kc + (g >> 1) * 8;
                uint32_t addr = aBase + (uint32_t)(row * 80 + col * 2);
                LDMX4(ah[mt][0], ah[mt][1], ah[mt][2], ah[mt][3], addr);
                LDMX4(al[mt][0], al[mt][1], al[mt][2], al[mt][3], addr + G_ARR);
            }
#pragma unroll
            for (int np = 0; np < 4; np++) {
                int nrow = wn * 64 + np * 16 + (g >> 1) * 8 + ln;
                int col = kc + (g & 1) * 8;
                uint32_t addr = bBase + (uint32_t)(nrow * 80 + col * 2);
                LDMX4(bh[np * 2][0], bh[np * 2][1], bh[np * 2 + 1][0], bh[np * 2 + 1][1], addr);
                LDMX4(bl[np * 2][0], bl[np * 2][1], bl[np * 2 + 1][0], bl[np * 2 + 1][1], addr + G_ARR);
            }
#pragma unroll
            for (int mt = 0; mt < 2; mt++)
#pragma unroll
                for (int nt = 0; nt < 8; nt++) {
                    MMA16816(acc[mt][nt], ah[mt], bh[nt]);
                    MMA16816(acc[mt][nt], ah[mt], bl[nt]);
                    MMA16816(acc[mt][nt], al[mt], bh[nt]);
                }
        }
        __syncthreads();
    }

    // ---- epilogue: direct stores with bias ----
    int qrow = lane >> 2, qcol = (lane & 3) * 2;
    int cbase = col0 + wn * 64;
#pragma unroll
    for (int mt = 0; mt < 2; mt++) {
#pragma unroll
        for (int half = 0; half < 2; half++) {
            int r = row0 + wm * 32 + mt * 16 + qrow + half * 8;
            if (r < M) {
                float* crow = C + (size_t)r * Ntot + cbase;
#pragma unroll
                for (int nt = 0; nt < 8; nt++) {
                    int cix = nt * 8 + qcol;
                    float2 bv = *(const float2*)&bias[cbase + cix];
                    float2 o;
                    o.x = acc[mt][nt][half * 2 + 0] + bv.x;
                    o.y = acc[mt][nt][half * 2 + 1] + bv.y;
                    *(float2*)&crow[cix] = o;
                }
            }
        }
    }
}

// ---------------- flash attention (unchanged) ----------------
#define QT 25
#define KT 128
#define KPAD 65
#define SPAD 129

__global__ __launch_bounds__(128) void attn_kernel(
    const float* __restrict__ qp, const float* __restrict__ kvp,
    const int* __restrict__ mask, const int* __restrict__ has_any,
    float* __restrict__ ctx)
{
    extern __shared__ float smf[];
    float* q_s  = smf;
    float* k_s  = q_s + QT * 64;
    float* v_s  = k_s + KT * KPAD;
    float* s_s  = v_s + KT * 64;
    float* m_s  = s_s + QT * SPAD;
    float* l_s  = m_s + QT;
    float* al_s = l_s + QT;

    int bh = blockIdx.x;
    int b = bh >> 4;
    int h = bh & 15;
    int q0 = blockIdx.y * QT;
    int tid = threadIdx.x;

    for (int i = tid; i < QT * 16; i += 128) {
        int qr = i >> 4, seg = (i & 15) * 4;
        float4 v = *(const float4*)(qp + ((size_t)(b * NQ_ + q0 + qr) * D_) + h * HD_ + seg);
        *(float4*)&q_s[qr * 64 + seg] = v;
    }
    if (tid < QT) { m_s[tid] = -INFINITY; l_s[tid] = 0.f; }
    __syncthreads();

    int qg = tid >> 4;
    int d0 = (tid & 15) * 4;
    float acc[4][4];
#pragma unroll
    for (int qi = 0; qi < 4; qi++)
#pragma unroll
        for (int j = 0; j < 4; j++) acc[qi][j] = 0.f;

    for (int k0 = 0; k0 < HW_; k0 += KT) {
        for (int i = tid; i < KT * 16; i += 128) {
            int kr = i >> 4, seg = (i & 15) * 4;
            const float* base = kvp + ((size_t)(b * HW_ + k0 + kr) * (2 * D_)) + h * HD_ + seg;
            float4 kk = *(const float4*)base;
            k_s[kr * KPAD + seg + 0] = kk.x;
            k_s[kr * KPAD + seg + 1] = kk.y;
            k_s[kr * KPAD + seg + 2] = kk.z;
            k_s[kr * KPAD + seg + 3] = kk.w;
            float4 vv = *(const float4*)(base + D_);
            *(float4*)&v_s[kr * 64 + seg] = vv;
        }
        __syncthreads();

        {
            float kreg[64];
#pragma unroll
            for (int d = 0; d < 64; d++) kreg[d] = k_s[tid * KPAD + d];
            const int* mrow = mask + (size_t)(b * NQ_ + q0) * HW_ + k0 + tid;
            for (int q = 0; q < QT; q++) {
                float d0a = 0.f, d1a = 0.f, d2a = 0.f, d3a = 0.f;
#pragma unroll
                for (int s16 = 0; s16 < 16; s16 += 4) {
                    float4 qa = *(const float4*)&q_s[q * 64 + s16 * 4];
                    d0a += qa.x * kreg[s16 * 4 + 0]; d0a += qa.y * kreg[s16 * 4 + 1];
                    d0a += qa.z * kreg[s16 * 4 + 2]; d0a += qa.w * kreg[s16 * 4 + 3];
                    float4 qb = *(const float4*)&q_s[q * 64 + s16 * 4 + 4];
                    d1a += qb.x * kreg[s16 * 4 + 4]; d1a += qb.y * kreg[s16 * 4 + 5];
                    d1a += qb.z * kreg[s16 * 4 + 6]; d1a += qb.w * kreg[s16 * 4 + 7];
                    float4 qc = *(const float4*)&q_s[q * 64 + s16 * 4 + 8];
                    d2a += qc.x * kreg[s16 * 4 + 8];  d2a += qc.y * kreg[s16 * 4 + 9];
                    d2a += qc.z * kreg[s16 * 4 + 10]; d2a += qc.w * kreg[s16 * 4 + 11];
                    float4 qd = *(const float4*)&q_s[q * 64 + s16 * 4 + 12];
                    d3a += qd.x * kreg[s16 * 4 + 12]; d3a += qd.y * kreg[s16 * 4 + 13];
                    d3a += qd.z * kreg[s16 * 4 + 14]; d3a += qd.w * kreg[s16 * 4 + 15];
                }
                float dot = (d0a + d1a) + (d2a + d3a);
                float sc = dot * 0.125f;
                int gq = b * NQ_ + q0 + q;
                int mval = mrow[(size_t)q * HW_];
                if (has_any[gq] && !mval) sc = NEG_;
                s_s[q * SPAD + tid] = sc;
            }
        }
        __syncthreads();

        if (tid < QT) {
            int q = tid;
            float mold = m_s[q];
            float mt = mold;
#pragma unroll 8
            for (int k = 0; k < KT; k++) mt = fmaxf(mt, s_s[q * SPAD + k]);
            float alpha = __expf(mold - mt);
            float sum = 0.f;
#pragma unroll 8
            for (int k = 0; k < KT; k++) {
                float e = __expf(s_s[q * SPAD + k] - mt);
                s_s[q * SPAD + k] = e;
                sum += e;
            }
            m_s[q] = mt;
            l_s[q] = l_s[q] * alpha + sum;
            al_s[q] = alpha;
        }
        __syncthreads();

#pragma unroll
        for (int qi = 0; qi < 4; qi++) {
            int q = qg + qi * 8;
            if (q < QT) {
                float a = al_s[q];
#pragma unroll
                for (int j = 0; j < 4; j++) acc[qi][j] *= a;
            }
        }
        for (int k = 0; k < KT; k++) {
            float4 vv = *(const float4*)&v_s[k * 64 + d0];
#pragma unroll
            for (int qi = 0; qi < 4; qi++) {
                int q = qg + qi * 8;
                if (q < QT) {
                    float p = s_s[q * SPAD + k];
                    acc[qi][0] += p * vv.x;
                    acc[qi][1] += p * vv.y;
                    acc[qi][2] += p * vv.z;
                    acc[qi][3] += p * vv.w;
                }
            }
        }
        __syncthreads();
    }

#pragma unroll
    for (int qi = 0; qi < 4; qi++) {
        int q = qg + qi * 8;
        if (q < QT) {
            float inv = 1.f / l_s[q];
            float* dst = ctx + ((size_t)(b * NQ_ + q0 + q) * D_) + h * HD_ + d0;
            float4 o = make_float4(acc[qi][0] * inv, acc[qi][1] * inv,
                                   acc[qi][2] * inv, acc[qi][3] * inv);
            *(float4*)dst = o;
        }
    }
}

// ---------------- launch ----------------
extern "C" void kernel_launch(void* const* d_in, const int* in_sizes, int n_in,
                              void* d_out, int out_size)
{
    const float* q    = (const float*)d_in[0];
    const float* kv   = (const float*)d_in[1];
    const int*   mask = (const int*)  d_in[2];
    const float* ipw  = (const float*)d_in[3];
    const float* ipb  = (const float*)d_in[4];
    const float* ow   = (const float*)d_in[5];
    const float* ob   = (const float*)d_in[6];
    const float* gq   = (const float*)d_in[7];
    const float* bq   = (const float*)d_in[8];
    const float* gkv  = (const float*)d_in[9];
    const float* bkv  = (const float*)d_in[10];
    float* out = (float*)d_out;

    __nv_bfloat16 *p_qn_hi, *p_qn_lo, *p_kvn_hi, *p_kvn_lo;
    __nv_bfloat16 *p_w_hi, *p_w_lo, *p_ow_hi, *p_ow_lo, *p_cx_hi, *p_cx_lo;
    float *p_qp, *p_kvp, *p_ctx;
    int* p_has;
    cudaGetSymbolAddress((void**)&p_qn_hi,  g_qn_hi);
    cudaGetSymbolAddress((void**)&p_qn_lo,  g_qn_lo);
    cudaGetSymbolAddress((void**)&p_kvn_hi, g_kvn_hi);
    cudaGetSymbolAddress((void**)&p_kvn_lo, g_kvn_lo);
    cudaGetSymbolAddress((void**)&p_w_hi,   g_w_hi);
    cudaGetSymbolAddress((void**)&p_w_lo,   g_w_lo);
    cudaGetSymbolAddress((void**)&p_ow_hi,  g_ow_hi);
    cudaGetSymbolAddress((void**)&p_ow_lo,  g_ow_lo);
    cudaGetSymbolAddress((void**)&p_cx_hi,  g_cx_hi);
    cudaGetSymbolAddress((void**)&p_cx_lo,  g_cx_lo);
    cudaGetSymbolAddress((void**)&p_qp,  g_qp);
    cudaGetSymbolAddress((void**)&p_kvp, g_kvp);
    cudaGetSymbolAddress((void**)&p_ctx, g_ctx);
    cudaGetSymbolAddress((void**)&p_has, g_has);

    cudaFuncSetAttribute(gemm_mma, cudaFuncAttributeMaxDynamicSharedMemorySize, GEMM_SMEM);
    size_t attn_smem = (QT * 64 + KT * KPAD + KT * 64 + QT * SPAD + 3 * QT) * sizeof(float);
    cudaFuncSetAttribute(attn_kernel, cudaFuncAttributeMaxDynamicSharedMemorySize,
                         (int)attn_smem);

    // layernorm + split
    ln_split_kernel<<<B_ * NQ_, 256>>>(q, gq, bq, p_qn_hi, p_qn_lo);
    ln_split_kernel<<<B_ * HW_, 256>>>(kv, gkv, bkv, p_kvn_hi, p_kvn_lo);
    has_kernel<<<B_ * NQ_, 256>>>(mask, p_has);

    // weight splits
    split_kernel<<<(3072 * 1024 / 4 + 255) / 256, 256>>>(ipw, p_w_hi, p_w_lo, 3072 * 1024 / 4);
    split_kernel<<<(1024 * 1024 / 4 + 255) / 256, 256>>>(ow, p_ow_hi, p_ow_lo, 1024 * 1024 / 4);

    // q projection: [400,1024] @ Wq^T -> [400,1024]
    gemm_mma<<<dim3(1024 / 128, (B_ * NQ_ + 127) / 128), 256, GEMM_SMEM>>>(
        p_qn_hi, p_qn_lo, p_w_hi, p_w_lo, ipb, p_qp, B_ * NQ_, 1024);

    // kv projection: [16384,1024] @ [Wk;Wv]^T -> [16384,2048]
    gemm_mma<<<dim3(2048 / 128, (B_ * HW_) / 128), 256, GEMM_SMEM>>>(
        p_kvn_hi, p_kvn_lo,
        p_w_hi + (size_t)1024 * 1024, p_w_lo + (size_t)1024 * 1024,
        ipb + 1024, p_kvp, B_ * HW_, 2048);

    // attention
    attn_kernel<<<dim3(B_ * H_, NQ_ / QT), 128, attn_smem>>>(
        p_qp, p_kvp, mask, p_has, p_ctx);

    // ctx split + output projection
    split_kernel<<<(400 * 1024 / 4 + 255) / 256, 256>>>(p_ctx, p_cx_hi, p_cx_lo, 400 * 1024 / 4);
    gemm_mma<<<dim3(1024 / 128, (B_ * NQ_ + 127) / 128), 256, GEMM_SMEM>>>(
        p_cx_hi, p_cx_lo, p_ow_hi, p_ow_lo, ob, out, B_ * NQ_, 1024);
}

// round 8
// speedup vs baseline: 3.2610x; 1.6543x over previous
#include <cuda_runtime.h>
#include <cuda_bf16.h>
#include <math.h>
#include <stdint.h>

#define B_  4
#define NQ_ 100
#define HW_ 4096
#define D_  1024
#define H_  16
#define HD_ 64
#define NEG_ (-1e9f)
#define ASPLIT 2
#define KEYS_PER_SPLIT (HW_ / ASPLIT)   // 2048
#define NT_PER_SPLIT   (KEYS_PER_SPLIT / 128)  // 16

// ---------------- scratch (device globals; no runtime allocation) ----------------
__device__ __nv_bfloat16 g_qn_hi [400  * 1024];
__device__ __nv_bfloat16 g_qn_lo [400  * 1024];
__device__ __nv_bfloat16 g_kvn_hi[16384 * 1024];
__device__ __nv_bfloat16 g_kvn_lo[16384 * 1024];
__device__ __nv_bfloat16 g_w_hi  [3072 * 1024];
__device__ __nv_bfloat16 g_w_lo  [3072 * 1024];
__device__ __nv_bfloat16 g_ow_hi [1024 * 1024];
__device__ __nv_bfloat16 g_ow_lo [1024 * 1024];
// head-major projections: [b*16+h][rows][64]
__device__ __nv_bfloat16 g_qhi[64 * 128 * 64];
__device__ __nv_bfloat16 g_qlo[64 * 128 * 64];
__device__ __nv_bfloat16 g_khi[(size_t)64 * 4096 * 64];
__device__ __nv_bfloat16 g_klo[(size_t)64 * 4096 * 64];
__device__ __nv_bfloat16 g_vhi[(size_t)64 * 4096 * 64];
__device__ __nv_bfloat16 g_vlo[(size_t)64 * 4096 * 64];
__device__ __nv_bfloat16 g_cx_hi[400 * 1024];
__device__ __nv_bfloat16 g_cx_lo[400 * 1024];
__device__ uint32_t g_bits[400 * 128];
__device__ float g_pm[ASPLIT * 64 * 128];
__device__ float g_pl[ASPLIT * 64 * 128];
__device__ float g_pO[(size_t)ASPLIT * 64 * 128 * 64];

// ---------------- helpers ----------------
__device__ __forceinline__ uint32_t smem_u32(const void* p) {
    uint32_t a;
    asm("{ .reg .u64 t; cvta.to.shared.u64 t, %1; cvt.u32.u64 %0, t; }" : "=r"(a) : "l"(p));
    return a;
}
__device__ __forceinline__ void cp16(uint32_t dst, const void* src, int nbytes) {
    asm volatile("cp.async.cg.shared.global [%0], [%1], 16, %2;"
                 :: "r"(dst), "l"(src), "r"(nbytes));
}
#define CP_COMMIT() asm volatile("cp.async.commit_group;" ::: "memory")
#define CP_WAIT1()  asm volatile("cp.async.wait_group 1;" ::: "memory")
#define CP_WAIT0()  asm volatile("cp.async.wait_group 0;" ::: "memory")

#define LDMX4(r0, r1, r2, r3, addr) \
    asm volatile("ldmatrix.sync.aligned.m8n8.x4.shared.b16 {%0,%1,%2,%3}, [%4];" \
                 : "=r"(r0), "=r"(r1), "=r"(r2), "=r"(r3) : "r"(addr))
#define LDMX4T(r0, r1, r2, r3, addr) \
    asm volatile("ldmatrix.sync.aligned.m8n8.x4.trans.shared.b16 {%0,%1,%2,%3}, [%4];" \
                 : "=r"(r0), "=r"(r1), "=r"(r2), "=r"(r3) : "r"(addr))

#define MMA16816(c, a, b) \
    asm volatile("mma.sync.aligned.m16n8k16.row.col.f32.bf16.bf16.f32 " \
                 "{%0,%1,%2,%3}, {%4,%5,%6,%7}, {%8,%9}, {%0,%1,%2,%3};" \
                 : "+f"((c)[0]), "+f"((c)[1]), "+f"((c)[2]), "+f"((c)[3]) \
                 : "r"((a)[0]), "r"((a)[1]), "r"((a)[2]), "r"((a)[3]), \
                   "r"((b)[0]), "r"((b)[1]))

__device__ __forceinline__ uint32_t pack_bf16x2(float lo_el, float hi_el) {
    uint32_t r;
    asm("cvt.rn.bf16x2.f32 %0, %1, %2;" : "=r"(r) : "f"(hi_el), "f"(lo_el));
    return r;
}

// ---------------- layernorm + bf16 hi/lo split ----------------
__global__ __launch_bounds__(256) void ln_split_kernel(
    const float* __restrict__ x, const float* __restrict__ g,
    const float* __restrict__ b,
    __nv_bfloat16* __restrict__ hi, __nv_bfloat16* __restrict__ lo)
{
    __shared__ float red[32];
    int row = blockIdx.x;
    int tid = threadIdx.x;
    const float* xr = x + (size_t)row * D_;

    float v[4];
#pragma unroll
    for (int i = 0; i < 4; i++) v[i] = xr[tid + 256 * i];

    float s = v[0] + v[1] + v[2] + v[3];
#pragma unroll
    for (int o = 16; o > 0; o >>= 1) s += __shfl_xor_sync(0xffffffffu, s, o);
    if ((tid & 31) == 0) red[tid >> 5] = s;
    __syncthreads();
    float t = (tid < 8) ? red[tid] : 0.f;
    if (tid < 32) {
#pragma unroll
        for (int o = 4; o > 0; o >>= 1) t += __shfl_xor_sync(0xffffffffu, t, o);
        if (tid == 0) red[0] = t;
    }
    __syncthreads();
    float mu = red[0] * (1.0f / D_);
    __syncthreads();

    float sq = 0.f;
#pragma unroll
    for (int i = 0; i < 4; i++) { float d = v[i] - mu; sq += d * d; }
#pragma unroll
    for (int o = 16; o > 0; o >>= 1) sq += __shfl_xor_sync(0xffffffffu, sq, o);
    if ((tid & 31) == 0) red[tid >> 5] = sq;
    __syncthreads();
    float t2 = (tid < 8) ? red[tid] : 0.f;
    if (tid < 32) {
#pragma unroll
        for (int o = 4; o > 0; o >>= 1) t2 += __shfl_xor_sync(0xffffffffu, t2, o);
        if (tid == 0) red[0] = t2;
    }
    __syncthreads();
    float var = red[0] * (1.0f / D_);
    float inv = rsqrtf(var + 1e-5f);

#pragma unroll
    for (int i = 0; i < 4; i++) {
        int c = tid + 256 * i;
        float y = (v[i] - mu) * inv * g[c] + b[c];
        __nv_bfloat16 h = __float2bfloat16(y);
        hi[(size_t)row * D_ + c] = h;
        lo[(size_t)row * D_ + c] = __float2bfloat16(y - __bfloat162float(h));
    }
}

// ---------------- fp32 -> bf16 hi/lo split (weights) ----------------
__global__ __launch_bounds__(256) void split_kernel(
    const float* __restrict__ x,
    __nv_bfloat16* __restrict__ hi, __nv_bfloat16* __restrict__ lo, int n4)
{
    int i = blockIdx.x * 256 + threadIdx.x;
    if (i >= n4) return;
    float4 v = ((const float4*)x)[i];
    __nv_bfloat16 h0 = __float2bfloat16(v.x);
    __nv_bfloat16 h1 = __float2bfloat16(v.y);
    __nv_bfloat16 h2 = __float2bfloat16(v.z);
    __nv_bfloat16 h3 = __float2bfloat16(v.w);
    __nv_bfloat162 hp0; hp0.x = h0; hp0.y = h1;
    __nv_bfloat162 hp1; hp1.x = h2; hp1.y = h3;
    __nv_bfloat162 lp0;
    lp0.x = __float2bfloat16(v.x - __bfloat162float(h0));
    lp0.y = __float2bfloat16(v.y - __bfloat162float(h1));
    __nv_bfloat162 lp1;
    lp1.x = __float2bfloat16(v.z - __bfloat162float(h2));
    lp1.y = __float2bfloat16(v.w - __bfloat162float(h3));
    ((__nv_bfloat162*)hi)[i * 2]     = hp0;
    ((__nv_bfloat162*)hi)[i * 2 + 1] = hp1;
    ((__nv_bfloat162*)lo)[i * 2]     = lp0;
    ((__nv_bfloat162*)lo)[i * 2 + 1] = lp1;
}

// ---------------- mask -> bitmask (has_any folded in: empty row => all ones) ----------------
__global__ __launch_bounds__(128) void maskpack_kernel(
    const int* __restrict__ mask, uint32_t* __restrict__ bits)
{
    int row = blockIdx.x;
    int tid = threadIdx.x;
    int wid = tid >> 5, lane = tid & 31;
    __shared__ uint32_t ws[128];
    const int* mr = mask + (size_t)row * HW_;
    int any = 0;
#pragma unroll
    for (int j = 0; j < 32; j++) {
        int v = mr[j * 128 + tid] != 0;
        any |= v;
        uint32_t bal = __ballot_sync(0xffffffffu, v);
        if (lane == 0) ws[j * 4 + wid] = bal;
    }
    int has = __syncthreads_or(any);
    bits[(size_t)row * 128 + tid] = has ? ws[tid] : 0xffffffffu;
}

// ---------------- mma.sync GEMM (3-pass hi/lo) with templated epilogue ----------------
// MODE 0: C fp32 + bias.  MODE 1: q head-split hi/lo.  MODE 2: kv head-split hi/lo.
#define G_ARR (128 * 80)               // 10240 bytes per array (stride 80B)
#define G_BUF (4 * G_ARR)
#define GEMM_SMEM (2 * G_BUF)          // 81920
#define NCHUNK 32

template<int MODE>
__global__ __launch_bounds__(256) void gemm_mma(
    const __nv_bfloat16* __restrict__ Ahi, const __nv_bfloat16* __restrict__ Alo,
    const __nv_bfloat16* __restrict__ Bhi, const __nv_bfloat16* __restrict__ Blo,
    const float* __restrict__ bias, float* __restrict__ C,
    __nv_bfloat16* __restrict__ ohi, __nv_bfloat16* __restrict__ olo,
    __nv_bfloat16* __restrict__ vhi, __nv_bfloat16* __restrict__ vlo,
    int M, int Ntot)
{
    extern __shared__ char sm[];
    uint32_t smb = smem_u32(sm);
    int tid = threadIdx.x;
    int wid = tid >> 5, lane = tid & 31;
    int wm = wid & 3, wn = wid >> 2;
    int row0 = blockIdx.y * 128;
    int col0 = blockIdx.x * 128;

    float acc[2][8][4];
#pragma unroll
    for (int a = 0; a < 2; a++)
#pragma unroll
        for (int b = 0; b < 8; b++)
#pragma unroll
            for (int c = 0; c < 4; c++) acc[a][b][c] = 0.f;

    int r_a = tid >> 2, seg = (tid & 3);

    auto load_chunk = [&](int c, int buf) {
        uint32_t base = smb + buf * G_BUF;
#pragma unroll
        for (int it = 0; it < 2; it++) {
            int r = r_a + it * 64;
            int gr = row0 + r;
            uint32_t dst = base + (uint32_t)(r * 80 + seg * 16);
            int nb = (gr < M) ? 16 : 0;
            cp16(dst,         Ahi + (size_t)gr * 1024 + c * 32 + seg * 8, nb);
            cp16(dst + G_ARR, Alo + (size_t)gr * 1024 + c * 32 + seg * 8, nb);
        }
#pragma unroll
        for (int it = 0; it < 2; it++) {
            int r = r_a + it * 64;
            int gr = col0 + r;
            uint32_t dst = base + 2 * G_ARR + (uint32_t)(r * 80 + seg * 16);
            cp16(dst,         Bhi + (size_t)gr * 1024 + c * 32 + seg * 8, 16);
            cp16(dst + G_ARR, Blo + (size_t)gr * 1024 + c * 32 + seg * 8, 16);
        }
    };

    load_chunk(0, 0);
    CP_COMMIT();

    for (int c = 0; c < NCHUNK; c++) {
        if (c + 1 < NCHUNK) {
            load_chunk(c + 1, (c + 1) & 1);
            CP_COMMIT();
            CP_WAIT1();
        } else {
            CP_WAIT0();
        }
        __syncthreads();

        uint32_t aBase = smb + (c & 1) * G_BUF;
        uint32_t bBase = aBase + 2 * G_ARR;
        int g = lane >> 3, ln = lane & 7;

#pragma unroll
        for (int s = 0; s < 2; s++) {
            int kc = s * 16;
            uint32_t ah[2][4], al[2][4], bh[8][2], bl[8][2];
#pragma unroll
            for (int mt = 0; mt < 2; mt++) {
                int row = wm * 32 + mt * 16 + (g & 1) * 8 + ln;
                int col = kc + (g >> 1) * 8;
                uint32_t addr = aBase + (uint32_t)(row * 80 + col * 2);
                LDMX4(ah[mt][0], ah[mt][1], ah[mt][2], ah[mt][3], addr);
                LDMX4(al[mt][0], al[mt][1], al[mt][2], al[mt][3], addr + G_ARR);
            }
#pragma unroll
            for (int np = 0; np < 4; np++) {
                int nrow = wn * 64 + np * 16 + (g >> 1) * 8 + ln;
                int col = kc + (g & 1) * 8;
                uint32_t addr = bBase + (uint32_t)(nrow * 80 + col * 2);
                LDMX4(bh[np * 2][0], bh[np * 2][1], bh[np * 2 + 1][0], bh[np * 2 + 1][1], addr);
                LDMX4(bl[np * 2][0], bl[np * 2][1], bl[np * 2 + 1][0], bl[np * 2 + 1][1], addr + G_ARR);
            }
#pragma unroll
            for (int mt = 0; mt < 2; mt++)
#pragma unroll
                for (int nt = 0; nt < 8; nt++) {
                    MMA16816(acc[mt][nt], ah[mt], bh[nt]);
                    MMA16816(acc[mt][nt], ah[mt], bl[nt]);
                    MMA16816(acc[mt][nt], al[mt], bh[nt]);
                }
        }
        __syncthreads();
    }

    // epilogue
    int qrow = lane >> 2, qcol = (lane & 3) * 2;
    int cbase = col0 + wn * 64;
#pragma unroll
    for (int mt = 0; mt < 2; mt++) {
#pragma unroll
        for (int half = 0; half < 2; half++) {
            int r = row0 + wm * 32 + mt * 16 + qrow + half * 8;
            if (r >= M) continue;
#pragma unroll
            for (int nt = 0; nt < 8; nt++) {
                int cix = nt * 8 + qcol;
                int cglob = cbase + cix;
                float2 bv = *(const float2*)&bias[cglob];
                float vx = acc[mt][nt][half * 2 + 0] + bv.x;
                float vy = acc[mt][nt][half * 2 + 1] + bv.y;
                if (MODE == 0) {
                    float2 o; o.x = vx; o.y = vy;
                    *(float2*)(C + (size_t)r * Ntot + cglob) = o;
                } else {
                    __nv_bfloat16 hx = __float2bfloat16(vx);
                    __nv_bfloat16 hy = __float2bfloat16(vy);
                    __nv_bfloat162 hp; hp.x = hx; hp.y = hy;
                    __nv_bfloat162 lp;
                    lp.x = __float2bfloat16(vx - __bfloat162float(hx));
                    lp.y = __float2bfloat16(vy - __bfloat162float(hy));
                    if (MODE == 1) {
                        int bb = r / 100, qq = r - bb * 100;
                        int hh = cglob >> 6;
                        size_t di = (((size_t)(bb * 16 + hh)) * 128 + qq) * 64 + (cglob & 63);
                        *(__nv_bfloat162*)(ohi + di) = hp;
                        *(__nv_bfloat162*)(olo + di) = lp;
                    } else {
                        int bb = r >> 12, kp = r & 4095;
                        int hh = (cglob >> 6) & 15;
                        size_t di = (((size_t)(bb * 16 + hh)) * 4096 + kp) * 64 + (cglob & 63);
                        if (cglob < 1024) {
                            *(__nv_bfloat162*)(ohi + di) = hp;
                            *(__nv_bfloat162*)(olo + di) = lp;
                        } else {
                            *(__nv_bfloat162*)(vhi + di) = hp;
                            *(__nv_bfloat162*)(vlo + di) = lp;
                        }
                    }
                }
            }
        }
    }
}

// ---------------- flash attention via mma.sync ----------------
// grid (64 bh, ASPLIT). 256 threads = 8 warps, warp w owns q-rows [16w, 16w+16).
// smem: QH | QL | 2 x (KH | KL | VH | VL), row stride 144B (72 bf16)
#define SQH 0
#define SQL 18432
#define SBUF0 36864
#define SBUFSZ 73728
#define SKH 0
#define SKL 18432
#define SVH 36864
#define SVL 55296
#define ATTN_SMEM (SBUF0 + 2 * SBUFSZ)   // 184320

__global__ __launch_bounds__(256) void attn_mma(
    const __nv_bfloat16* __restrict__ qhi, const __nv_bfloat16* __restrict__ qlo,
    const __nv_bfloat16* __restrict__ khi, const __nv_bfloat16* __restrict__ klo,
    const __nv_bfloat16* __restrict__ vhi, const __nv_bfloat16* __restrict__ vlo,
    const uint32_t* __restrict__ bits,
    float* __restrict__ pm, float* __restrict__ pl, float* __restrict__ pO)
{
    extern __shared__ char sm[];
    uint32_t smb = smem_u32(sm);
    int tid = threadIdx.x;
    int wid = tid >> 5, lane = tid & 31;
    int bh = blockIdx.x;
    int split = blockIdx.y;
    int bB = bh >> 4;
    int wr = wid * 16;
    int g = lane >> 3, ln = lane & 7;

    // ---- load Q (zero-padded rows >= 100) ----
#pragma unroll
    for (int it = 0; it < 4; it++) {
        int i = tid + it * 256;
        int r = i >> 3, sg = i & 7;
        size_t goff = ((size_t)bh * 128 + r) * 64 + sg * 8;
        int nb = (r < NQ_) ? 16 : 0;
        uint32_t so = (uint32_t)(r * 144 + sg * 16);
        cp16(smb + SQH + so, qhi + goff, nb);
        cp16(smb + SQL + so, qlo + goff, nb);
    }
    CP_COMMIT();

    auto load_tile = [&](int kt, int buf) {
        int k0 = split * KEYS_PER_SPLIT + kt * 128;
        uint32_t base = smb + SBUF0 + buf * SBUFSZ;
#pragma unroll
        for (int it = 0; it < 4; it++) {
            int i = tid + it * 256;
            int r = i >> 3, sg = i & 7;
            size_t goff = ((size_t)bh * 4096 + k0 + r) * 64 + sg * 8;
            uint32_t so = (uint32_t)(r * 144 + sg * 16);
            cp16(base + SKH + so, khi + goff, 16);
            cp16(base + SKL + so, klo + goff, 16);
            cp16(base + SVH + so, vhi + goff, 16);
            cp16(base + SVL + so, vlo + goff, 16);
        }
    };

    load_tile(0, 0);
    CP_COMMIT();
    CP_WAIT1();           // Q group done
    __syncthreads();

    // ---- Q fragments (persist across tiles) ----
    uint32_t qh[4][4], ql[4][4];
#pragma unroll
    for (int ks = 0; ks < 4; ks++) {
        int row = wr + (g & 1) * 8 + ln;
        int col = ks * 16 + (g >> 1) * 8;
        uint32_t a = smb + SQH + (uint32_t)(row * 144 + col * 2);
        LDMX4(qh[ks][0], qh[ks][1], qh[ks][2], qh[ks][3], a);
        LDMX4(ql[ks][0], ql[ks][1], ql[ks][2], ql[ks][3], a + (SQL - SQH));
    }

    int r0 = wr + (lane >> 2);
    int r1 = r0 + 8;
    int t2 = lane & 3;

    float rm0 = -INFINITY, rm1 = -INFINITY, rl0 = 0.f, rl1 = 0.f;
    float O[8][4];
#pragma unroll
    for (int dt = 0; dt < 8; dt++)
#pragma unroll
        for (int j = 0; j < 4; j++) O[dt][j] = 0.f;

    for (int kt = 0; kt < NT_PER_SPLIT; kt++) {
        if (kt + 1 < NT_PER_SPLIT) {
            load_tile(kt + 1, (kt + 1) & 1);
            CP_COMMIT();
            CP_WAIT1();
        } else {
            CP_WAIT0();
        }
        __syncthreads();

        uint32_t bb = smb + SBUF0 + (kt & 1) * SBUFSZ;
        int k0 = split * KEYS_PER_SPLIT + kt * 128;

        // ---- scores S = Q K^T (3-pass hi/lo) ----
        float sc[16][4];
#pragma unroll
        for (int nt = 0; nt < 16; nt++)
#pragma unroll
            for (int j = 0; j < 4; j++) sc[nt][j] = 0.f;

#pragma unroll
        for (int np = 0; np < 8; np++) {
            uint32_t kh4[4][4], kl4[4][4];
#pragma unroll
            for (int ks = 0; ks < 4; ks++) {
                int row = np * 16 + (g >> 1) * 8 + ln;
                int col = ks * 16 + (g & 1) * 8;
                uint32_t a = bb + SKH + (uint32_t)(row * 144 + col * 2);
                LDMX4(kh4[ks][0], kh4[ks][1], kh4[ks][2], kh4[ks][3], a);
                LDMX4(kl4[ks][0], kl4[ks][1], kl4[ks][2], kl4[ks][3], a + (SKL - SKH));
            }
#pragma unroll
            for (int ks = 0; ks < 4; ks++) {
                MMA16816(sc[2 * np],     qh[ks], &kh4[ks][0]);
                MMA16816(sc[2 * np + 1], qh[ks], &kh4[ks][2]);
                MMA16816(sc[2 * np],     qh[ks], &kl4[ks][0]);
                MMA16816(sc[2 * np + 1], qh[ks], &kl4[ks][2]);
                MMA16816(sc[2 * np],     ql[ks], &kh4[ks][0]);
                MMA16816(sc[2 * np + 1], ql[ks], &kh4[ks][2]);
            }
        }

        // ---- mask + scale ----
        uint32_t mw0[4], mw1[4];
        int woff = k0 >> 5;
        if (r0 < NQ_) *(uint4*)mw0 = *(const uint4*)(bits + (size_t)(bB * 100 + r0) * 128 + woff);
        else { mw0[0] = mw0[1] = mw0[2] = mw0[3] = 0xffffffffu; }
        if (r1 < NQ_) *(uint4*)mw1 = *(const uint4*)(bits + (size_t)(bB * 100 + r1) * 128 + woff);
        else { mw1[0] = mw1[1] = mw1[2] = mw1[3] = 0xffffffffu; }

        float mx0 = -INFINITY, mx1 = -INFINITY;
#pragma unroll
        for (int nt = 0; nt < 16; nt++) {
            int sh = (nt & 3) * 8 + 2 * t2;
            uint32_t wr0 = mw0[nt >> 2] >> sh;
            uint32_t wr1 = mw1[nt >> 2] >> sh;
            float s0 = (wr0 & 1u) ? sc[nt][0] * 0.125f : NEG_;
            float s1 = (wr0 & 2u) ? sc[nt][1] * 0.125f : NEG_;
            float s2 = (wr1 & 1u) ? sc[nt][2] * 0.125f : NEG_;
            float s3 = (wr1 & 2u) ? sc[nt][3] * 0.125f : NEG_;
            sc[nt][0] = s0; sc[nt][1] = s1; sc[nt][2] = s2; sc[nt][3] = s3;
            mx0 = fmaxf(mx0, fmaxf(s0, s1));
            mx1 = fmaxf(mx1, fmaxf(s2, s3));
        }
        mx0 = fmaxf(mx0, __shfl_xor_sync(0xffffffffu, mx0, 1));
        mx0 = fmaxf(mx0, __shfl_xor_sync(0xffffffffu, mx0, 2));
        mx1 = fmaxf(mx1, __shfl_xor_sync(0xffffffffu, mx1, 1));
        mx1 = fmaxf(mx1, __shfl_xor_sync(0xffffffffu, mx1, 2));

        float nm0 = fmaxf(rm0, mx0), nm1 = fmaxf(rm1, mx1);
        float a0 = __expf(rm0 - nm0), a1 = __expf(rm1 - nm1);
        rm0 = nm0; rm1 = nm1;

        float sum0 = 0.f, sum1 = 0.f;
#pragma unroll
        for (int nt = 0; nt < 16; nt++) {
            float p0 = __expf(sc[nt][0] - nm0);
            float p1 = __expf(sc[nt][1] - nm0);
            float p2 = __expf(sc[nt][2] - nm1);
            float p3 = __expf(sc[nt][3] - nm1);
            sc[nt][0] = p0; sc[nt][1] = p1; sc[nt][2] = p2; sc[nt][3] = p3;
            sum0 += p0 + p1; sum1 += p2 + p3;
        }
        sum0 += __shfl_xor_sync(0xffffffffu, sum0, 1);
        sum0 += __shfl_xor_sync(0xffffffffu, sum0, 2);
        sum1 += __shfl_xor_sync(0xffffffffu, sum1, 1);
        sum1 += __shfl_xor_sync(0xffffffffu, sum1, 2);
        rl0 = rl0 * a0 + sum0;
        rl1 = rl1 * a1 + sum1;

#pragma unroll
        for (int dt = 0; dt < 8; dt++) {
            O[dt][0] *= a0; O[dt][1] *= a0;
            O[dt][2] *= a1; O[dt][3] *= a1;
        }

        // ---- pack P hi/lo A-fragments ----
        uint32_t ph[8][4], plr[8][4];
#pragma unroll
        for (int ks = 0; ks < 8; ks++) {
            int n0 = 2 * ks, n1 = 2 * ks + 1;
            float x0 = sc[n0][0], x1 = sc[n0][1], x2 = sc[n0][2], x3 = sc[n0][3];
            float y0 = sc[n1][0], y1 = sc[n1][1], y2 = sc[n1][2], y3 = sc[n1][3];
            ph[ks][0] = pack_bf16x2(x0, x1);
            ph[ks][1] = pack_bf16x2(x2, x3);
            ph[ks][2] = pack_bf16x2(y0, y1);
            ph[ks][3] = pack_bf16x2(y2, y3);
            plr[ks][0] = pack_bf16x2(x0 - __bfloat162float(__float2bfloat16(x0)),
                                     x1 - __bfloat162float(__float2bfloat16(x1)));
            plr[ks][1] = pack_bf16x2(x2 - __bfloat162float(__float2bfloat16(x2)),
                                     x3 - __bfloat162float(__float2bfloat16(x3)));
            plr[ks][2] = pack_bf16x2(y0 - __bfloat162float(__float2bfloat16(y0)),
                                     y1 - __bfloat162float(__float2bfloat16(y1)));
            plr[ks][3] = pack_bf16x2(y2 - __bfloat162float(__float2bfloat16(y2)),
                                     y3 - __bfloat162float(__float2bfloat16(y3)));
        }

        // ---- O += P V (3-pass hi/lo), V via ldmatrix.trans ----
#pragma unroll
        for (int dt2 = 0; dt2 < 4; dt2++) {
#pragma unroll
            for (int ks = 0; ks < 8; ks++) {
                int row = ks * 16 + (g & 1) * 8 + ln;
                int col = dt2 * 16 + (g >> 1) * 8;
                uint32_t a = bb + SVH + (uint32_t)(row * 144 + col * 2);
                uint32_t vh4[4], vl4[4];
                LDMX4T(vh4[0], vh4[1], vh4[2], vh4[3], a);
                LDMX4T(vl4[0], vl4[1], vl4[2], vl4[3], a + (SVL - SVH));
                MMA16816(O[2 * dt2],     ph[ks],  &vh4[0]);
                MMA16816(O[2 * dt2 + 1], ph[ks],  &vh4[2]);
                MMA16816(O[2 * dt2],     plr[ks], &vh4[0]);
                MMA16816(O[2 * dt2 + 1], plr[ks], &vh4[2]);
                MMA16816(O[2 * dt2],     ph[ks],  &vl4[0]);
                MMA16816(O[2 * dt2 + 1], ph[ks],  &vl4[2]);
            }
        }
        __syncthreads();
    }

    // ---- store partials (unnormalized) ----
    size_t pbase = ((size_t)(split * 64 + bh)) * 128;
    if (t2 == 0) {
        pm[pbase + r0] = rm0; pm[pbase + r1] = rm1;
        pl[pbase + r0] = rl0; pl[pbase + r1] = rl1;
    }
#pragma unroll
    for (int dt = 0; dt < 8; dt++) {
        int d = dt * 8 + 2 * t2;
        float2 o0; o0.x = O[dt][0]; o0.y = O[dt][1];
        float2 o1; o1.x = O[dt][2]; o1.y = O[dt][3];
        *(float2*)(pO + (pbase + r0) * 64 + d) = o0;
        *(float2*)(pO + (pbase + r1) * 64 + d) = o1;
    }
}

// ---------------- merge split-K partials -> ctx hi/lo ----------------
__global__ __launch_bounds__(256) void merge_kernel(
    const float* __restrict__ pm, const float* __restrict__ pl,
    const float* __restrict__ pO,
    __nv_bfloat16* __restrict__ cxhi, __nv_bfloat16* __restrict__ cxlo)
{
    int idx = blockIdx.x * 256 + threadIdx.x;
    if (idx >= 400 * 1024) return;
    int row = idx >> 10;
    int col = idx & 1023;
    int b = row / 100, q = row - b * 100;
    int h = col >> 6, d = col & 63;
    size_t p0 = ((size_t)(0 * 64 + b * 16 + h)) * 128 + q;
    size_t p1 = ((size_t)(1 * 64 + b * 16 + h)) * 128 + q;
    float m0 = pm[p0], m1 = pm[p1];
    float M = fmaxf(m0, m1);
    float w0 = __expf(m0 - M), w1 = __expf(m1 - M);
    float L = pl[p0] * w0 + pl[p1] * w1;
    float val = (pO[p0 * 64 + d] * w0 + pO[p1 * 64 + d] * w1) / L;
    __nv_bfloat16 hx = __float2bfloat16(val);
    cxhi[idx] = hx;
    cxlo[idx] = __float2bfloat16(val - __bfloat162float(hx));
}

// ---------------- launch ----------------
extern "C" void kernel_launch(void* const* d_in, const int* in_sizes, int n_in,
                              void* d_out, int out_size)
{
    const float* q    = (const float*)d_in[0];
    const float* kv   = (const float*)d_in[1];
    const int*   mask = (const int*)  d_in[2];
    const float* ipw  = (const float*)d_in[3];
    const float* ipb  = (const float*)d_in[4];
    const float* ow   = (const float*)d_in[5];
    const float* ob   = (const float*)d_in[6];
    const float* gq   = (const float*)d_in[7];
    const float* bq   = (const float*)d_in[8];
    const float* gkv  = (const float*)d_in[9];
    const float* bkv  = (const float*)d_in[10];
    float* out = (float*)d_out;

    __nv_bfloat16 *p_qn_hi, *p_qn_lo, *p_kvn_hi, *p_kvn_lo;
    __nv_bfloat16 *p_w_hi, *p_w_lo, *p_ow_hi, *p_ow_lo, *p_cx_hi, *p_cx_lo;
    __nv_bfloat16 *p_qhi, *p_qlo, *p_khi, *p_klo, *p_vhi, *p_vlo;
    float *p_pm, *p_pl, *p_pO;
    uint32_t* p_bits;
    cudaGetSymbolAddress((void**)&p_qn_hi,  g_qn_hi);
    cudaGetSymbolAddress((void**)&p_qn_lo,  g_qn_lo);
    cudaGetSymbolAddress((void**)&p_kvn_hi, g_kvn_hi);
    cudaGetSymbolAddress((void**)&p_kvn_lo, g_kvn_lo);
    cudaGetSymbolAddress((void**)&p_w_hi,   g_w_hi);
    cudaGetSymbolAddress((void**)&p_w_lo,   g_w_lo);
    cudaGetSymbolAddress((void**)&p_ow_hi,  g_ow_hi);
    cudaGetSymbolAddress((void**)&p_ow_lo,  g_ow_lo);
    cudaGetSymbolAddress((void**)&p_cx_hi,  g_cx_hi);
    cudaGetSymbolAddress((void**)&p_cx_lo,  g_cx_lo);
    cudaGetSymbolAddress((void**)&p_qhi, g_qhi);
    cudaGetSymbolAddress((void**)&p_qlo, g_qlo);
    cudaGetSymbolAddress((void**)&p_khi, g_khi);
    cudaGetSymbolAddress((void**)&p_klo, g_klo);
    cudaGetSymbolAddress((void**)&p_vhi, g_vhi);
    cudaGetSymbolAddress((void**)&p_vlo, g_vlo);
    cudaGetSymbolAddress((void**)&p_bits, g_bits);
    cudaGetSymbolAddress((void**)&p_pm, g_pm);
    cudaGetSymbolAddress((void**)&p_pl, g_pl);
    cudaGetSymbolAddress((void**)&p_pO, g_pO);

    cudaFuncSetAttribute(gemm_mma<0>, cudaFuncAttributeMaxDynamicSharedMemorySize, GEMM_SMEM);
    cudaFuncSetAttribute(gemm_mma<1>, cudaFuncAttributeMaxDynamicSharedMemorySize, GEMM_SMEM);
    cudaFuncSetAttribute(gemm_mma<2>, cudaFuncAttributeMaxDynamicSharedMemorySize, GEMM_SMEM);
    cudaFuncSetAttribute(attn_mma, cudaFuncAttributeMaxDynamicSharedMemorySize, ATTN_SMEM);

    // layernorm + split
    ln_split_kernel<<<B_ * NQ_, 256>>>(q, gq, bq, p_qn_hi, p_qn_lo);
    ln_split_kernel<<<B_ * HW_, 256>>>(kv, gkv, bkv, p_kvn_hi, p_kvn_lo);
    maskpack_kernel<<<B_ * NQ_, 128>>>(mask, p_bits);

    // weight splits
    split_kernel<<<(3072 * 1024 / 4 + 255) / 256, 256>>>(ipw, p_w_hi, p_w_lo, 3072 * 1024 / 4);
    split_kernel<<<(1024 * 1024 / 4 + 255) / 256, 256>>>(ow, p_ow_hi, p_ow_lo, 1024 * 1024 / 4);

    // q projection -> head-major hi/lo
    gemm_mma<1><<<dim3(8, 4), 256, GEMM_SMEM>>>(
        p_qn_hi, p_qn_lo, p_w_hi, p_w_lo, ipb, nullptr,
        p_qhi, p_qlo, nullptr, nullptr, B_ * NQ_, 1024);

    // kv projection -> head-major hi/lo K and V
    gemm_mma<2><<<dim3(16, 128), 256, GEMM_SMEM>>>(
        p_kvn_hi, p_kvn_lo,
        p_w_hi + (size_t)1024 * 1024, p_w_lo + (size_t)1024 * 1024,
        ipb + 1024, nullptr,
        p_khi, p_klo, p_vhi, p_vlo, B_ * HW_, 2048);

    // attention (split-K)
    attn_mma<<<dim3(64, ASPLIT), 256, ATTN_SMEM>>>(
        p_qhi, p_qlo, p_khi, p_klo, p_vhi, p_vlo, p_bits, p_pm, p_pl, p_pO);

    // merge -> ctx hi/lo
    merge_kernel<<<(400 * 1024 + 255) / 256, 256>>>(p_pm, p_pl, p_pO, p_cx_hi, p_cx_lo);

    // output projection
    gemm_mma<0><<<dim3(8, 4), 256, GEMM_SMEM>>>(
        p_cx_hi, p_cx_lo, p_ow_hi, p_ow_lo, ob, out,
        nullptr, nullptr, nullptr, nullptr, B_ * NQ_, 1024);
}

// round 12
// speedup vs baseline: 3.4339x; 1.0530x over previous
#include <cuda_runtime.h>
#include <cuda_bf16.h>
#include <math.h>
#include <stdint.h>

#define B_  4
#define NQ_ 100
#define HW_ 4096
#define D_  1024
#define H_  16
#define HD_ 64
#define NEG_ (-1e9f)
#define ASPLIT 2
#define KEYS_PER_SPLIT (HW_ / ASPLIT)   // 2048
#define NT_PER_SPLIT   (KEYS_PER_SPLIT / 128)  // 16

// ---------------- scratch (device globals; no runtime allocation) ----------------
__device__ __nv_bfloat16 g_qn_hi [400  * 1024];
__device__ __nv_bfloat16 g_qn_lo [400  * 1024];
__device__ __nv_bfloat16 g_kvn_hi[16384 * 1024];
__device__ __nv_bfloat16 g_kvn_lo[16384 * 1024];
__device__ __nv_bfloat16 g_w_hi  [3072 * 1024];
__device__ __nv_bfloat16 g_w_lo  [3072 * 1024];
__device__ __nv_bfloat16 g_ow_hi [1024 * 1024];
__device__ __nv_bfloat16 g_ow_lo [1024 * 1024];
// head-major projections: [b*16+h][rows][64]
__device__ __nv_bfloat16 g_qhi[64 * 128 * 64];
__device__ __nv_bfloat16 g_qlo[64 * 128 * 64];
__device__ __nv_bfloat16 g_khi[(size_t)64 * 4096 * 64];
__device__ __nv_bfloat16 g_klo[(size_t)64 * 4096 * 64];
__device__ __nv_bfloat16 g_vhi[(size_t)64 * 4096 * 64];
__device__ __nv_bfloat16 g_vlo[(size_t)64 * 4096 * 64];
__device__ __nv_bfloat16 g_cx_hi[400 * 1024];
__device__ __nv_bfloat16 g_cx_lo[400 * 1024];
__device__ uint32_t g_bits[400 * 128];
__device__ float g_pm[ASPLIT * 64 * 128];
__device__ float g_pl[ASPLIT * 64 * 128];
__device__ float g_pO[(size_t)ASPLIT * 64 * 128 * 64];

// ---------------- helpers ----------------
__device__ __forceinline__ uint32_t smem_u32(const void* p) {
    uint32_t a;
    asm("{ .reg .u64 t; cvta.to.shared.u64 t, %1; cvt.u32.u64 %0, t; }" : "=r"(a) : "l"(p));
    return a;
}
__device__ __forceinline__ void cp16(uint32_t dst, const void* src, int nbytes) {
    asm volatile("cp.async.cg.shared.global [%0], [%1], 16, %2;"
                 :: "r"(dst), "l"(src), "r"(nbytes));
}
#define CP_COMMIT() asm volatile("cp.async.commit_group;" ::: "memory")
#define CP_WAIT1()  asm volatile("cp.async.wait_group 1;" ::: "memory")
#define CP_WAIT0()  asm volatile("cp.async.wait_group 0;" ::: "memory")

#define LDMX4(r0, r1, r2, r3, addr) \
    asm volatile("ldmatrix.sync.aligned.m8n8.x4.shared.b16 {%0,%1,%2,%3}, [%4];" \
                 : "=r"(r0), "=r"(r1), "=r"(r2), "=r"(r3) : "r"(addr))
#define LDMX4T(r0, r1, r2, r3, addr) \
    asm volatile("ldmatrix.sync.aligned.m8n8.x4.trans.shared.b16 {%0,%1,%2,%3}, [%4];" \
                 : "=r"(r0), "=r"(r1), "=r"(r2), "=r"(r3) : "r"(addr))

#define MMA16816(c, a, b) \
    asm volatile("mma.sync.aligned.m16n8k16.row.col.f32.bf16.bf16.f32 " \
                 "{%0,%1,%2,%3}, {%4,%5,%6,%7}, {%8,%9}, {%0,%1,%2,%3};" \
                 : "+f"((c)[0]), "+f"((c)[1]), "+f"((c)[2]), "+f"((c)[3]) \
                 : "r"((a)[0]), "r"((a)[1]), "r"((a)[2]), "r"((a)[3]), \
                   "r"((b)[0]), "r"((b)[1]))

__device__ __forceinline__ uint32_t pack_bf16x2(float lo_el, float hi_el) {
    uint32_t r;
    asm("cvt.rn.bf16x2.f32 %0, %1, %2;" : "=r"(r) : "f"(hi_el), "f"(lo_el));
    return r;
}

// ---------------- layernorm + bf16 hi/lo split ----------------
__global__ __launch_bounds__(256) void ln_split_kernel(
    const float* __restrict__ x, const float* __restrict__ g,
    const float* __restrict__ b,
    __nv_bfloat16* __restrict__ hi, __nv_bfloat16* __restrict__ lo)
{
    __shared__ float red[32];
    int row = blockIdx.x;
    int tid = threadIdx.x;
    const float* xr = x + (size_t)row * D_;

    float v[4];
#pragma unroll
    for (int i = 0; i < 4; i++) v[i] = xr[tid + 256 * i];

    float s = v[0] + v[1] + v[2] + v[3];
#pragma unroll
    for (int o = 16; o > 0; o >>= 1) s += __shfl_xor_sync(0xffffffffu, s, o);
    if ((tid & 31) == 0) red[tid >> 5] = s;
    __syncthreads();
    float t = (tid < 8) ? red[tid] : 0.f;
    if (tid < 32) {
#pragma unroll
        for (int o = 4; o > 0; o >>= 1) t += __shfl_xor_sync(0xffffffffu, t, o);
        if (tid == 0) red[0] = t;
    }
    __syncthreads();
    float mu = red[0] * (1.0f / D_);
    __syncthreads();

    float sq = 0.f;
#pragma unroll
    for (int i = 0; i < 4; i++) { float d = v[i] - mu; sq += d * d; }
#pragma unroll
    for (int o = 16; o > 0; o >>= 1) sq += __shfl_xor_sync(0xffffffffu, sq, o);
    if ((tid & 31) == 0) red[tid >> 5] = sq;
    __syncthreads();
    float t2 = (tid < 8) ? red[tid] : 0.f;
    if (tid < 32) {
#pragma unroll
        for (int o = 4; o > 0; o >>= 1) t2 += __shfl_xor_sync(0xffffffffu, t2, o);
        if (tid == 0) red[0] = t2;
    }
    __syncthreads();
    float var = red[0] * (1.0f / D_);
    float inv = rsqrtf(var + 1e-5f);

#pragma unroll
    for (int i = 0; i < 4; i++) {
        int c = tid + 256 * i;
        float y = (v[i] - mu) * inv * g[c] + b[c];
        __nv_bfloat16 h = __float2bfloat16(y);
        hi[(size_t)row * D_ + c] = h;
        lo[(size_t)row * D_ + c] = __float2bfloat16(y - __bfloat162float(h));
    }
}

// ---------------- fp32 -> bf16 hi/lo split (weights) ----------------
__global__ __launch_bounds__(256) void split_kernel(
    const float* __restrict__ x,
    __nv_bfloat16* __restrict__ hi, __nv_bfloat16* __restrict__ lo, int n4)
{
    int i = blockIdx.x * 256 + threadIdx.x;
    if (i >= n4) return;
    float4 v = ((const float4*)x)[i];
    __nv_bfloat16 h0 = __float2bfloat16(v.x);
    __nv_bfloat16 h1 = __float2bfloat16(v.y);
    __nv_bfloat16 h2 = __float2bfloat16(v.z);
    __nv_bfloat16 h3 = __float2bfloat16(v.w);
    __nv_bfloat162 hp0; hp0.x = h0; hp0.y = h1;
    __nv_bfloat162 hp1; hp1.x = h2; hp1.y = h3;
    __nv_bfloat162 lp0;
    lp0.x = __float2bfloat16(v.x - __bfloat162float(h0));
    lp0.y = __float2bfloat16(v.y - __bfloat162float(h1));
    __nv_bfloat162 lp1;
    lp1.x = __float2bfloat16(v.z - __bfloat162float(h2));
    lp1.y = __float2bfloat16(v.w - __bfloat162float(h3));
    ((__nv_bfloat162*)hi)[i * 2]     = hp0;
    ((__nv_bfloat162*)hi)[i * 2 + 1] = hp1;
    ((__nv_bfloat162*)lo)[i * 2]     = lp0;
    ((__nv_bfloat162*)lo)[i * 2 + 1] = lp1;
}

// ---------------- mask -> bitmask (has_any folded in: empty row => all ones) ----------------
__global__ __launch_bounds__(128) void maskpack_kernel(
    const int* __restrict__ mask, uint32_t* __restrict__ bits)
{
    int row = blockIdx.x;
    int tid = threadIdx.x;
    int wid = tid >> 5, lane = tid & 31;
    __shared__ uint32_t ws[128];
    const int* mr = mask + (size_t)row * HW_;
    int any = 0;
#pragma unroll
    for (int j = 0; j < 32; j++) {
        int v = mr[j * 128 + tid] != 0;
        any |= v;
        uint32_t bal = __ballot_sync(0xffffffffu, v);
        if (lane == 0) ws[j * 4 + wid] = bal;
    }
    int has = __syncthreads_or(any);
    bits[(size_t)row * 128 + tid] = has ? ws[tid] : 0xffffffffu;
}

// ---------------- mma.sync GEMM (3-pass hi/lo), pass-outer MMA ordering ----------------
// MODE 0: C fp32 + bias.  MODE 1: q head-split hi/lo.  MODE 2: kv head-split hi/lo.
// NTT = per-warp n-tiles (8 -> BN=128, 4 -> BN=64). Warp grid 4x2.
#define A_SZ (128 * 80)                // 10240 bytes per A array (stride 80B)
#define NCHUNK 32

template<int MODE, int NTT>
__global__ __launch_bounds__(256) void gemm_mma(
    const __nv_bfloat16* __restrict__ Ahi, const __nv_bfloat16* __restrict__ Alo,
    const __nv_bfloat16* __restrict__ Bhi, const __nv_bfloat16* __restrict__ Blo,
    const float* __restrict__ bias, float* __restrict__ C,
    __nv_bfloat16* __restrict__ ohi, __nv_bfloat16* __restrict__ olo,
    __nv_bfloat16* __restrict__ vhi, __nv_bfloat16* __restrict__ vlo,
    int M, int Ntot)
{
    constexpr int BN   = NTT * 16;
    constexpr int B_SZ = BN * 80;
    constexpr int BUF  = 2 * A_SZ + 2 * B_SZ;

    extern __shared__ char sm[];
    uint32_t smb = smem_u32(sm);
    int tid = threadIdx.x;
    int wid = tid >> 5, lane = tid & 31;
    int wm = wid & 3, wn = wid >> 2;
    int row0 = blockIdx.y * 128;
    int col0 = blockIdx.x * BN;

    float acc[2][NTT][4];
#pragma unroll
    for (int a = 0; a < 2; a++)
#pragma unroll
        for (int b = 0; b < NTT; b++)
#pragma unroll
            for (int c = 0; c < 4; c++) acc[a][b][c] = 0.f;

    int r_a = tid >> 2, seg = (tid & 3);

    auto load_chunk = [&](int c, int buf) {
        uint32_t base = smb + buf * BUF;
#pragma unroll
        for (int it = 0; it < 2; it++) {
            int r = r_a + it * 64;
            int gr = row0 + r;
            uint32_t dst = base + (uint32_t)(r * 80 + seg * 16);
            int nb = (gr < M) ? 16 : 0;
            cp16(dst,        Ahi + (size_t)gr * 1024 + c * 32 + seg * 8, nb);
            cp16(dst + A_SZ, Alo + (size_t)gr * 1024 + c * 32 + seg * 8, nb);
        }
#pragma unroll
        for (int it = 0; it < BN / 64; it++) {
            int r = r_a + it * 64;
            int gr = col0 + r;
            uint32_t dst = base + 2 * A_SZ + (uint32_t)(r * 80 + seg * 16);
            cp16(dst,        Bhi + (size_t)gr * 1024 + c * 32 + seg * 8, 16);
            cp16(dst + B_SZ, Blo + (size_t)gr * 1024 + c * 32 + seg * 8, 16);
        }
    };

    load_chunk(0, 0);
    CP_COMMIT();

    for (int c = 0; c < NCHUNK; c++) {
        if (c + 1 < NCHUNK) {
            load_chunk(c + 1, (c + 1) & 1);
            CP_COMMIT();
            CP_WAIT1();
        } else {
            CP_WAIT0();
        }
        __syncthreads();

        uint32_t aBase = smb + (c & 1) * BUF;
        uint32_t bBase = aBase + 2 * A_SZ;
        int g = lane >> 3, ln = lane & 7;

#pragma unroll
        for (int s = 0; s < 2; s++) {
            int kc = s * 16;
            uint32_t ah[2][4], al[2][4], bh[NTT][2], bl[NTT][2];
#pragma unroll
            for (int mt = 0; mt < 2; mt++) {
                int row = wm * 32 + mt * 16 + (g & 1) * 8 + ln;
                int col = kc + (g >> 1) * 8;
                uint32_t addr = aBase + (uint32_t)(row * 80 + col * 2);
                LDMX4(ah[mt][0], ah[mt][1], ah[mt][2], ah[mt][3], addr);
                LDMX4(al[mt][0], al[mt][1], al[mt][2], al[mt][3], addr + A_SZ);
            }
#pragma unroll
            for (int np = 0; np < NTT / 2; np++) {
                int nrow = wn * (BN / 2) + np * 16 + (g >> 1) * 8 + ln;
                int col = kc + (g & 1) * 8;
                uint32_t addr = bBase + (uint32_t)(nrow * 80 + col * 2);
                LDMX4(bh[np * 2][0], bh[np * 2][1], bh[np * 2 + 1][0], bh[np * 2 + 1][1], addr);
                LDMX4(bl[np * 2][0], bl[np * 2][1], bl[np * 2 + 1][0], bl[np * 2 + 1][1], addr + B_SZ);
            }
            // pass-outer ordering: same-acc spacing = 2*NTT instructions
#pragma unroll
            for (int mt = 0; mt < 2; mt++)
#pragma unroll
                for (int nt = 0; nt < NTT; nt++)
                    MMA16816(acc[mt][nt], ah[mt], bh[nt]);
#pragma unroll
            for (int mt = 0; mt < 2; mt++)
#pragma unroll
                for (int nt = 0; nt < NTT; nt++)
                    MMA16816(acc[mt][nt], ah[mt], bl[nt]);
#pragma unroll
            for (int mt = 0; mt < 2; mt++)
#pragma unroll
                for (int nt = 0; nt < NTT; nt++)
                    MMA16816(acc[mt][nt], al[mt], bh[nt]);
        }
        __syncthreads();
    }

    // epilogue
    int qrow = lane >> 2, qcol = (lane & 3) * 2;
    int cbase = col0 + wn * (BN / 2);
#pragma unroll
    for (int mt = 0; mt < 2; mt++) {
#pragma unroll
        for (int half = 0; half < 2; half++) {
            int r = row0 + wm * 32 + mt * 16 + qrow + half * 8;
            if (r >= M) continue;
#pragma unroll
            for (int nt = 0; nt < NTT; nt++) {
                int cix = nt * 8 + qcol;
                int cglob = cbase + cix;
                float2 bv = *(const float2*)&bias[cglob];
                float vx = acc[mt][nt][half * 2 + 0] + bv.x;
                float vy = acc[mt][nt][half * 2 + 1] + bv.y;
                if (MODE == 0) {
                    float2 o; o.x = vx; o.y = vy;
                    *(float2*)(C + (size_t)r * Ntot + cglob) = o;
                } else {
                    __nv_bfloat16 hx = __float2bfloat16(vx);
                    __nv_bfloat16 hy = __float2bfloat16(vy);
                    __nv_bfloat162 hp; hp.x = hx; hp.y = hy;
                    __nv_bfloat162 lp;
                    lp.x = __float2bfloat16(vx - __bfloat162float(hx));
                    lp.y = __float2bfloat16(vy - __bfloat162float(hy));
                    if (MODE == 1) {
                        int bb = r / 100, qq = r - bb * 100;
                        int hh = cglob >> 6;
                        size_t di = (((size_t)(bb * 16 + hh)) * 128 + qq) * 64 + (cglob & 63);
                        *(__nv_bfloat162*)(ohi + di) = hp;
                        *(__nv_bfloat162*)(olo + di) = lp;
                    } else {
                        int bb = r >> 12, kp = r & 4095;
                        int hh = (cglob >> 6) & 15;
                        size_t di = (((size_t)(bb * 16 + hh)) * 4096 + kp) * 64 + (cglob & 63);
                        if (cglob < 1024) {
                            *(__nv_bfloat162*)(ohi + di) = hp;
                            *(__nv_bfloat162*)(olo + di) = lp;
                        } else {
                            *(__nv_bfloat162*)(vhi + di) = hp;
                            *(__nv_bfloat162*)(vlo + di) = lp;
                        }
                    }
                }
            }
        }
    }
}

// ---------------- flash attention via mma.sync ----------------
// grid (64 bh, ASPLIT). 256 threads = 8 warps, warp w owns q-rows [16w, 16w+16).
// smem: QH | QL | 2 x (KH | KL | VH | VL), row stride 144B (72 bf16)
#define SQH 0
#define SQL 18432
#define SBUF0 36864
#define SBUFSZ 73728
#define SKH 0
#define SKL 18432
#define SVH 36864
#define SVL 55296
#define ATTN_SMEM (SBUF0 + 2 * SBUFSZ)   // 184320

__global__ __launch_bounds__(256) void attn_mma(
    const __nv_bfloat16* __restrict__ qhi, const __nv_bfloat16* __restrict__ qlo,
    const __nv_bfloat16* __restrict__ khi, const __nv_bfloat16* __restrict__ klo,
    const __nv_bfloat16* __restrict__ vhi, const __nv_bfloat16* __restrict__ vlo,
    const uint32_t* __restrict__ bits,
    float* __restrict__ pm, float* __restrict__ pl, float* __restrict__ pO)
{
    extern __shared__ char sm[];
    uint32_t smb = smem_u32(sm);
    int tid = threadIdx.x;
    int wid = tid >> 5, lane = tid & 31;
    int bh = blockIdx.x;
    int split = blockIdx.y;
    int bB = bh >> 4;
    int wr = wid * 16;
    int g = lane >> 3, ln = lane & 7;

    // ---- load Q (zero-padded rows >= 100) ----
#pragma unroll
    for (int it = 0; it < 4; it++) {
        int i = tid + it * 256;
        int r = i >> 3, sg = i & 7;
        size_t goff = ((size_t)bh * 128 + r) * 64 + sg * 8;
        int nb = (r < NQ_) ? 16 : 0;
        uint32_t so = (uint32_t)(r * 144 + sg * 16);
        cp16(smb + SQH + so, qhi + goff, nb);
        cp16(smb + SQL + so, qlo + goff, nb);
    }
    CP_COMMIT();

    auto load_tile = [&](int kt, int buf) {
        int k0 = split * KEYS_PER_SPLIT + kt * 128;
        uint32_t base = smb + SBUF0 + buf * SBUFSZ;
#pragma unroll
        for (int it = 0; it < 4; it++) {
            int i = tid + it * 256;
            int r = i >> 3, sg = i & 7;
            size_t goff = ((size_t)bh * 4096 + k0 + r) * 64 + sg * 8;
            uint32_t so = (uint32_t)(r * 144 + sg * 16);
            cp16(base + SKH + so, khi + goff, 16);
            cp16(base + SKL + so, klo + goff, 16);
            cp16(base + SVH + so, vhi + goff, 16);
            cp16(base + SVL + so, vlo + goff, 16);
        }
    };

    load_tile(0, 0);
    CP_COMMIT();
    CP_WAIT1();           // Q group done
    __syncthreads();

    // ---- Q fragments (persist across tiles) ----
    uint32_t qh[4][4], ql[4][4];
#pragma unroll
    for (int ks = 0; ks < 4; ks++) {
        int row = wr + (g & 1) * 8 + ln;
        int col = ks * 16 + (g >> 1) * 8;
        uint32_t a = smb + SQH + (uint32_t)(row * 144 + col * 2);
        LDMX4(qh[ks][0], qh[ks][1], qh[ks][2], qh[ks][3], a);
        LDMX4(ql[ks][0], ql[ks][1], ql[ks][2], ql[ks][3], a + (SQL - SQH));
    }

    int r0 = wr + (lane >> 2);
    int r1 = r0 + 8;
    int t2 = lane & 3;

    float rm0 = -INFINITY, rm1 = -INFINITY, rl0 = 0.f, rl1 = 0.f;
    float O[8][4];
#pragma unroll
    for (int dt = 0; dt < 8; dt++)
#pragma unroll
        for (int j = 0; j < 4; j++) O[dt][j] = 0.f;

    for (int kt = 0; kt < NT_PER_SPLIT; kt++) {
        if (kt + 1 < NT_PER_SPLIT) {
            load_tile(kt + 1, (kt + 1) & 1);
            CP_COMMIT();
            CP_WAIT1();
        } else {
            CP_WAIT0();
        }
        __syncthreads();

        uint32_t bb = smb + SBUF0 + (kt & 1) * SBUFSZ;
        int k0 = split * KEYS_PER_SPLIT + kt * 128;

        // ---- scores S = Q K^T (3-pass hi/lo), np-pairs for 4-acc rotation ----
        float sc[16][4];
#pragma unroll
        for (int nt = 0; nt < 16; nt++)
#pragma unroll
            for (int j = 0; j < 4; j++) sc[nt][j] = 0.f;

#pragma unroll
        for (int npp = 0; npp < 4; npp++) {
            uint32_t kh2[2][4][4], kl2[2][4][4];
#pragma unroll
            for (int j = 0; j < 2; j++) {
                int np = npp * 2 + j;
#pragma unroll
                for (int ks = 0; ks < 4; ks++) {
                    int row = np * 16 + (g >> 1) * 8 + ln;
                    int col = ks * 16 + (g & 1) * 8;
                    uint32_t a = bb + SKH + (uint32_t)(row * 144 + col * 2);
                    LDMX4(kh2[j][ks][0], kh2[j][ks][1], kh2[j][ks][2], kh2[j][ks][3], a);
                    LDMX4(kl2[j][ks][0], kl2[j][ks][1], kl2[j][ks][2], kl2[j][ks][3], a + (SKL - SKH));
                }
            }
#pragma unroll
            for (int ks = 0; ks < 4; ks++) {
#pragma unroll
                for (int j = 0; j < 2; j++) {
                    MMA16816(sc[4 * npp + 2 * j],     qh[ks], &kh2[j][ks][0]);
                    MMA16816(sc[4 * npp + 2 * j + 1], qh[ks], &kh2[j][ks][2]);
                }
#pragma unroll
                for (int j = 0; j < 2; j++) {
                    MMA16816(sc[4 * npp + 2 * j],     qh[ks], &kl2[j][ks][0]);
                    MMA16816(sc[4 * npp + 2 * j + 1], qh[ks], &kl2[j][ks][2]);
                }
#pragma unroll
                for (int j = 0; j < 2; j++) {
                    MMA16816(sc[4 * npp + 2 * j],     ql[ks], &kh2[j][ks][0]);
                    MMA16816(sc[4 * npp + 2 * j + 1], ql[ks], &kh2[j][ks][2]);
                }
            }
        }

        // ---- mask + scale ----
        uint32_t mw0[4], mw1[4];
        int woff = k0 >> 5;
        if (r0 < NQ_) *(uint4*)mw0 = *(const uint4*)(bits + (size_t)(bB * 100 + r0) * 128 + woff);
        else { mw0[0] = mw0[1] = mw0[2] = mw0[3] = 0xffffffffu; }
        if (r1 < NQ_) *(uint4*)mw1 = *(const uint4*)(bits + (size_t)(bB * 100 + r1) * 128 + woff);
        else { mw1[0] = mw1[1] = mw1[2] = mw1[3] = 0xffffffffu; }

        float mx0 = -INFINITY, mx1 = -INFINITY;
#pragma unroll
        for (int nt = 0; nt < 16; nt++) {
            int sh = (nt & 3) * 8 + 2 * t2;
            uint32_t wr0 = mw0[nt >> 2] >> sh;
            uint32_t wr1 = mw1[nt >> 2] >> sh;
            float s0 = (wr0 & 1u) ? sc[nt][0] * 0.125f : NEG_;
            float s1 = (wr0 & 2u) ? sc[nt][1] * 0.125f : NEG_;
            float s2 = (wr1 & 1u) ? sc[nt][2] * 0.125f : NEG_;
            float s3 = (wr1 & 2u) ? sc[nt][3] * 0.125f : NEG_;
            sc[nt][0] = s0; sc[nt][1] = s1; sc[nt][2] = s2; sc[nt][3] = s3;
            mx0 = fmaxf(mx0, fmaxf(s0, s1));
            mx1 = fmaxf(mx1, fmaxf(s2, s3));
        }
        mx0 = fmaxf(mx0, __shfl_xor_sync(0xffffffffu, mx0, 1));
        mx0 = fmaxf(mx0, __shfl_xor_sync(0xffffffffu, mx0, 2));
        mx1 = fmaxf(mx1, __shfl_xor_sync(0xffffffffu, mx1, 1));
        mx1 = fmaxf(mx1, __shfl_xor_sync(0xffffffffu, mx1, 2));

        float nm0 = fmaxf(rm0, mx0), nm1 = fmaxf(rm1, mx1);
        float a0 = __expf(rm0 - nm0), a1 = __expf(rm1 - nm1);
        rm0 = nm0; rm1 = nm1;

        float sum0 = 0.f, sum1 = 0.f;
#pragma unroll
        for (int nt = 0; nt < 16; nt++) {
            float p0 = __expf(sc[nt][0] - nm0);
            float p1 = __expf(sc[nt][1] - nm0);
            float p2 = __expf(sc[nt][2] - nm1);
            float p3 = __expf(sc[nt][3] - nm1);
            sc[nt][0] = p0; sc[nt][1] = p1; sc[nt][2] = p2; sc[nt][3] = p3;
            sum0 += p0 + p1; sum1 += p2 + p3;
        }
        sum0 += __shfl_xor_sync(0xffffffffu, sum0, 1);
        sum0 += __shfl_xor_sync(0xffffffffu, sum0, 2);
        sum1 += __shfl_xor_sync(0xffffffffu, sum1, 1);
        sum1 += __shfl_xor_sync(0xffffffffu, sum1, 2);
        rl0 = rl0 * a0 + sum0;
        rl1 = rl1 * a1 + sum1;

#pragma unroll
        for (int dt = 0; dt < 8; dt++) {
            O[dt][0] *= a0; O[dt][1] *= a0;
            O[dt][2] *= a1; O[dt][3] *= a1;
        }

        // ---- pack P hi/lo A-fragments ----
        uint32_t ph[8][4], plr[8][4];
#pragma unroll
        for (int ks = 0; ks < 8; ks++) {
            int n0 = 2 * ks, n1 = 2 * ks + 1;
            float x0 = sc[n0][0], x1 = sc[n0][1], x2 = sc[n0][2], x3 = sc[n0][3];
            float y0 = sc[n1][0], y1 = sc[n1][1], y2 = sc[n1][2], y3 = sc[n1][3];
            ph[ks][0] = pack_bf16x2(x0, x1);
            ph[ks][1] = pack_bf16x2(x2, x3);
            ph[ks][2] = pack_bf16x2(y0, y1);
            ph[ks][3] = pack_bf16x2(y2, y3);
            plr[ks][0] = pack_bf16x2(x0 - __bfloat162float(__float2bfloat16(x0)),
                                     x1 - __bfloat162float(__float2bfloat16(x1)));
            plr[ks][1] = pack_bf16x2(x2 - __bfloat162float(__float2bfloat16(x2)),
                                     x3 - __bfloat162float(__float2bfloat16(x3)));
            plr[ks][2] = pack_bf16x2(y0 - __bfloat162float(__float2bfloat16(y0)),
                                     y1 - __bfloat162float(__float2bfloat16(y1)));
            plr[ks][3] = pack_bf16x2(y2 - __bfloat162float(__float2bfloat16(y2)),
                                     y3 - __bfloat162float(__float2bfloat16(y3)));
        }

        // ---- O += P V (3-pass hi/lo), ks-outer with preloaded V frags (8-acc rotation) ----
#pragma unroll
        for (int ks = 0; ks < 8; ks++) {
            uint32_t vh4[4][4], vl4[4][4];
#pragma unroll
            for (int dt2 = 0; dt2 < 4; dt2++) {
                int row = ks * 16 + (g & 1) * 8 + ln;
                int col = dt2 * 16 + (g >> 1) * 8;
                uint32_t a = bb + SVH + (uint32_t)(row * 144 + col * 2);
                LDMX4T(vh4[dt2][0], vh4[dt2][1], vh4[dt2][2], vh4[dt2][3], a);
                LDMX4T(vl4[dt2][0], vl4[dt2][1], vl4[dt2][2], vl4[dt2][3], a + (SVL - SVH));
            }
#pragma unroll
            for (int dt2 = 0; dt2 < 4; dt2++) {
                MMA16816(O[2 * dt2],     ph[ks], &vh4[dt2][0]);
                MMA16816(O[2 * dt2 + 1], ph[ks], &vh4[dt2][2]);
            }
#pragma unroll
            for (int dt2 = 0; dt2 < 4; dt2++) {
                MMA16816(O[2 * dt2],     plr[ks], &vh4[dt2][0]);
                MMA16816(O[2 * dt2 + 1], plr[ks], &vh4[dt2][2]);
            }
#pragma unroll
            for (int dt2 = 0; dt2 < 4; dt2++) {
                MMA16816(O[2 * dt2],     ph[ks], &vl4[dt2][0]);
                MMA16816(O[2 * dt2 + 1], ph[ks], &vl4[dt2][2]);
            }
        }
        __syncthreads();
    }

    // ---- store partials (unnormalized) ----
    size_t pbase = ((size_t)(split * 64 + bh)) * 128;
    if (t2 == 0) {
        pm[pbase + r0] = rm0; pm[pbase + r1] = rm1;
        pl[pbase + r0] = rl0; pl[pbase + r1] = rl1;
    }
#pragma unroll
    for (int dt = 0; dt < 8; dt++) {
        int d = dt * 8 + 2 * t2;
        float2 o0; o0.x = O[dt][0]; o0.y = O[dt][1];
        float2 o1; o1.x = O[dt][2]; o1.y = O[dt][3];
        *(float2*)(pO + (pbase + r0) * 64 + d) = o0;
        *(float2*)(pO + (pbase + r1) * 64 + d) = o1;
    }
}

// ---------------- merge split-K partials -> ctx hi/lo ----------------
__global__ __launch_bounds__(256) void merge_kernel(
    const float* __restrict__ pm, const float* __restrict__ pl,
    const float* __restrict__ pO,
    __nv_bfloat16* __restrict__ cxhi, __nv_bfloat16* __restrict__ cxlo)
{
    int idx = blockIdx.x * 256 + threadIdx.x;
    if (idx >= 400 * 1024) return;
    int row = idx >> 10;
    int col = idx & 1023;
    int b = row / 100, q = row - b * 100;
    int h = col >> 6, d = col & 63;
    size_t p0 = ((size_t)(0 * 64 + b * 16 + h)) * 128 + q;
    size_t p1 = ((size_t)(1 * 64 + b * 16 + h)) * 128 + q;
    float m0 = pm[p0], m1 = pm[p1];
    float M = fmaxf(m0, m1);
    float w0 = __expf(m0 - M), w1 = __expf(m1 - M);
    float L = pl[p0] * w0 + pl[p1] * w1;
    float val = (pO[p0 * 64 + d] * w0 + pO[p1 * 64 + d] * w1) / L;
    __nv_bfloat16 hx = __float2bfloat16(val);
    cxhi[idx] = hx;
    cxlo[idx] = __float2bfloat16(val - __bfloat162float(hx));
}

// ---------------- launch ----------------
extern "C" void kernel_launch(void* const* d_in, const int* in_sizes, int n_in,
                              void* d_out, int out_size)
{
    const float* q    = (const float*)d_in[0];
    const float* kv   = (const float*)d_in[1];
    const int*   mask = (const int*)  d_in[2];
    const float* ipw  = (const float*)d_in[3];
    const float* ipb  = (const float*)d_in[4];
    const float* ow   = (const float*)d_in[5];
    const float* ob   = (const float*)d_in[6];
    const float* gq   = (const float*)d_in[7];
    const float* bq   = (const float*)d_in[8];
    const float* gkv  = (const float*)d_in[9];
    const float* bkv  = (const float*)d_in[10];
    float* out = (float*)d_out;

    __nv_bfloat16 *p_qn_hi, *p_qn_lo, *p_kvn_hi, *p_kvn_lo;
    __nv_bfloat16 *p_w_hi, *p_w_lo, *p_ow_hi, *p_ow_lo, *p_cx_hi, *p_cx_lo;
    __nv_bfloat16 *p_qhi, *p_qlo, *p_khi, *p_klo, *p_vhi, *p_vlo;
    float *p_pm, *p_pl, *p_pO;
    uint32_t* p_bits;
    cudaGetSymbolAddress((void**)&p_qn_hi,  g_qn_hi);
    cudaGetSymbolAddress((void**)&p_qn_lo,  g_qn_lo);
    cudaGetSymbolAddress((void**)&p_kvn_hi, g_kvn_hi);
    cudaGetSymbolAddress((void**)&p_kvn_lo, g_kvn_lo);
    cudaGetSymbolAddress((void**)&p_w_hi,   g_w_hi);
    cudaGetSymbolAddress((void**)&p_w_lo,   g_w_lo);
    cudaGetSymbolAddress((void**)&p_ow_hi,  g_ow_hi);
    cudaGetSymbolAddress((void**)&p_ow_lo,  g_ow_lo);
    cudaGetSymbolAddress((void**)&p_cx_hi,  g_cx_hi);
    cudaGetSymbolAddress((void**)&p_cx_lo,  g_cx_lo);
    cudaGetSymbolAddress((void**)&p_qhi, g_qhi);
    cudaGetSymbolAddress((void**)&p_qlo, g_qlo);
    cudaGetSymbolAddress((void**)&p_khi, g_khi);
    cudaGetSymbolAddress((void**)&p_klo, g_klo);
    cudaGetSymbolAddress((void**)&p_vhi, g_vhi);
    cudaGetSymbolAddress((void**)&p_vlo, g_vlo);
    cudaGetSymbolAddress((void**)&p_bits, g_bits);
    cudaGetSymbolAddress((void**)&p_pm, g_pm);
    cudaGetSymbolAddress((void**)&p_pl, g_pl);
    cudaGetSymbolAddress((void**)&p_pO, g_pO);

    const int SMEM8 = 2 * (2 * A_SZ + 2 * 128 * 80);   // 81920
    const int SMEM4 = 2 * (2 * A_SZ + 2 * 64 * 80);    // 61440
    cudaFuncSetAttribute(gemm_mma<0, 4>, cudaFuncAttributeMaxDynamicSharedMemorySize, SMEM4);
    cudaFuncSetAttribute(gemm_mma<1, 4>, cudaFuncAttributeMaxDynamicSharedMemorySize, SMEM4);
    cudaFuncSetAttribute(gemm_mma<2, 8>, cudaFuncAttributeMaxDynamicSharedMemorySize, SMEM8);
    cudaFuncSetAttribute(attn_mma, cudaFuncAttributeMaxDynamicSharedMemorySize, ATTN_SMEM);

    // layernorm + split
    ln_split_kernel<<<B_ * NQ_, 256>>>(q, gq, bq, p_qn_hi, p_qn_lo);
    ln_split_kernel<<<B_ * HW_, 256>>>(kv, gkv, bkv, p_kvn_hi, p_kvn_lo);
    maskpack_kernel<<<B_ * NQ_, 128>>>(mask, p_bits);

    // weight splits
    split_kernel<<<(3072 * 1024 / 4 + 255) / 256, 256>>>(ipw, p_w_hi, p_w_lo, 3072 * 1024 / 4);
    split_kernel<<<(1024 * 1024 / 4 + 255) / 256, 256>>>(ow, p_ow_hi, p_ow_lo, 1024 * 1024 / 4);

    // q projection -> head-major hi/lo (BN=64 -> 64 CTAs)
    gemm_mma<1, 4><<<dim3(16, 4), 256, SMEM4>>>(
        p_qn_hi, p_qn_lo, p_w_hi, p_w_lo, ipb, nullptr,
        p_qhi, p_qlo, nullptr, nullptr, B_ * NQ_, 1024);

    // kv projection -> head-major hi/lo K and V (BN=128 -> 2048 CTAs)
    gemm_mma<2, 8><<<dim3(16, 128), 256, SMEM8>>>(
        p_kvn_hi, p_kvn_lo,
        p_w_hi + (size_t)1024 * 1024, p_w_lo + (size_t)1024 * 1024,
        ipb + 1024, nullptr,
        p_khi, p_klo, p_vhi, p_vlo, B_ * HW_, 2048);

    // attention (split-K)
    attn_mma<<<dim3(64, ASPLIT), 256, ATTN_SMEM>>>(
        p_qhi, p_qlo, p_khi, p_klo, p_vhi, p_vlo, p_bits, p_pm, p_pl, p_pO);

    // merge -> ctx hi/lo
    merge_kernel<<<(400 * 1024 + 255) / 256, 256>>>(p_pm, p_pl, p_pO, p_cx_hi, p_cx_lo);

    // output projection (BN=64 -> 64 CTAs)
    gemm_mma<0, 4><<<dim3(16, 4), 256, SMEM4>>>(
        p_cx_hi, p_cx_lo, p_ow_hi, p_ow_lo, ob, out,
        nullptr, nullptr, nullptr, nullptr, B_ * NQ_, 1024);
}

// round 14
// speedup vs baseline: 4.6516x; 1.3546x over previous
#include <cuda_runtime.h>
#include <cuda_fp16.h>
#include <math.h>
#include <stdint.h>

#define B_  4
#define NQ_ 100
#define HW_ 4096
#define D_  1024
#define H_  16
#define HD_ 64
#define NEG_ (-1e9f)
#define ASPLIT 2
#define KEYS_PER_SPLIT (HW_ / ASPLIT)   // 2048
#define NT_PER_SPLIT   (KEYS_PER_SPLIT / 128)  // 16

// ---------------- scratch (device globals; no runtime allocation) ----------------
__device__ __half g_qn_hi [400  * 1024];
__device__ __half g_kvn_hi[16384 * 1024];
__device__ __half g_w_hi  [3072 * 1024];
__device__ __half g_w_lo  [3072 * 1024];
__device__ __half g_ow_hi [1024 * 1024];
__device__ __half g_ow_lo [1024 * 1024];
// head-major projections: [b*16+h][rows][64]
__device__ __half g_qhi[64 * 128 * 64];
__device__ __half g_khi[(size_t)64 * 4096 * 64];
__device__ __half g_klo[(size_t)64 * 4096 * 64];
__device__ __half g_vhi[(size_t)64 * 4096 * 64];
__device__ __half g_vlo[(size_t)64 * 4096 * 64];
__device__ __half g_cx_hi[400 * 1024];
__device__ uint32_t g_bits[400 * 128];
__device__ float g_pm[ASPLIT * 64 * 128];
__device__ float g_pl[ASPLIT * 64 * 128];
__device__ float g_pO[(size_t)ASPLIT * 64 * 128 * 64];

// ---------------- helpers ----------------
__device__ __forceinline__ uint32_t smem_u32(const void* p) {
    uint32_t a;
    asm("{ .reg .u64 t; cvta.to.shared.u64 t, %1; cvt.u32.u64 %0, t; }" : "=r"(a) : "l"(p));
    return a;
}
__device__ __forceinline__ void cp16(uint32_t dst, const void* src, int nbytes) {
    asm volatile("cp.async.cg.shared.global [%0], [%1], 16, %2;"
                 :: "r"(dst), "l"(src), "r"(nbytes));
}
#define CP_COMMIT() asm volatile("cp.async.commit_group;" ::: "memory")
#define CP_WAIT1()  asm volatile("cp.async.wait_group 1;" ::: "memory")
#define CP_WAIT0()  asm volatile("cp.async.wait_group 0;" ::: "memory")

#define LDMX4(r0, r1, r2, r3, addr) \
    asm volatile("ldmatrix.sync.aligned.m8n8.x4.shared.b16 {%0,%1,%2,%3}, [%4];" \
                 : "=r"(r0), "=r"(r1), "=r"(r2), "=r"(r3) : "r"(addr))
#define LDMX4T(r0, r1, r2, r3, addr) \
    asm volatile("ldmatrix.sync.aligned.m8n8.x4.trans.shared.b16 {%0,%1,%2,%3}, [%4];" \
                 : "=r"(r0), "=r"(r1), "=r"(r2), "=r"(r3) : "r"(addr))

#define MMA16816(c, a, b) \
    asm volatile("mma.sync.aligned.m16n8k16.row.col.f32.f16.f16.f32 " \
                 "{%0,%1,%2,%3}, {%4,%5,%6,%7}, {%8,%9}, {%0,%1,%2,%3};" \
                 : "+f"((c)[0]), "+f"((c)[1]), "+f"((c)[2]), "+f"((c)[3]) \
                 : "r"((a)[0]), "r"((a)[1]), "r"((a)[2]), "r"((a)[3]), \
                   "r"((b)[0]), "r"((b)[1]))

__device__ __forceinline__ uint32_t pack_f16x2(float lo_el, float hi_el) {
    uint32_t r;
    asm("cvt.rn.f16x2.f32 %0, %1, %2;" : "=r"(r) : "f"(hi_el), "f"(lo_el));
    return r;
}

// ---------------- layernorm -> fp16 hi (no lo; A-side of 2-pass GEMM) ----------------
__global__ __launch_bounds__(256) void ln_half_kernel(
    const float* __restrict__ x, const float* __restrict__ g,
    const float* __restrict__ b, __half* __restrict__ hi)
{
    __shared__ float red[32];
    int row = blockIdx.x;
    int tid = threadIdx.x;
    const float* xr = x + (size_t)row * D_;

    float v[4];
#pragma unroll
    for (int i = 0; i < 4; i++) v[i] = xr[tid + 256 * i];

    float s = v[0] + v[1] + v[2] + v[3];
#pragma unroll
    for (int o = 16; o > 0; o >>= 1) s += __shfl_xor_sync(0xffffffffu, s, o);
    if ((tid & 31) == 0) red[tid >> 5] = s;
    __syncthreads();
    float t = (tid < 8) ? red[tid] : 0.f;
    if (tid < 32) {
#pragma unroll
        for (int o = 4; o > 0; o >>= 1) t += __shfl_xor_sync(0xffffffffu, t, o);
        if (tid == 0) red[0] = t;
    }
    __syncthreads();
    float mu = red[0] * (1.0f / D_);
    __syncthreads();

    float sq = 0.f;
#pragma unroll
    for (int i = 0; i < 4; i++) { float d = v[i] - mu; sq += d * d; }
#pragma unroll
    for (int o = 16; o > 0; o >>= 1) sq += __shfl_xor_sync(0xffffffffu, sq, o);
    if ((tid & 31) == 0) red[tid >> 5] = sq;
    __syncthreads();
    float t2 = (tid < 8) ? red[tid] : 0.f;
    if (tid < 32) {
#pragma unroll
        for (int o = 4; o > 0; o >>= 1) t2 += __shfl_xor_sync(0xffffffffu, t2, o);
        if (tid == 0) red[0] = t2;
    }
    __syncthreads();
    float var = red[0] * (1.0f / D_);
    float inv = rsqrtf(var + 1e-5f);

#pragma unroll
    for (int i = 0; i < 4; i++) {
        int c = tid + 256 * i;
        float y = (v[i] - mu) * inv * g[c] + b[c];
        hi[(size_t)row * D_ + c] = __float2half(y);
    }
}

// ---------------- fp32 -> fp16 hi/lo split (weights; B-side keeps lo) ----------------
__global__ __launch_bounds__(256) void split_kernel(
    const float* __restrict__ x,
    __half* __restrict__ hi, __half* __restrict__ lo, int n4)
{
    int i = blockIdx.x * 256 + threadIdx.x;
    if (i >= n4) return;
    float4 v = ((const float4*)x)[i];
    __half h0 = __float2half(v.x);
    __half h1 = __float2half(v.y);
    __half h2 = __float2half(v.z);
    __half h3 = __float2half(v.w);
    __half2 hp0; hp0.x = h0; hp0.y = h1;
    __half2 hp1; hp1.x = h2; hp1.y = h3;
    __half2 lp0;
    lp0.x = __float2half(v.x - __half2float(h0));
    lp0.y = __float2half(v.y - __half2float(h1));
    __half2 lp1;
    lp1.x = __float2half(v.z - __half2float(h2));
    lp1.y = __float2half(v.w - __half2float(h3));
    ((__half2*)hi)[i * 2]     = hp0;
    ((__half2*)hi)[i * 2 + 1] = hp1;
    ((__half2*)lo)[i * 2]     = lp0;
    ((__half2*)lo)[i * 2 + 1] = lp1;
}

// ---------------- mask -> bitmask (has_any folded in: empty row => all ones) ----------------
__global__ __launch_bounds__(128) void maskpack_kernel(
    const int* __restrict__ mask, uint32_t* __restrict__ bits)
{
    int row = blockIdx.x;
    int tid = threadIdx.x;
    int wid = tid >> 5, lane = tid & 31;
    __shared__ uint32_t ws[128];
    const int* mr = mask + (size_t)row * HW_;
    int any = 0;
#pragma unroll
    for (int j = 0; j < 32; j++) {
        int v = mr[j * 128 + tid] != 0;
        any |= v;
        uint32_t bal = __ballot_sync(0xffffffffu, v);
        if (lane == 0) ws[j * 4 + wid] = bal;
    }
    int has = __syncthreads_or(any);
    bits[(size_t)row * 128 + tid] = has ? ws[tid] : 0xffffffffu;
}

// ---------------- mma.sync GEMM (fp16 2-pass: A_hi*B_hi + A_hi*B_lo) ----------------
// MODE 0: C fp32 + bias.  MODE 1: q head-split hi.  MODE 2: kv head-split hi/lo.
// NTT = per-warp n-tiles (8 -> BN=128, 4 -> BN=64). Warp grid 4x2.
#define A_SZ (128 * 80)                // 10240 bytes (A hi only, stride 80B)
#define NCHUNK 32

template<int MODE, int NTT>
__global__ __launch_bounds__(256) void gemm_mma(
    const __half* __restrict__ Ahi,
    const __half* __restrict__ Bhi, const __half* __restrict__ Blo,
    const float* __restrict__ bias, float* __restrict__ C,
    __half* __restrict__ ohi,
    __half* __restrict__ klo, __half* __restrict__ vhi, __half* __restrict__ vlo,
    int M, int Ntot)
{
    constexpr int BN   = NTT * 16;
    constexpr int B_SZ = BN * 80;
    constexpr int BUF  = A_SZ + 2 * B_SZ;

    extern __shared__ char sm[];
    uint32_t smb = smem_u32(sm);
    int tid = threadIdx.x;
    int wid = tid >> 5, lane = tid & 31;
    int wm = wid & 3, wn = wid >> 2;
    int row0 = blockIdx.y * 128;
    int col0 = blockIdx.x * BN;

    float acc[2][NTT][4];
#pragma unroll
    for (int a = 0; a < 2; a++)
#pragma unroll
        for (int b = 0; b < NTT; b++)
#pragma unroll
            for (int c = 0; c < 4; c++) acc[a][b][c] = 0.f;

    int r_a = tid >> 2, seg = (tid & 3);

    auto load_chunk = [&](int c, int buf) {
        uint32_t base = smb + buf * BUF;
#pragma unroll
        for (int it = 0; it < 2; it++) {
            int r = r_a + it * 64;
            int gr = row0 + r;
            uint32_t dst = base + (uint32_t)(r * 80 + seg * 16);
            int nb = (gr < M) ? 16 : 0;
            cp16(dst, Ahi + (size_t)gr * 1024 + c * 32 + seg * 8, nb);
        }
#pragma unroll
        for (int it = 0; it < BN / 64; it++) {
            int r = r_a + it * 64;
            int gr = col0 + r;
            uint32_t dst = base + A_SZ + (uint32_t)(r * 80 + seg * 16);
            cp16(dst,        Bhi + (size_t)gr * 1024 + c * 32 + seg * 8, 16);
            cp16(dst + B_SZ, Blo + (size_t)gr * 1024 + c * 32 + seg * 8, 16);
        }
    };

    load_chunk(0, 0);
    CP_COMMIT();

    for (int c = 0; c < NCHUNK; c++) {
        if (c + 1 < NCHUNK) {
            load_chunk(c + 1, (c + 1) & 1);
            CP_COMMIT();
            CP_WAIT1();
        } else {
            CP_WAIT0();
        }
        __syncthreads();

        uint32_t aBase = smb + (c & 1) * BUF;
        uint32_t bBase = aBase + A_SZ;
        int g = lane >> 3, ln = lane & 7;

#pragma unroll
        for (int s = 0; s < 2; s++) {
            int kc = s * 16;
            uint32_t ah[2][4], bh[NTT][2], bl[NTT][2];
#pragma unroll
            for (int mt = 0; mt < 2; mt++) {
                int row = wm * 32 + mt * 16 + (g & 1) * 8 + ln;
                int col = kc + (g >> 1) * 8;
                uint32_t addr = aBase + (uint32_t)(row * 80 + col * 2);
                LDMX4(ah[mt][0], ah[mt][1], ah[mt][2], ah[mt][3], addr);
            }
#pragma unroll
            for (int np = 0; np < NTT / 2; np++) {
                int nrow = wn * (BN / 2) + np * 16 + (g >> 1) * 8 + ln;
                int col = kc + (g & 1) * 8;
                uint32_t addr = bBase + (uint32_t)(nrow * 80 + col * 2);
                LDMX4(bh[np * 2][0], bh[np * 2][1], bh[np * 2 + 1][0], bh[np * 2 + 1][1], addr);
                LDMX4(bl[np * 2][0], bl[np * 2][1], bl[np * 2 + 1][0], bl[np * 2 + 1][1], addr + B_SZ);
            }
            // pass-outer ordering: same-acc spacing = 2*NTT instructions
#pragma unroll
            for (int mt = 0; mt < 2; mt++)
#pragma unroll
                for (int nt = 0; nt < NTT; nt++)
                    MMA16816(acc[mt][nt], ah[mt], bh[nt]);
#pragma unroll
            for (int mt = 0; mt < 2; mt++)
#pragma unroll
                for (int nt = 0; nt < NTT; nt++)
                    MMA16816(acc[mt][nt], ah[mt], bl[nt]);
        }
        __syncthreads();
    }

    // epilogue
    int qrow = lane >> 2, qcol = (lane & 3) * 2;
    int cbase = col0 + wn * (BN / 2);
#pragma unroll
    for (int mt = 0; mt < 2; mt++) {
#pragma unroll
        for (int half = 0; half < 2; half++) {
            int r = row0 + wm * 32 + mt * 16 + qrow + half * 8;
            if (r >= M) continue;
#pragma unroll
            for (int nt = 0; nt < NTT; nt++) {
                int cix = nt * 8 + qcol;
                int cglob = cbase + cix;
                float2 bv = *(const float2*)&bias[cglob];
                float vx = acc[mt][nt][half * 2 + 0] + bv.x;
                float vy = acc[mt][nt][half * 2 + 1] + bv.y;
                if (MODE == 0) {
                    float2 o; o.x = vx; o.y = vy;
                    *(float2*)(C + (size_t)r * Ntot + cglob) = o;
                } else if (MODE == 1) {
                    __half2 hp; hp.x = __float2half(vx); hp.y = __float2half(vy);
                    int bb = r / 100, qq = r - bb * 100;
                    int hh = cglob >> 6;
                    size_t di = (((size_t)(bb * 16 + hh)) * 128 + qq) * 64 + (cglob & 63);
                    *(__half2*)(ohi + di) = hp;
                } else {
                    __half hx = __float2half(vx);
                    __half hy = __float2half(vy);
                    __half2 hp; hp.x = hx; hp.y = hy;
                    __half2 lp;
                    lp.x = __float2half(vx - __half2float(hx));
                    lp.y = __float2half(vy - __half2float(hy));
                    int bb = r >> 12, kp = r & 4095;
                    int hh = (cglob >> 6) & 15;
                    size_t di = (((size_t)(bb * 16 + hh)) * 4096 + kp) * 64 + (cglob & 63);
                    if (cglob < 1024) {
                        *(__half2*)(ohi + di) = hp;
                        *(__half2*)(klo + di) = lp;
                    } else {
                        *(__half2*)(vhi + di) = hp;
                        *(__half2*)(vlo + di) = lp;
                    }
                }
            }
        }
    }
}

// ---------------- flash attention via mma.sync (fp16 2-pass) ----------------
// grid (64 bh, ASPLIT). 256 threads = 8 warps, warp w owns q-rows [16w, 16w+16).
// smem: QH | 2 x (KH | KL | VH | VL), row stride 144B
#define SQH 0
#define SBUF0 18432
#define SBUFSZ 73728
#define SKH 0
#define SKL 18432
#define SVH 36864
#define SVL 55296
#define ATTN_SMEM (SBUF0 + 2 * SBUFSZ)   // 165888

__global__ __launch_bounds__(256) void attn_mma(
    const __half* __restrict__ qhi,
    const __half* __restrict__ khi, const __half* __restrict__ klo,
    const __half* __restrict__ vhi, const __half* __restrict__ vlo,
    const uint32_t* __restrict__ bits,
    float* __restrict__ pm, float* __restrict__ pl, float* __restrict__ pO)
{
    extern __shared__ char sm[];
    uint32_t smb = smem_u32(sm);
    int tid = threadIdx.x;
    int wid = tid >> 5, lane = tid & 31;
    int bh = blockIdx.x;
    int split = blockIdx.y;
    int bB = bh >> 4;
    int wr = wid * 16;
    int g = lane >> 3, ln = lane & 7;

    // ---- load Q hi (zero-padded rows >= 100) ----
#pragma unroll
    for (int it = 0; it < 4; it++) {
        int i = tid + it * 256;
        int r = i >> 3, sg = i & 7;
        size_t goff = ((size_t)bh * 128 + r) * 64 + sg * 8;
        int nb = (r < NQ_) ? 16 : 0;
        uint32_t so = (uint32_t)(r * 144 + sg * 16);
        cp16(smb + SQH + so, qhi + goff, nb);
    }
    CP_COMMIT();

    auto load_tile = [&](int kt, int buf) {
        int k0 = split * KEYS_PER_SPLIT + kt * 128;
        uint32_t base = smb + SBUF0 + buf * SBUFSZ;
#pragma unroll
        for (int it = 0; it < 4; it++) {
            int i = tid + it * 256;
            int r = i >> 3, sg = i & 7;
            size_t goff = ((size_t)bh * 4096 + k0 + r) * 64 + sg * 8;
            uint32_t so = (uint32_t)(r * 144 + sg * 16);
            cp16(base + SKH + so, khi + goff, 16);
            cp16(base + SKL + so, klo + goff, 16);
            cp16(base + SVH + so, vhi + goff, 16);
            cp16(base + SVL + so, vlo + goff, 16);
        }
    };

    load_tile(0, 0);
    CP_COMMIT();
    CP_WAIT1();           // Q group done
    __syncthreads();

    // ---- Q fragments (persist across tiles) ----
    uint32_t qh[4][4];
#pragma unroll
    for (int ks = 0; ks < 4; ks++) {
        int row = wr + (g & 1) * 8 + ln;
        int col = ks * 16 + (g >> 1) * 8;
        uint32_t a = smb + SQH + (uint32_t)(row * 144 + col * 2);
        LDMX4(qh[ks][0], qh[ks][1], qh[ks][2], qh[ks][3], a);
    }

    int r0 = wr + (lane >> 2);
    int r1 = r0 + 8;
    int t2 = lane & 3;

    float rm0 = -INFINITY, rm1 = -INFINITY, rl0 = 0.f, rl1 = 0.f;
    float O[8][4];
#pragma unroll
    for (int dt = 0; dt < 8; dt++)
#pragma unroll
        for (int j = 0; j < 4; j++) O[dt][j] = 0.f;

    for (int kt = 0; kt < NT_PER_SPLIT; kt++) {
        if (kt + 1 < NT_PER_SPLIT) {
            load_tile(kt + 1, (kt + 1) & 1);
            CP_COMMIT();
            CP_WAIT1();
        } else {
            CP_WAIT0();
        }
        __syncthreads();

        uint32_t bb = smb + SBUF0 + (kt & 1) * SBUFSZ;
        int k0 = split * KEYS_PER_SPLIT + kt * 128;

        // ---- scores S = Q K^T (2-pass: qh*kh + qh*kl) ----
        float sc[16][4];
#pragma unroll
        for (int nt = 0; nt < 16; nt++)
#pragma unroll
            for (int j = 0; j < 4; j++) sc[nt][j] = 0.f;

#pragma unroll
        for (int npp = 0; npp < 4; npp++) {
            uint32_t kh2[2][4][4], kl2[2][4][4];
#pragma unroll
            for (int j = 0; j < 2; j++) {
                int np = npp * 2 + j;
#pragma unroll
                for (int ks = 0; ks < 4; ks++) {
                    int row = np * 16 + (g >> 1) * 8 + ln;
                    int col = ks * 16 + (g & 1) * 8;
                    uint32_t a = bb + SKH + (uint32_t)(row * 144 + col * 2);
                    LDMX4(kh2[j][ks][0], kh2[j][ks][1], kh2[j][ks][2], kh2[j][ks][3], a);
                    LDMX4(kl2[j][ks][0], kl2[j][ks][1], kl2[j][ks][2], kl2[j][ks][3], a + (SKL - SKH));
                }
            }
#pragma unroll
            for (int ks = 0; ks < 4; ks++) {
#pragma unroll
                for (int j = 0; j < 2; j++) {
                    MMA16816(sc[4 * npp + 2 * j],     qh[ks], &kh2[j][ks][0]);
                    MMA16816(sc[4 * npp + 2 * j + 1], qh[ks], &kh2[j][ks][2]);
                }
#pragma unroll
                for (int j = 0; j < 2; j++) {
                    MMA16816(sc[4 * npp + 2 * j],     qh[ks], &kl2[j][ks][0]);
                    MMA16816(sc[4 * npp + 2 * j + 1], qh[ks], &kl2[j][ks][2]);
                }
            }
        }

        // ---- mask + scale ----
        uint32_t mw0[4], mw1[4];
        int woff = k0 >> 5;
        if (r0 < NQ_) *(uint4*)mw0 = *(const uint4*)(bits + (size_t)(bB * 100 + r0) * 128 + woff);
        else { mw0[0] = mw0[1] = mw0[2] = mw0[3] = 0xffffffffu; }
        if (r1 < NQ_) *(uint4*)mw1 = *(const uint4*)(bits + (size_t)(bB * 100 + r1) * 128 + woff);
        else { mw1[0] = mw1[1] = mw1[2] = mw1[3] = 0xffffffffu; }

        float mx0 = -INFINITY, mx1 = -INFINITY;
#pragma unroll
        for (int nt = 0; nt < 16; nt++) {
            int sh = (nt & 3) * 8 + 2 * t2;
            uint32_t wr0 = mw0[nt >> 2] >> sh;
            uint32_t wr1 = mw1[nt >> 2] >> sh;
            float s0 = (wr0 & 1u) ? sc[nt][0] * 0.125f : NEG_;
            float s1 = (wr0 & 2u) ? sc[nt][1] * 0.125f : NEG_;
            float s2 = (wr1 & 1u) ? sc[nt][2] * 0.125f : NEG_;
            float s3 = (wr1 & 2u) ? sc[nt][3] * 0.125f : NEG_;
            sc[nt][0] = s0; sc[nt][1] = s1; sc[nt][2] = s2; sc[nt][3] = s3;
            mx0 = fmaxf(mx0, fmaxf(s0, s1));
            mx1 = fmaxf(mx1, fmaxf(s2, s3));
        }
        mx0 = fmaxf(mx0, __shfl_xor_sync(0xffffffffu, mx0, 1));
        mx0 = fmaxf(mx0, __shfl_xor_sync(0xffffffffu, mx0, 2));
        mx1 = fmaxf(mx1, __shfl_xor_sync(0xffffffffu, mx1, 1));
        mx1 = fmaxf(mx1, __shfl_xor_sync(0xffffffffu, mx1, 2));

        float nm0 = fmaxf(rm0, mx0), nm1 = fmaxf(rm1, mx1);
        float a0 = __expf(rm0 - nm0), a1 = __expf(rm1 - nm1);
        rm0 = nm0; rm1 = nm1;

        float sum0 = 0.f, sum1 = 0.f;
#pragma unroll
        for (int nt = 0; nt < 16; nt++) {
            float p0 = __expf(sc[nt][0] - nm0);
            float p1 = __expf(sc[nt][1] - nm0);
            float p2 = __expf(sc[nt][2] - nm1);
            float p3 = __expf(sc[nt][3] - nm1);
            sc[nt][0] = p0; sc[nt][1] = p1; sc[nt][2] = p2; sc[nt][3] = p3;
            sum0 += p0 + p1; sum1 += p2 + p3;
        }
        sum0 += __shfl_xor_sync(0xffffffffu, sum0, 1);
        sum0 += __shfl_xor_sync(0xffffffffu, sum0, 2);
        sum1 += __shfl_xor_sync(0xffffffffu, sum1, 1);
        sum1 += __shfl_xor_sync(0xffffffffu, sum1, 2);
        rl0 = rl0 * a0 + sum0;
        rl1 = rl1 * a1 + sum1;

#pragma unroll
        for (int dt = 0; dt < 8; dt++) {
            O[dt][0] *= a0; O[dt][1] *= a0;
            O[dt][2] *= a1; O[dt][3] *= a1;
        }

        // ---- pack P fp16 A-fragments (hi only) ----
        uint32_t ph[8][4];
#pragma unroll
        for (int ks = 0; ks < 8; ks++) {
            int n0 = 2 * ks, n1 = 2 * ks + 1;
            ph[ks][0] = pack_f16x2(sc[n0][0], sc[n0][1]);
            ph[ks][1] = pack_f16x2(sc[n0][2], sc[n0][3]);
            ph[ks][2] = pack_f16x2(sc[n1][0], sc[n1][1]);
            ph[ks][3] = pack_f16x2(sc[n1][2], sc[n1][3]);
        }

        // ---- O += P V (2-pass: ph*vh + ph*vl), ks-outer with preloaded V frags ----
#pragma unroll
        for (int ks = 0; ks < 8; ks++) {
            uint32_t vh4[4][4], vl4[4][4];
#pragma unroll
            for (int dt2 = 0; dt2 < 4; dt2++) {
                int row = ks * 16 + (g & 1) * 8 + ln;
                int col = dt2 * 16 + (g >> 1) * 8;
                uint32_t a = bb + SVH + (uint32_t)(row * 144 + col * 2);
                LDMX4T(vh4[dt2][0], vh4[dt2][1], vh4[dt2][2], vh4[dt2][3], a);
                LDMX4T(vl4[dt2][0], vl4[dt2][1], vl4[dt2][2], vl4[dt2][3], a + (SVL - SVH));
            }
#pragma unroll
            for (int dt2 = 0; dt2 < 4; dt2++) {
                MMA16816(O[2 * dt2],     ph[ks], &vh4[dt2][0]);
                MMA16816(O[2 * dt2 + 1], ph[ks], &vh4[dt2][2]);
            }
#pragma unroll
            for (int dt2 = 0; dt2 < 4; dt2++) {
                MMA16816(O[2 * dt2],     ph[ks], &vl4[dt2][0]);
                MMA16816(O[2 * dt2 + 1], ph[ks], &vl4[dt2][2]);
            }
        }
        __syncthreads();
    }

    // ---- store partials (unnormalized) ----
    size_t pbase = ((size_t)(split * 64 + bh)) * 128;
    if (t2 == 0) {
        pm[pbase + r0] = rm0; pm[pbase + r1] = rm1;
        pl[pbase + r0] = rl0; pl[pbase + r1] = rl1;
    }
#pragma unroll
    for (int dt = 0; dt < 8; dt++) {
        int d = dt * 8 + 2 * t2;
        float2 o0; o0.x = O[dt][0]; o0.y = O[dt][1];
        float2 o1; o1.x = O[dt][2]; o1.y = O[dt][3];
        *(float2*)(pO + (pbase + r0) * 64 + d) = o0;
        *(float2*)(pO + (pbase + r1) * 64 + d) = o1;
    }
}

// ---------------- merge split-K partials -> ctx fp16 hi ----------------
__global__ __launch_bounds__(256) void merge_kernel(
    const float* __restrict__ pm, const float* __restrict__ pl,
    const float* __restrict__ pO, __half* __restrict__ cxhi)
{
    int idx = blockIdx.x * 256 + threadIdx.x;
    if (idx >= 400 * 1024) return;
    int row = idx >> 10;
    int col = idx & 1023;
    int b = row / 100, q = row - b * 100;
    int h = col >> 6, d = col & 63;
    size_t p0 = ((size_t)(0 * 64 + b * 16 + h)) * 128 + q;
    size_t p1 = ((size_t)(1 * 64 + b * 16 + h)) * 128 + q;
    float m0 = pm[p0], m1 = pm[p1];
    float M = fmaxf(m0, m1);
    float w0 = __expf(m0 - M), w1 = __expf(m1 - M);
    float L = pl[p0] * w0 + pl[p1] * w1;
    float val = (pO[p0 * 64 + d] * w0 + pO[p1 * 64 + d] * w1) / L;
    cxhi[idx] = __float2half(val);
}

// ---------------- launch ----------------
extern "C" void kernel_launch(void* const* d_in, const int* in_sizes, int n_in,
                              void* d_out, int out_size)
{
    const float* q    = (const float*)d_in[0];
    const float* kv   = (const float*)d_in[1];
    const int*   mask = (const int*)  d_in[2];
    const float* ipw  = (const float*)d_in[3];
    const float* ipb  = (const float*)d_in[4];
    const float* ow   = (const float*)d_in[5];
    const float* ob   = (const float*)d_in[6];
    const float* gq   = (const float*)d_in[7];
    const float* bq   = (const float*)d_in[8];
    const float* gkv  = (const float*)d_in[9];
    const float* bkv  = (const float*)d_in[10];
    float* out = (float*)d_out;

    __half *p_qn_hi, *p_kvn_hi, *p_w_hi, *p_w_lo, *p_ow_hi, *p_ow_lo, *p_cx_hi;
    __half *p_qhi, *p_khi, *p_klo, *p_vhi, *p_vlo;
    float *p_pm, *p_pl, *p_pO;
    uint32_t* p_bits;
    cudaGetSymbolAddress((void**)&p_qn_hi,  g_qn_hi);
    cudaGetSymbolAddress((void**)&p_kvn_hi, g_kvn_hi);
    cudaGetSymbolAddress((void**)&p_w_hi,   g_w_hi);
    cudaGetSymbolAddress((void**)&p_w_lo,   g_w_lo);
    cudaGetSymbolAddress((void**)&p_ow_hi,  g_ow_hi);
    cudaGetSymbolAddress((void**)&p_ow_lo,  g_ow_lo);
    cudaGetSymbolAddress((void**)&p_cx_hi,  g_cx_hi);
    cudaGetSymbolAddress((void**)&p_qhi, g_qhi);
    cudaGetSymbolAddress((void**)&p_khi, g_khi);
    cudaGetSymbolAddress((void**)&p_klo, g_klo);
    cudaGetSymbolAddress((void**)&p_vhi, g_vhi);
    cudaGetSymbolAddress((void**)&p_vlo, g_vlo);
    cudaGetSymbolAddress((void**)&p_bits, g_bits);
    cudaGetSymbolAddress((void**)&p_pm, g_pm);
    cudaGetSymbolAddress((void**)&p_pl, g_pl);
    cudaGetSymbolAddress((void**)&p_pO, g_pO);

    const int SMEM8 = 2 * (A_SZ + 2 * 128 * 80);   // 61440
    const int SMEM4 = 2 * (A_SZ + 2 * 64 * 80);    // 40960
    cudaFuncSetAttribute(gemm_mma<0, 4>, cudaFuncAttributeMaxDynamicSharedMemorySize, SMEM4);
    cudaFuncSetAttribute(gemm_mma<1, 4>, cudaFuncAttributeMaxDynamicSharedMemorySize, SMEM4);
    cudaFuncSetAttribute(gemm_mma<2, 8>, cudaFuncAttributeMaxDynamicSharedMemorySize, SMEM8);
    cudaFuncSetAttribute(attn_mma, cudaFuncAttributeMaxDynamicSharedMemorySize, ATTN_SMEM);

    // layernorm (fp16 hi only)
    ln_half_kernel<<<B_ * NQ_, 256>>>(q, gq, bq, p_qn_hi);
    ln_half_kernel<<<B_ * HW_, 256>>>(kv, gkv, bkv, p_kvn_hi);
    maskpack_kernel<<<B_ * NQ_, 128>>>(mask, p_bits);

    // weight splits (fp16 hi/lo)
    split_kernel<<<(3072 * 1024 / 4 + 255) / 256, 256>>>(ipw, p_w_hi, p_w_lo, 3072 * 1024 / 4);
    split_kernel<<<(1024 * 1024 / 4 + 255) / 256, 256>>>(ow, p_ow_hi, p_ow_lo, 1024 * 1024 / 4);

    // q projection -> head-major hi (BN=64 -> 64 CTAs)
    gemm_mma<1, 4><<<dim3(16, 4), 256, SMEM4>>>(
        p_qn_hi, p_w_hi, p_w_lo, ipb, nullptr,
        p_qhi, nullptr, nullptr, nullptr, B_ * NQ_, 1024);

    // kv projection -> head-major hi/lo K and V (BN=128 -> 2048 CTAs)
    gemm_mma<2, 8><<<dim3(16, 128), 256, SMEM8>>>(
        p_kvn_hi,
        p_w_hi + (size_t)1024 * 1024, p_w_lo + (size_t)1024 * 1024,
        ipb + 1024, nullptr,
        p_khi, p_klo, p_vhi, p_vlo, B_ * HW_, 2048);

    // attention (split-K)
    attn_mma<<<dim3(64, ASPLIT), 256, ATTN_SMEM>>>(
        p_qhi, p_khi, p_klo, p_vhi, p_vlo, p_bits, p_pm, p_pl, p_pO);

    // merge -> ctx fp16 hi
    merge_kernel<<<(400 * 1024 + 255) / 256, 256>>>(p_pm, p_pl, p_pO, p_cx_hi);

    // output projection (BN=64 -> 64 CTAs)
    gemm_mma<0, 4><<<dim3(16, 4), 256, SMEM4>>>(
        p_cx_hi, p_ow_hi, p_ow_lo, ob, out,
        nullptr, nullptr, nullptr, nullptr, B_ * NQ_, 1024);
}

// round 15
// speedup vs baseline: 4.6585x; 1.0015x over previous
#include <cuda_runtime.h>
#include <cuda_fp16.h>
#include <math.h>
#include <stdint.h>

#define B_  4
#define NQ_ 100
#define HW_ 4096
#define D_  1024
#define H_  16
#define HD_ 64
#define NEG_ (-1e9f)
#define ASPLIT 2
#define KEYS_PER_SPLIT (HW_ / ASPLIT)   // 2048
#define NT_PER_SPLIT   (KEYS_PER_SPLIT / 128)  // 16

// ---------------- scratch (device globals; no runtime allocation) ----------------
__device__ __half g_qn_hi [400  * 1024];
__device__ __half g_kvn_hi[16384 * 1024];
__device__ __half g_w_hi  [3072 * 1024];
__device__ __half g_w_lo  [3072 * 1024];
__device__ __half g_ow_hi [1024 * 1024];
__device__ __half g_ow_lo [1024 * 1024];
// head-major projections: [b*16+h][rows][64]
__device__ __half g_qhi[64 * 128 * 64];
__device__ __half g_khi[(size_t)64 * 4096 * 64];
__device__ __half g_klo[(size_t)64 * 4096 * 64];
__device__ __half g_vhi[(size_t)64 * 4096 * 64];
__device__ __half g_vlo[(size_t)64 * 4096 * 64];
__device__ __half g_cx_hi[400 * 1024];
__device__ uint32_t g_bits[400 * 128];
__device__ float g_pm[ASPLIT * 64 * 128];
__device__ float g_pl[ASPLIT * 64 * 128];
__device__ float g_pO[(size_t)ASPLIT * 64 * 128 * 64];

// ---------------- helpers ----------------
__device__ __forceinline__ uint32_t smem_u32(const void* p) {
    uint32_t a;
    asm("{ .reg .u64 t; cvta.to.shared.u64 t, %1; cvt.u32.u64 %0, t; }" : "=r"(a) : "l"(p));
    return a;
}
__device__ __forceinline__ void cp16(uint32_t dst, const void* src, int nbytes) {
    asm volatile("cp.async.cg.shared.global [%0], [%1], 16, %2;"
                 :: "r"(dst), "l"(src), "r"(nbytes));
}
#define CP_COMMIT() asm volatile("cp.async.commit_group;" ::: "memory")
#define CP_WAIT1()  asm volatile("cp.async.wait_group 1;" ::: "memory")
#define CP_WAIT0()  asm volatile("cp.async.wait_group 0;" ::: "memory")

#define LDMX4(r0, r1, r2, r3, addr) \
    asm volatile("ldmatrix.sync.aligned.m8n8.x4.shared.b16 {%0,%1,%2,%3}, [%4];" \
                 : "=r"(r0), "=r"(r1), "=r"(r2), "=r"(r3) : "r"(addr))
#define LDMX4T(r0, r1, r2, r3, addr) \
    asm volatile("ldmatrix.sync.aligned.m8n8.x4.trans.shared.b16 {%0,%1,%2,%3}, [%4];" \
                 : "=r"(r0), "=r"(r1), "=r"(r2), "=r"(r3) : "r"(addr))

#define MMA16816(c, a, b) \
    asm volatile("mma.sync.aligned.m16n8k16.row.col.f32.f16.f16.f32 " \
                 "{%0,%1,%2,%3}, {%4,%5,%6,%7}, {%8,%9}, {%0,%1,%2,%3};" \
                 : "+f"((c)[0]), "+f"((c)[1]), "+f"((c)[2]), "+f"((c)[3]) \
                 : "r"((a)[0]), "r"((a)[1]), "r"((a)[2]), "r"((a)[3]), \
                   "r"((b)[0]), "r"((b)[1]))

__device__ __forceinline__ uint32_t pack_f16x2(float lo_el, float hi_el) {
    uint32_t r;
    asm("cvt.rn.f16x2.f32 %0, %1, %2;" : "=r"(r) : "f"(hi_el), "f"(lo_el));
    return r;
}

// ---------------- layernorm -> fp16 hi ----------------
__global__ __launch_bounds__(256) void ln_half_kernel(
    const float* __restrict__ x, const float* __restrict__ g,
    const float* __restrict__ b, __half* __restrict__ hi)
{
    __shared__ float red[32];
    int row = blockIdx.x;
    int tid = threadIdx.x;
    const float* xr = x + (size_t)row * D_;

    float v[4];
#pragma unroll
    for (int i = 0; i < 4; i++) v[i] = xr[tid + 256 * i];

    float s = v[0] + v[1] + v[2] + v[3];
#pragma unroll
    for (int o = 16; o > 0; o >>= 1) s += __shfl_xor_sync(0xffffffffu, s, o);
    if ((tid & 31) == 0) red[tid >> 5] = s;
    __syncthreads();
    float t = (tid < 8) ? red[tid] : 0.f;
    if (tid < 32) {
#pragma unroll
        for (int o = 4; o > 0; o >>= 1) t += __shfl_xor_sync(0xffffffffu, t, o);
        if (tid == 0) red[0] = t;
    }
    __syncthreads();
    float mu = red[0] * (1.0f / D_);
    __syncthreads();

    float sq = 0.f;
#pragma unroll
    for (int i = 0; i < 4; i++) { float d = v[i] - mu; sq += d * d; }
#pragma unroll
    for (int o = 16; o > 0; o >>= 1) sq += __shfl_xor_sync(0xffffffffu, sq, o);
    if ((tid & 31) == 0) red[tid >> 5] = sq;
    __syncthreads();
    float t2 = (tid < 8) ? red[tid] : 0.f;
    if (tid < 32) {
#pragma unroll
        for (int o = 4; o > 0; o >>= 1) t2 += __shfl_xor_sync(0xffffffffu, t2, o);
        if (tid == 0) red[0] = t2;
    }
    __syncthreads();
    float var = red[0] * (1.0f / D_);
    float inv = rsqrtf(var + 1e-5f);

#pragma unroll
    for (int i = 0; i < 4; i++) {
        int c = tid + 256 * i;
        float y = (v[i] - mu) * inv * g[c] + b[c];
        hi[(size_t)row * D_ + c] = __float2half(y);
    }
}

// ---------------- fp32 -> fp16 hi/lo split (weights) ----------------
__global__ __launch_bounds__(256) void split_kernel(
    const float* __restrict__ x,
    __half* __restrict__ hi, __half* __restrict__ lo, int n4)
{
    int i = blockIdx.x * 256 + threadIdx.x;
    if (i >= n4) return;
    float4 v = ((const float4*)x)[i];
    __half h0 = __float2half(v.x);
    __half h1 = __float2half(v.y);
    __half h2 = __float2half(v.z);
    __half h3 = __float2half(v.w);
    __half2 hp0; hp0.x = h0; hp0.y = h1;
    __half2 hp1; hp1.x = h2; hp1.y = h3;
    __half2 lp0;
    lp0.x = __float2half(v.x - __half2float(h0));
    lp0.y = __float2half(v.y - __half2float(h1));
    __half2 lp1;
    lp1.x = __float2half(v.z - __half2float(h2));
    lp1.y = __float2half(v.w - __half2float(h3));
    ((__half2*)hi)[i * 2]     = hp0;
    ((__half2*)hi)[i * 2 + 1] = hp1;
    ((__half2*)lo)[i * 2]     = lp0;
    ((__half2*)lo)[i * 2 + 1] = lp1;
}

// ---------------- mask -> bitmask ----------------
__global__ __launch_bounds__(128) void maskpack_kernel(
    const int* __restrict__ mask, uint32_t* __restrict__ bits)
{
    int row = blockIdx.x;
    int tid = threadIdx.x;
    int wid = tid >> 5, lane = tid & 31;
    __shared__ uint32_t ws[128];
    const int* mr = mask + (size_t)row * HW_;
    int any = 0;
#pragma unroll
    for (int j = 0; j < 32; j++) {
        int v = mr[j * 128 + tid] != 0;
        any |= v;
        uint32_t bal = __ballot_sync(0xffffffffu, v);
        if (lane == 0) ws[j * 4 + wid] = bal;
    }
    int has = __syncthreads_or(any);
    bits[(size_t)row * 128 + tid] = has ? ws[tid] : 0xffffffffu;
}

// ---------------- mma.sync GEMM (fp16 2-pass), generalized tiles ----------------
// MODE 0: C fp32 + bias.  MODE 1: q head-split hi.  MODE 2: kv head-split hi/lo.
// Warp grid WMW x WNW; per warp MTT m16-tiles and NTT n8-tiles.
#define NCHUNK 32

template<int MODE, int MTT, int NTT, int WMW, int WNW>
__global__ __launch_bounds__(WMW * WNW * 32) void gemm_mma(
    const __half* __restrict__ Ahi,
    const __half* __restrict__ Bhi, const __half* __restrict__ Blo,
    const float* __restrict__ bias, float* __restrict__ C,
    __half* __restrict__ ohi,
    __half* __restrict__ klo, __half* __restrict__ vhi, __half* __restrict__ vlo,
    int M, int Ntot)
{
    constexpr int THREADS = WMW * WNW * 32;
    constexpr int BM = WMW * MTT * 16;
    constexpr int BN = WNW * NTT * 8;
    constexpr int A_SZT = BM * 80;
    constexpr int B_SZT = BN * 80;
    constexpr int BUF = A_SZT + 2 * B_SZT;

    extern __shared__ char sm[];
    uint32_t smb = smem_u32(sm);
    int tid = threadIdx.x;
    int wid = tid >> 5, lane = tid & 31;
    int wm = wid % WMW, wn = wid / WMW;
    int row0 = blockIdx.y * BM;
    int col0 = blockIdx.x * BN;

    float acc[MTT][NTT][4];
#pragma unroll
    for (int a = 0; a < MTT; a++)
#pragma unroll
        for (int b = 0; b < NTT; b++)
#pragma unroll
            for (int c = 0; c < 4; c++) acc[a][b][c] = 0.f;

    int r_a = tid >> 2, seg = (tid & 3);

    auto load_chunk = [&](int c, int buf) {
        uint32_t base = smb + buf * BUF;
#pragma unroll
        for (int it = 0; it < BM / (THREADS / 4); it++) {
            int r = r_a + it * (THREADS / 4);
            int gr = row0 + r;
            int nb = (gr < M) ? 16 : 0;
            cp16(base + (uint32_t)(r * 80 + seg * 16),
                 Ahi + (size_t)gr * 1024 + c * 32 + seg * 8, nb);
        }
#pragma unroll
        for (int it = 0; it < BN / (THREADS / 4); it++) {
            int r = r_a + it * (THREADS / 4);
            int gr = col0 + r;
            uint32_t dst = base + A_SZT + (uint32_t)(r * 80 + seg * 16);
            cp16(dst,         Bhi + (size_t)gr * 1024 + c * 32 + seg * 8, 16);
            cp16(dst + B_SZT, Blo + (size_t)gr * 1024 + c * 32 + seg * 8, 16);
        }
    };

    load_chunk(0, 0);
    CP_COMMIT();

    for (int c = 0; c < NCHUNK; c++) {
        if (c + 1 < NCHUNK) {
            load_chunk(c + 1, (c + 1) & 1);
            CP_COMMIT();
            CP_WAIT1();
        } else {
            CP_WAIT0();
        }
        __syncthreads();

        uint32_t aBase = smb + (c & 1) * BUF;
        uint32_t bBase = aBase + A_SZT;
        int g = lane >> 3, ln = lane & 7;

#pragma unroll
        for (int s = 0; s < 2; s++) {
            int kc = s * 16;
            uint32_t ah[MTT][4], bh[NTT][2], bl[NTT][2];
#pragma unroll
            for (int mt = 0; mt < MTT; mt++) {
                int row = wm * (MTT * 16) + mt * 16 + (g & 1) * 8 + ln;
                int col = kc + (g >> 1) * 8;
                uint32_t addr = aBase + (uint32_t)(row * 80 + col * 2);
                LDMX4(ah[mt][0], ah[mt][1], ah[mt][2], ah[mt][3], addr);
            }
#pragma unroll
            for (int np = 0; np < NTT / 2; np++) {
                int nrow = wn * (NTT * 8) + np * 16 + (g >> 1) * 8 + ln;
                int col = kc + (g & 1) * 8;
                uint32_t addr = bBase + (uint32_t)(nrow * 80 + col * 2);
                LDMX4(bh[np * 2][0], bh[np * 2][1], bh[np * 2 + 1][0], bh[np * 2 + 1][1], addr);
                LDMX4(bl[np * 2][0], bl[np * 2][1], bl[np * 2 + 1][0], bl[np * 2 + 1][1], addr + B_SZT);
            }
            // pass-outer ordering
#pragma unroll
            for (int mt = 0; mt < MTT; mt++)
#pragma unroll
                for (int nt = 0; nt < NTT; nt++)
                    MMA16816(acc[mt][nt], ah[mt], bh[nt]);
#pragma unroll
            for (int mt = 0; mt < MTT; mt++)
#pragma unroll
                for (int nt = 0; nt < NTT; nt++)
                    MMA16816(acc[mt][nt], ah[mt], bl[nt]);
        }
        __syncthreads();
    }

    // epilogue
    int qrow = lane >> 2, qcol = (lane & 3) * 2;
    int cbase = col0 + wn * (NTT * 8);
#pragma unroll
    for (int mt = 0; mt < MTT; mt++) {
#pragma unroll
        for (int half = 0; half < 2; half++) {
            int r = row0 + wm * (MTT * 16) + mt * 16 + qrow + half * 8;
            if (r >= M) continue;
#pragma unroll
            for (int nt = 0; nt < NTT; nt++) {
                int cix = nt * 8 + qcol;
                int cglob = cbase + cix;
                float2 bv = *(const float2*)&bias[cglob];
                float vx = acc[mt][nt][half * 2 + 0] + bv.x;
                float vy = acc[mt][nt][half * 2 + 1] + bv.y;
                if (MODE == 0) {
                    float2 o; o.x = vx; o.y = vy;
                    *(float2*)(C + (size_t)r * Ntot + cglob) = o;
                } else if (MODE == 1) {
                    __half2 hp; hp.x = __float2half(vx); hp.y = __float2half(vy);
                    int bb = r / 100, qq = r - bb * 100;
                    int hh = cglob >> 6;
                    size_t di = (((size_t)(bb * 16 + hh)) * 128 + qq) * 64 + (cglob & 63);
                    *(__half2*)(ohi + di) = hp;
                } else {
                    __half hx = __float2half(vx);
                    __half hy = __float2half(vy);
                    __half2 hp; hp.x = hx; hp.y = hy;
                    __half2 lp;
                    lp.x = __float2half(vx - __half2float(hx));
                    lp.y = __float2half(vy - __half2float(hy));
                    int bb = r >> 12, kp = r & 4095;
                    int hh = (cglob >> 6) & 15;
                    size_t di = (((size_t)(bb * 16 + hh)) * 4096 + kp) * 64 + (cglob & 63);
                    if (cglob < 1024) {
                        *(__half2*)(ohi + di) = hp;
                        *(__half2*)(klo + di) = lp;
                    } else {
                        *(__half2*)(vhi + di) = hp;
                        *(__half2*)(vlo + di) = lp;
                    }
                }
            }
        }
    }
}

// ---------------- flash attention via mma.sync (fp16 2-pass) ----------------
#define SQH 0
#define SBUF0 18432
#define SBUFSZ 73728
#define SKH 0
#define SKL 18432
#define SVH 36864
#define SVL 55296
#define ATTN_SMEM (SBUF0 + 2 * SBUFSZ)   // 165888

__global__ __launch_bounds__(256) void attn_mma(
    const __half* __restrict__ qhi,
    const __half* __restrict__ khi, const __half* __restrict__ klo,
    const __half* __restrict__ vhi, const __half* __restrict__ vlo,
    const uint32_t* __restrict__ bits,
    float* __restrict__ pm, float* __restrict__ pl, float* __restrict__ pO)
{
    extern __shared__ char sm[];
    uint32_t smb = smem_u32(sm);
    int tid = threadIdx.x;
    int wid = tid >> 5, lane = tid & 31;
    int bh = blockIdx.x;
    int split = blockIdx.y;
    int bB = bh >> 4;
    int wr = wid * 16;
    int g = lane >> 3, ln = lane & 7;

#pragma unroll
    for (int it = 0; it < 4; it++) {
        int i = tid + it * 256;
        int r = i >> 3, sg = i & 7;
        size_t goff = ((size_t)bh * 128 + r) * 64 + sg * 8;
        int nb = (r < NQ_) ? 16 : 0;
        uint32_t so = (uint32_t)(r * 144 + sg * 16);
        cp16(smb + SQH + so, qhi + goff, nb);
    }
    CP_COMMIT();

    auto load_tile = [&](int kt, int buf) {
        int k0 = split * KEYS_PER_SPLIT + kt * 128;
        uint32_t base = smb + SBUF0 + buf * SBUFSZ;
#pragma unroll
        for (int it = 0; it < 4; it++) {
            int i = tid + it * 256;
            int r = i >> 3, sg = i & 7;
            size_t goff = ((size_t)bh * 4096 + k0 + r) * 64 + sg * 8;
            uint32_t so = (uint32_t)(r * 144 + sg * 16);
            cp16(base + SKH + so, khi + goff, 16);
            cp16(base + SKL + so, klo + goff, 16);
            cp16(base + SVH + so, vhi + goff, 16);
            cp16(base + SVL + so, vlo + goff, 16);
        }
    };

    load_tile(0, 0);
    CP_COMMIT();
    CP_WAIT1();
    __syncthreads();

    uint32_t qh[4][4];
#pragma unroll
    for (int ks = 0; ks < 4; ks++) {
        int row = wr + (g & 1) * 8 + ln;
        int col = ks * 16 + (g >> 1) * 8;
        uint32_t a = smb + SQH + (uint32_t)(row * 144 + col * 2);
        LDMX4(qh[ks][0], qh[ks][1], qh[ks][2], qh[ks][3], a);
    }

    int r0 = wr + (lane >> 2);
    int r1 = r0 + 8;
    int t2 = lane & 3;

    float rm0 = -INFINITY, rm1 = -INFINITY, rl0 = 0.f, rl1 = 0.f;
    float O[8][4];
#pragma unroll
    for (int dt = 0; dt < 8; dt++)
#pragma unroll
        for (int j = 0; j < 4; j++) O[dt][j] = 0.f;

    for (int kt = 0; kt < NT_PER_SPLIT; kt++) {
        if (kt + 1 < NT_PER_SPLIT) {
            load_tile(kt + 1, (kt + 1) & 1);
            CP_COMMIT();
            CP_WAIT1();
        } else {
            CP_WAIT0();
        }
        __syncthreads();

        uint32_t bb = smb + SBUF0 + (kt & 1) * SBUFSZ;
        int k0 = split * KEYS_PER_SPLIT + kt * 128;

        float sc[16][4];
#pragma unroll
        for (int nt = 0; nt < 16; nt++)
#pragma unroll
            for (int j = 0; j < 4; j++) sc[nt][j] = 0.f;

#pragma unroll
        for (int npp = 0; npp < 4; npp++) {
            uint32_t kh2[2][4][4], kl2[2][4][4];
#pragma unroll
            for (int j = 0; j < 2; j++) {
                int np = npp * 2 + j;
#pragma unroll
                for (int ks = 0; ks < 4; ks++) {
                    int row = np * 16 + (g >> 1) * 8 + ln;
                    int col = ks * 16 + (g & 1) * 8;
                    uint32_t a = bb + SKH + (uint32_t)(row * 144 + col * 2);
                    LDMX4(kh2[j][ks][0], kh2[j][ks][1], kh2[j][ks][2], kh2[j][ks][3], a);
                    LDMX4(kl2[j][ks][0], kl2[j][ks][1], kl2[j][ks][2], kl2[j][ks][3], a + (SKL - SKH));
                }
            }
#pragma unroll
            for (int ks = 0; ks < 4; ks++) {
#pragma unroll
                for (int j = 0; j < 2; j++) {
                    MMA16816(sc[4 * npp + 2 * j],     qh[ks], &kh2[j][ks][0]);
                    MMA16816(sc[4 * npp + 2 * j + 1], qh[ks], &kh2[j][ks][2]);
                }
#pragma unroll
                for (int j = 0; j < 2; j++) {
                    MMA16816(sc[4 * npp + 2 * j],     qh[ks], &kl2[j][ks][0]);
                    MMA16816(sc[4 * npp + 2 * j + 1], qh[ks], &kl2[j][ks][2]);
                }
            }
        }

        uint32_t mw0[4], mw1[4];
        int woff = k0 >> 5;
        if (r0 < NQ_) *(uint4*)mw0 = *(const uint4*)(bits + (size_t)(bB * 100 + r0) * 128 + woff);
        else { mw0[0] = mw0[1] = mw0[2] = mw0[3] = 0xffffffffu; }
        if (r1 < NQ_) *(uint4*)mw1 = *(const uint4*)(bits + (size_t)(bB * 100 + r1) * 128 + woff);
        else { mw1[0] = mw1[1] = mw1[2] = mw1[3] = 0xffffffffu; }

        float mx0 = -INFINITY, mx1 = -INFINITY;
#pragma unroll
        for (int nt = 0; nt < 16; nt++) {
            int sh = (nt & 3) * 8 + 2 * t2;
            uint32_t wr0 = mw0[nt >> 2] >> sh;
            uint32_t wr1 = mw1[nt >> 2] >> sh;
            float s0 = (wr0 & 1u) ? sc[nt][0] * 0.125f : NEG_;
            float s1 = (wr0 & 2u) ? sc[nt][1] * 0.125f : NEG_;
            float s2 = (wr1 & 1u) ? sc[nt][2] * 0.125f : NEG_;
            float s3 = (wr1 & 2u) ? sc[nt][3] * 0.125f : NEG_;
            sc[nt][0] = s0; sc[nt][1] = s1; sc[nt][2] = s2; sc[nt][3] = s3;
            mx0 = fmaxf(mx0, fmaxf(s0, s1));
            mx1 = fmaxf(mx1, fmaxf(s2, s3));
        }
        mx0 = fmaxf(mx0, __shfl_xor_sync(0xffffffffu, mx0, 1));
        mx0 = fmaxf(mx0, __shfl_xor_sync(0xffffffffu, mx0, 2));
        mx1 = fmaxf(mx1, __shfl_xor_sync(0xffffffffu, mx1, 1));
        mx1 = fmaxf(mx1, __shfl_xor_sync(0xffffffffu, mx1, 2));

        float nm0 = fmaxf(rm0, mx0), nm1 = fmaxf(rm1, mx1);
        float a0 = __expf(rm0 - nm0), a1 = __expf(rm1 - nm1);
        rm0 = nm0; rm1 = nm1;

        float sum0 = 0.f, sum1 = 0.f;
#pragma unroll
        for (int nt = 0; nt < 16; nt++) {
            float p0 = __expf(sc[nt][0] - nm0);
            float p1 = __expf(sc[nt][1] - nm0);
            float p2 = __expf(sc[nt][2] - nm1);
            float p3 = __expf(sc[nt][3] - nm1);
            sc[nt][0] = p0; sc[nt][1] = p1; sc[nt][2] = p2; sc[nt][3] = p3;
            sum0 += p0 + p1; sum1 += p2 + p3;
        }
        sum0 += __shfl_xor_sync(0xffffffffu, sum0, 1);
        sum0 += __shfl_xor_sync(0xffffffffu, sum0, 2);
        sum1 += __shfl_xor_sync(0xffffffffu, sum1, 1);
        sum1 += __shfl_xor_sync(0xffffffffu, sum1, 2);
        rl0 = rl0 * a0 + sum0;
        rl1 = rl1 * a1 + sum1;

#pragma unroll
        for (int dt = 0; dt < 8; dt++) {
            O[dt][0] *= a0; O[dt][1] *= a0;
            O[dt][2] *= a1; O[dt][3] *= a1;
        }

        uint32_t ph[8][4];
#pragma unroll
        for (int ks = 0; ks < 8; ks++) {
            int n0 = 2 * ks, n1 = 2 * ks + 1;
            ph[ks][0] = pack_f16x2(sc[n0][0], sc[n0][1]);
            ph[ks][1] = pack_f16x2(sc[n0][2], sc[n0][3]);
            ph[ks][2] = pack_f16x2(sc[n1][0], sc[n1][1]);
            ph[ks][3] = pack_f16x2(sc[n1][2], sc[n1][3]);
        }

#pragma unroll
        for (int ks = 0; ks < 8; ks++) {
            uint32_t vh4[4][4], vl4[4][4];
#pragma unroll
            for (int dt2 = 0; dt2 < 4; dt2++) {
                int row = ks * 16 + (g & 1) * 8 + ln;
                int col = dt2 * 16 + (g >> 1) * 8;
                uint32_t a = bb + SVH + (uint32_t)(row * 144 + col * 2);
                LDMX4T(vh4[dt2][0], vh4[dt2][1], vh4[dt2][2], vh4[dt2][3], a);
                LDMX4T(vl4[dt2][0], vl4[dt2][1], vl4[dt2][2], vl4[dt2][3], a + (SVL - SVH));
            }
#pragma unroll
            for (int dt2 = 0; dt2 < 4; dt2++) {
                MMA16816(O[2 * dt2],     ph[ks], &vh4[dt2][0]);
                MMA16816(O[2 * dt2 + 1], ph[ks], &vh4[dt2][2]);
            }
#pragma unroll
            for (int dt2 = 0; dt2 < 4; dt2++) {
                MMA16816(O[2 * dt2],     ph[ks], &vl4[dt2][0]);
                MMA16816(O[2 * dt2 + 1], ph[ks], &vl4[dt2][2]);
            }
        }
        __syncthreads();
    }

    size_t pbase = ((size_t)(split * 64 + bh)) * 128;
    if (t2 == 0) {
        pm[pbase + r0] = rm0; pm[pbase + r1] = rm1;
        pl[pbase + r0] = rl0; pl[pbase + r1] = rl1;
    }
#pragma unroll
    for (int dt = 0; dt < 8; dt++) {
        int d = dt * 8 + 2 * t2;
        float2 o0; o0.x = O[dt][0]; o0.y = O[dt][1];
        float2 o1; o1.x = O[dt][2]; o1.y = O[dt][3];
        *(float2*)(pO + (pbase + r0) * 64 + d) = o0;
        *(float2*)(pO + (pbase + r1) * 64 + d) = o1;
    }
}

// ---------------- merge split-K partials -> ctx fp16 hi ----------------
__global__ __launch_bounds__(256) void merge_kernel(
    const float* __restrict__ pm, const float* __restrict__ pl,
    const float* __restrict__ pO, __half* __restrict__ cxhi)
{
    int idx = blockIdx.x * 256 + threadIdx.x;
    if (idx >= 400 * 1024) return;
    int row = idx >> 10;
    int col = idx & 1023;
    int b = row / 100, q = row - b * 100;
    int h = col >> 6, d = col & 63;
    size_t p0 = ((size_t)(0 * 64 + b * 16 + h)) * 128 + q;
    size_t p1 = ((size_t)(1 * 64 + b * 16 + h)) * 128 + q;
    float m0 = pm[p0], m1 = pm[p1];
    float M = fmaxf(m0, m1);
    float w0 = __expf(m0 - M), w1 = __expf(m1 - M);
    float L = pl[p0] * w0 + pl[p1] * w1;
    float val = (pO[p0 * 64 + d] * w0 + pO[p1 * 64 + d] * w1) / L;
    cxhi[idx] = __float2half(val);
}

// ---------------- launch ----------------
extern "C" void kernel_launch(void* const* d_in, const int* in_sizes, int n_in,
                              void* d_out, int out_size)
{
    const float* q    = (const float*)d_in[0];
    const float* kv   = (const float*)d_in[1];
    const int*   mask = (const int*)  d_in[2];
    const float* ipw  = (const float*)d_in[3];
    const float* ipb  = (const float*)d_in[4];
    const float* ow   = (const float*)d_in[5];
    const float* ob   = (const float*)d_in[6];
    const float* gq   = (const float*)d_in[7];
    const float* bq   = (const float*)d_in[8];
    const float* gkv  = (const float*)d_in[9];
    const float* bkv  = (const float*)d_in[10];
    float* out = (float*)d_out;

    __half *p_qn_hi, *p_kvn_hi, *p_w_hi, *p_w_lo, *p_ow_hi, *p_ow_lo, *p_cx_hi;
    __half *p_qhi, *p_khi, *p_klo, *p_vhi, *p_vlo;
    float *p_pm, *p_pl, *p_pO;
    uint32_t* p_bits;
    cudaGetSymbolAddress((void**)&p_qn_hi,  g_qn_hi);
    cudaGetSymbolAddress((void**)&p_kvn_hi, g_kvn_hi);
    cudaGetSymbolAddress((void**)&p_w_hi,   g_w_hi);
    cudaGetSymbolAddress((void**)&p_w_lo,   g_w_lo);
    cudaGetSymbolAddress((void**)&p_ow_hi,  g_ow_hi);
    cudaGetSymbolAddress((void**)&p_ow_lo,  g_ow_lo);
    cudaGetSymbolAddress((void**)&p_cx_hi,  g_cx_hi);
    cudaGetSymbolAddress((void**)&p_qhi, g_qhi);
    cudaGetSymbolAddress((void**)&p_khi, g_khi);
    cudaGetSymbolAddress((void**)&p_klo, g_klo);
    cudaGetSymbolAddress((void**)&p_vhi, g_vhi);
    cudaGetSymbolAddress((void**)&p_vlo, g_vlo);
    cudaGetSymbolAddress((void**)&p_bits, g_bits);
    cudaGetSymbolAddress((void**)&p_pm, g_pm);
    cudaGetSymbolAddress((void**)&p_pl, g_pl);
    cudaGetSymbolAddress((void**)&p_pO, g_pO);

    // small gemms: BM=128, BN=64 (warp grid 4x2, mt=2, nt=4), 256 threads
    const int SMEM_S = 2 * (128 * 80 + 2 * 64 * 80);       // 41040? -> 2*(10240+10240)=40960
    // kv gemm: BM=256, BN=128 (warp grid 4x4, mt=4, nt=4), 512 threads
    const int SMEM_K = 2 * (256 * 80 + 2 * 128 * 80);      // 2*(20480+20480)=81920
    cudaFuncSetAttribute((const void*)gemm_mma<0, 2, 4, 4, 2>,
                         cudaFuncAttributeMaxDynamicSharedMemorySize, SMEM_S);
    cudaFuncSetAttribute((const void*)gemm_mma<1, 2, 4, 4, 2>,
                         cudaFuncAttributeMaxDynamicSharedMemorySize, SMEM_S);
    cudaFuncSetAttribute((const void*)gemm_mma<2, 4, 4, 4, 4>,
                         cudaFuncAttributeMaxDynamicSharedMemorySize, SMEM_K);
    cudaFuncSetAttribute(attn_mma, cudaFuncAttributeMaxDynamicSharedMemorySize, ATTN_SMEM);

    // layernorm (fp16 hi only)
    ln_half_kernel<<<B_ * NQ_, 256>>>(q, gq, bq, p_qn_hi);
    ln_half_kernel<<<B_ * HW_, 256>>>(kv, gkv, bkv, p_kvn_hi);
    maskpack_kernel<<<B_ * NQ_, 128>>>(mask, p_bits);

    // weight splits (fp16 hi/lo)
    split_kernel<<<(3072 * 1024 / 4 + 255) / 256, 256>>>(ipw, p_w_hi, p_w_lo, 3072 * 1024 / 4);
    split_kernel<<<(1024 * 1024 / 4 + 255) / 256, 256>>>(ow, p_ow_hi, p_ow_lo, 1024 * 1024 / 4);

    // q projection -> head-major hi (BN=64 -> 64 CTAs, 256 thr)
    gemm_mma<1, 2, 4, 4, 2><<<dim3(16, 4), 256, SMEM_S>>>(
        p_qn_hi, p_w_hi, p_w_lo, ipb, nullptr,
        p_qhi, nullptr, nullptr, nullptr, B_ * NQ_, 1024);

    // kv projection -> head-major hi/lo K and V (BM=256/BN=128 -> 1024 CTAs, 512 thr)
    gemm_mma<2, 4, 4, 4, 4><<<dim3(16, 64), 512, SMEM_K>>>(
        p_kvn_hi,
        p_w_hi + (size_t)1024 * 1024, p_w_lo + (size_t)1024 * 1024,
        ipb + 1024, nullptr,
        p_khi, p_klo, p_vhi, p_vlo, B_ * HW_, 2048);

    // attention (split-K)
    attn_mma<<<dim3(64, ASPLIT), 256, ATTN_SMEM>>>(
        p_qhi, p_khi, p_klo, p_vhi, p_vlo, p_bits, p_pm, p_pl, p_pO);

    // merge -> ctx fp16 hi
    merge_kernel<<<(400 * 1024 + 255) / 256, 256>>>(p_pm, p_pl, p_pO, p_cx_hi);

    // output projection (BN=64 -> 64 CTAs, 256 thr)
    gemm_mma<0, 2, 4, 4, 2><<<dim3(16, 4), 256, SMEM_S>>>(
        p_cx_hi, p_ow_hi, p_ow_lo, ob, out,
        nullptr, nullptr, nullptr, nullptr, B_ * NQ_, 1024);
}

// round 16
// speedup vs baseline: 6.0263x; 1.2936x over previous
#include <cuda_runtime.h>
#include <cuda_fp16.h>
#include <math.h>
#include <stdint.h>

#define B_  4
#define NQ_ 100
#define HW_ 4096
#define D_  1024
#define H_  16
#define HD_ 64
#define NEG_ (-1e9f)
#define ASPLIT 2
#define KEYS_PER_SPLIT (HW_ / ASPLIT)   // 2048
#define NT_PER_SPLIT   (KEYS_PER_SPLIT / 128)  // 16

// ---------------- scratch (device globals; no runtime allocation) ----------------
__device__ __half g_qn_hi [400  * 1024];
__device__ __half g_kvn_hi[16384 * 1024];
__device__ __half g_w_hi  [3072 * 1024];
__device__ __half g_w_lo  [3072 * 1024];
__device__ __half g_ow_hi [1024 * 1024];
__device__ __half g_ow_lo [1024 * 1024];
// head-major projections: [b*16+h][rows][64]
__device__ __half g_qhi[64 * 128 * 64];
__device__ __half g_khi[(size_t)64 * 4096 * 64];
__device__ __half g_klo[(size_t)64 * 4096 * 64];
__device__ __half g_vhi[(size_t)64 * 4096 * 64];
__device__ __half g_vlo[(size_t)64 * 4096 * 64];
__device__ __half g_cx_hi[400 * 1024];
__device__ uint32_t g_bits[400 * 128];
__device__ float g_pm[ASPLIT * 64 * 128];
__device__ float g_pl[ASPLIT * 64 * 128];
__device__ float g_pO[(size_t)ASPLIT * 64 * 128 * 64];

// ---------------- helpers ----------------
__device__ __forceinline__ uint32_t smem_u32(const void* p) {
    uint32_t a;
    asm("{ .reg .u64 t; cvta.to.shared.u64 t, %1; cvt.u32.u64 %0, t; }" : "=r"(a) : "l"(p));
    return a;
}
__device__ __forceinline__ void cp16(uint32_t dst, const void* src, int nbytes) {
    asm volatile("cp.async.cg.shared.global [%0], [%1], 16, %2;"
                 :: "r"(dst), "l"(src), "r"(nbytes));
}
#define CP_COMMIT() asm volatile("cp.async.commit_group;" ::: "memory")
#define CP_WAIT1()  asm volatile("cp.async.wait_group 1;" ::: "memory")
#define CP_WAIT0()  asm volatile("cp.async.wait_group 0;" ::: "memory")

#define LDMX4(r0, r1, r2, r3, addr) \
    asm volatile("ldmatrix.sync.aligned.m8n8.x4.shared.b16 {%0,%1,%2,%3}, [%4];" \
                 : "=r"(r0), "=r"(r1), "=r"(r2), "=r"(r3) : "r"(addr))
#define LDMX4T(r0, r1, r2, r3, addr) \
    asm volatile("ldmatrix.sync.aligned.m8n8.x4.trans.shared.b16 {%0,%1,%2,%3}, [%4];" \
                 : "=r"(r0), "=r"(r1), "=r"(r2), "=r"(r3) : "r"(addr))

#define MMA16816(c, a, b) \
    asm volatile("mma.sync.aligned.m16n8k16.row.col.f32.f16.f16.f32 " \
                 "{%0,%1,%2,%3}, {%4,%5,%6,%7}, {%8,%9}, {%0,%1,%2,%3};" \
                 : "+f"((c)[0]), "+f"((c)[1]), "+f"((c)[2]), "+f"((c)[3]) \
                 : "r"((a)[0]), "r"((a)[1]), "r"((a)[2]), "r"((a)[3]), \
                   "r"((b)[0]), "r"((b)[1]))

__device__ __forceinline__ uint32_t pack_f16x2(float lo_el, float hi_el) {
    uint32_t r;
    asm("cvt.rn.f16x2.f32 %0, %1, %2;" : "=r"(r) : "f"(hi_el), "f"(lo_el));
    return r;
}

// ---------------- layernorm -> fp16 hi ----------------
__global__ __launch_bounds__(256) void ln_half_kernel(
    const float* __restrict__ x, const float* __restrict__ g,
    const float* __restrict__ b, __half* __restrict__ hi)
{
    __shared__ float red[32];
    int row = blockIdx.x;
    int tid = threadIdx.x;
    const float* xr = x + (size_t)row * D_;

    float v[4];
#pragma unroll
    for (int i = 0; i < 4; i++) v[i] = xr[tid + 256 * i];

    float s = v[0] + v[1] + v[2] + v[3];
#pragma unroll
    for (int o = 16; o > 0; o >>= 1) s += __shfl_xor_sync(0xffffffffu, s, o);
    if ((tid & 31) == 0) red[tid >> 5] = s;
    __syncthreads();
    float t = (tid < 8) ? red[tid] : 0.f;
    if (tid < 32) {
#pragma unroll
        for (int o = 4; o > 0; o >>= 1) t += __shfl_xor_sync(0xffffffffu, t, o);
        if (tid == 0) red[0] = t;
    }
    __syncthreads();
    float mu = red[0] * (1.0f / D_);
    __syncthreads();

    float sq = 0.f;
#pragma unroll
    for (int i = 0; i < 4; i++) { float d = v[i] - mu; sq += d * d; }
#pragma unroll
    for (int o = 16; o > 0; o >>= 1) sq += __shfl_xor_sync(0xffffffffu, sq, o);
    if ((tid & 31) == 0) red[tid >> 5] = sq;
    __syncthreads();
    float t2 = (tid < 8) ? red[tid] : 0.f;
    if (tid < 32) {
#pragma unroll
        for (int o = 4; o > 0; o >>= 1) t2 += __shfl_xor_sync(0xffffffffu, t2, o);
        if (tid == 0) red[0] = t2;
    }
    __syncthreads();
    float var = red[0] * (1.0f / D_);
    float inv = rsqrtf(var + 1e-5f);

#pragma unroll
    for (int i = 0; i < 4; i++) {
        int c = tid + 256 * i;
        float y = (v[i] - mu) * inv * g[c] + b[c];
        hi[(size_t)row * D_ + c] = __float2half(y);
    }
}

// ---------------- fp32 -> fp16 hi/lo split (weights) ----------------
__global__ __launch_bounds__(256) void split_kernel(
    const float* __restrict__ x,
    __half* __restrict__ hi, __half* __restrict__ lo, int n4)
{
    int i = blockIdx.x * 256 + threadIdx.x;
    if (i >= n4) return;
    float4 v = ((const float4*)x)[i];
    __half h0 = __float2half(v.x);
    __half h1 = __float2half(v.y);
    __half h2 = __float2half(v.z);
    __half h3 = __float2half(v.w);
    __half2 hp0; hp0.x = h0; hp0.y = h1;
    __half2 hp1; hp1.x = h2; hp1.y = h3;
    __half2 lp0;
    lp0.x = __float2half(v.x - __half2float(h0));
    lp0.y = __float2half(v.y - __half2float(h1));
    __half2 lp1;
    lp1.x = __float2half(v.z - __half2float(h2));
    lp1.y = __float2half(v.w - __half2float(h3));
    ((__half2*)hi)[i * 2]     = hp0;
    ((__half2*)hi)[i * 2 + 1] = hp1;
    ((__half2*)lo)[i * 2]     = lp0;
    ((__half2*)lo)[i * 2 + 1] = lp1;
}

// ---------------- mask -> bitmask ----------------
__global__ __launch_bounds__(128) void maskpack_kernel(
    const int* __restrict__ mask, uint32_t* __restrict__ bits)
{
    int row = blockIdx.x;
    int tid = threadIdx.x;
    int wid = tid >> 5, lane = tid & 31;
    __shared__ uint32_t ws[128];
    const int* mr = mask + (size_t)row * HW_;
    int any = 0;
#pragma unroll
    for (int j = 0; j < 32; j++) {
        int v = mr[j * 128 + tid] != 0;
        any |= v;
        uint32_t bal = __ballot_sync(0xffffffffu, v);
        if (lane == 0) ws[j * 4 + wid] = bal;
    }
    int has = __syncthreads_or(any);
    bits[(size_t)row * 128 + tid] = has ? ws[tid] : 0xffffffffu;
}

// ---------------- mma.sync GEMM, generalized tiles, BPASS in {1,2} ----------------
// MODE 0: C fp32 + bias.  MODE 1: q head-split hi.  MODE 2: kv head-split hi/lo.
#define NCHUNK 32

template<int MODE, int MTT, int NTT, int WMW, int WNW, int BPASS>
__global__ __launch_bounds__(WMW * WNW * 32) void gemm_mma(
    const __half* __restrict__ Ahi,
    const __half* __restrict__ Bhi, const __half* __restrict__ Blo,
    const float* __restrict__ bias, float* __restrict__ C,
    __half* __restrict__ ohi,
    __half* __restrict__ klo, __half* __restrict__ vhi, __half* __restrict__ vlo,
    int M, int Ntot)
{
    constexpr int THREADS = WMW * WNW * 32;
    constexpr int BM = WMW * MTT * 16;
    constexpr int BN = WNW * NTT * 8;
    constexpr int A_SZT = BM * 80;
    constexpr int B_SZT = BN * 80;
    constexpr int BUF = A_SZT + BPASS * B_SZT;

    extern __shared__ char sm[];
    uint32_t smb = smem_u32(sm);
    int tid = threadIdx.x;
    int wid = tid >> 5, lane = tid & 31;
    int wm = wid % WMW, wn = wid / WMW;
    int row0 = blockIdx.y * BM;
    int col0 = blockIdx.x * BN;

    float acc[MTT][NTT][4];
#pragma unroll
    for (int a = 0; a < MTT; a++)
#pragma unroll
        for (int b = 0; b < NTT; b++)
#pragma unroll
            for (int c = 0; c < 4; c++) acc[a][b][c] = 0.f;

    int r_a = tid >> 2, seg = (tid & 3);

    auto load_chunk = [&](int c, int buf) {
        uint32_t base = smb + buf * BUF;
#pragma unroll
        for (int it = 0; it < BM / (THREADS / 4); it++) {
            int r = r_a + it * (THREADS / 4);
            int gr = row0 + r;
            int nb = (gr < M) ? 16 : 0;
            cp16(base + (uint32_t)(r * 80 + seg * 16),
                 Ahi + (size_t)gr * 1024 + c * 32 + seg * 8, nb);
        }
#pragma unroll
        for (int it = 0; it < BN / (THREADS / 4); it++) {
            int r = r_a + it * (THREADS / 4);
            int gr = col0 + r;
            uint32_t dst = base + A_SZT + (uint32_t)(r * 80 + seg * 16);
            cp16(dst, Bhi + (size_t)gr * 1024 + c * 32 + seg * 8, 16);
            if (BPASS == 2)
                cp16(dst + B_SZT, Blo + (size_t)gr * 1024 + c * 32 + seg * 8, 16);
        }
    };

    load_chunk(0, 0);
    CP_COMMIT();

    for (int c = 0; c < NCHUNK; c++) {
        if (c + 1 < NCHUNK) {
            load_chunk(c + 1, (c + 1) & 1);
            CP_COMMIT();
            CP_WAIT1();
        } else {
            CP_WAIT0();
        }
        __syncthreads();

        uint32_t aBase = smb + (c & 1) * BUF;
        uint32_t bBase = aBase + A_SZT;
        int g = lane >> 3, ln = lane & 7;

#pragma unroll
        for (int s = 0; s < 2; s++) {
            int kc = s * 16;
            uint32_t ah[MTT][4], bh[NTT][2], bl[NTT][2];
#pragma unroll
            for (int mt = 0; mt < MTT; mt++) {
                int row = wm * (MTT * 16) + mt * 16 + (g & 1) * 8 + ln;
                int col = kc + (g >> 1) * 8;
                uint32_t addr = aBase + (uint32_t)(row * 80 + col * 2);
                LDMX4(ah[mt][0], ah[mt][1], ah[mt][2], ah[mt][3], addr);
            }
#pragma unroll
            for (int np = 0; np < NTT / 2; np++) {
                int nrow = wn * (NTT * 8) + np * 16 + (g >> 1) * 8 + ln;
                int col = kc + (g & 1) * 8;
                uint32_t addr = bBase + (uint32_t)(nrow * 80 + col * 2);
                LDMX4(bh[np * 2][0], bh[np * 2][1], bh[np * 2 + 1][0], bh[np * 2 + 1][1], addr);
                if (BPASS == 2)
                    LDMX4(bl[np * 2][0], bl[np * 2][1], bl[np * 2 + 1][0], bl[np * 2 + 1][1], addr + B_SZT);
            }
            // pass-outer ordering
#pragma unroll
            for (int mt = 0; mt < MTT; mt++)
#pragma unroll
                for (int nt = 0; nt < NTT; nt++)
                    MMA16816(acc[mt][nt], ah[mt], bh[nt]);
            if (BPASS == 2) {
#pragma unroll
                for (int mt = 0; mt < MTT; mt++)
#pragma unroll
                    for (int nt = 0; nt < NTT; nt++)
                        MMA16816(acc[mt][nt], ah[mt], bl[nt]);
            }
        }
        __syncthreads();
    }

    // epilogue
    int qrow = lane >> 2, qcol = (lane & 3) * 2;
    int cbase = col0 + wn * (NTT * 8);
#pragma unroll
    for (int mt = 0; mt < MTT; mt++) {
#pragma unroll
        for (int half = 0; half < 2; half++) {
            int r = row0 + wm * (MTT * 16) + mt * 16 + qrow + half * 8;
            if (r >= M) continue;
#pragma unroll
            for (int nt = 0; nt < NTT; nt++) {
                int cix = nt * 8 + qcol;
                int cglob = cbase + cix;
                float2 bv = *(const float2*)&bias[cglob];
                float vx = acc[mt][nt][half * 2 + 0] + bv.x;
                float vy = acc[mt][nt][half * 2 + 1] + bv.y;
                if (MODE == 0) {
                    float2 o; o.x = vx; o.y = vy;
                    *(float2*)(C + (size_t)r * Ntot + cglob) = o;
                } else if (MODE == 1) {
                    __half2 hp; hp.x = __float2half(vx); hp.y = __float2half(vy);
                    int bb = r / 100, qq = r - bb * 100;
                    int hh = cglob >> 6;
                    size_t di = (((size_t)(bb * 16 + hh)) * 128 + qq) * 64 + (cglob & 63);
                    *(__half2*)(ohi + di) = hp;
                } else {
                    __half hx = __float2half(vx);
                    __half hy = __float2half(vy);
                    __half2 hp; hp.x = hx; hp.y = hy;
                    __half2 lp;
                    lp.x = __float2half(vx - __half2float(hx));
                    lp.y = __float2half(vy - __half2float(hy));
                    int bb = r >> 12, kp = r & 4095;
                    int hh = (cglob >> 6) & 15;
                    size_t di = (((size_t)(bb * 16 + hh)) * 4096 + kp) * 64 + (cglob & 63);
                    if (cglob < 1024) {
                        *(__half2*)(ohi + di) = hp;
                        *(__half2*)(klo + di) = lp;
                    } else {
                        *(__half2*)(vhi + di) = hp;
                        *(__half2*)(vlo + di) = lp;
                    }
                }
            }
        }
    }
}

// ---------------- flash attention via mma.sync (fp16 2-pass) ----------------
#define SQH 0
#define SBUF0 18432
#define SBUFSZ 73728
#define SKH 0
#define SKL 18432
#define SVH 36864
#define SVL 55296
#define ATTN_SMEM (SBUF0 + 2 * SBUFSZ)   // 165888

__global__ __launch_bounds__(256) void attn_mma(
    const __half* __restrict__ qhi,
    const __half* __restrict__ khi, const __half* __restrict__ klo,
    const __half* __restrict__ vhi, const __half* __restrict__ vlo,
    const uint32_t* __restrict__ bits,
    float* __restrict__ pm, float* __restrict__ pl, float* __restrict__ pO)
{
    extern __shared__ char sm[];
    uint32_t smb = smem_u32(sm);
    int tid = threadIdx.x;
    int wid = tid >> 5, lane = tid & 31;
    int bh = blockIdx.x;
    int split = blockIdx.y;
    int bB = bh >> 4;
    int wr = wid * 16;
    int g = lane >> 3, ln = lane & 7;

#pragma unroll
    for (int it = 0; it < 4; it++) {
        int i = tid + it * 256;
        int r = i >> 3, sg = i & 7;
        size_t goff = ((size_t)bh * 128 + r) * 64 + sg * 8;
        int nb = (r < NQ_) ? 16 : 0;
        uint32_t so = (uint32_t)(r * 144 + sg * 16);
        cp16(smb + SQH + so, qhi + goff, nb);
    }
    CP_COMMIT();

    auto load_tile = [&](int kt, int buf) {
        int k0 = split * KEYS_PER_SPLIT + kt * 128;
        uint32_t base = smb + SBUF0 + buf * SBUFSZ;
#pragma unroll
        for (int it = 0; it < 4; it++) {
            int i = tid + it * 256;
            int r = i >> 3, sg = i & 7;
            size_t goff = ((size_t)bh * 4096 + k0 + r) * 64 + sg * 8;
            uint32_t so = (uint32_t)(r * 144 + sg * 16);
            cp16(base + SKH + so, khi + goff, 16);
            cp16(base + SKL + so, klo + goff, 16);
            cp16(base + SVH + so, vhi + goff, 16);
            cp16(base + SVL + so, vlo + goff, 16);
        }
    };

    load_tile(0, 0);
    CP_COMMIT();
    CP_WAIT1();
    __syncthreads();

    uint32_t qh[4][4];
#pragma unroll
    for (int ks = 0; ks < 4; ks++) {
        int row = wr + (g & 1) * 8 + ln;
        int col = ks * 16 + (g >> 1) * 8;
        uint32_t a = smb + SQH + (uint32_t)(row * 144 + col * 2);
        LDMX4(qh[ks][0], qh[ks][1], qh[ks][2], qh[ks][3], a);
    }

    int r0 = wr + (lane >> 2);
    int r1 = r0 + 8;
    int t2 = lane & 3;

    float rm0 = -INFINITY, rm1 = -INFINITY, rl0 = 0.f, rl1 = 0.f;
    float O[8][4];
#pragma unroll
    for (int dt = 0; dt < 8; dt++)
#pragma unroll
        for (int j = 0; j < 4; j++) O[dt][j] = 0.f;

    for (int kt = 0; kt < NT_PER_SPLIT; kt++) {
        if (kt + 1 < NT_PER_SPLIT) {
            load_tile(kt + 1, (kt + 1) & 1);
            CP_COMMIT();
            CP_WAIT1();
        } else {
            CP_WAIT0();
        }
        __syncthreads();

        uint32_t bb = smb + SBUF0 + (kt & 1) * SBUFSZ;
        int k0 = split * KEYS_PER_SPLIT + kt * 128;

        float sc[16][4];
#pragma unroll
        for (int nt = 0; nt < 16; nt++)
#pragma unroll
            for (int j = 0; j < 4; j++) sc[nt][j] = 0.f;

#pragma unroll
        for (int npp = 0; npp < 4; npp++) {
            uint32_t kh2[2][4][4], kl2[2][4][4];
#pragma unroll
            for (int j = 0; j < 2; j++) {
                int np = npp * 2 + j;
#pragma unroll
                for (int ks = 0; ks < 4; ks++) {
                    int row = np * 16 + (g >> 1) * 8 + ln;
                    int col = ks * 16 + (g & 1) * 8;
                    uint32_t a = bb + SKH + (uint32_t)(row * 144 + col * 2);
                    LDMX4(kh2[j][ks][0], kh2[j][ks][1], kh2[j][ks][2], kh2[j][ks][3], a);
                    LDMX4(kl2[j][ks][0], kl2[j][ks][1], kl2[j][ks][2], kl2[j][ks][3], a + (SKL - SKH));
                }
            }
#pragma unroll
            for (int ks = 0; ks < 4; ks++) {
#pragma unroll
                for (int j = 0; j < 2; j++) {
                    MMA16816(sc[4 * npp + 2 * j],     qh[ks], &kh2[j][ks][0]);
                    MMA16816(sc[4 * npp + 2 * j + 1], qh[ks], &kh2[j][ks][2]);
                }
#pragma unroll
                for (int j = 0; j < 2; j++) {
                    MMA16816(sc[4 * npp + 2 * j],     qh[ks], &kl2[j][ks][0]);
                    MMA16816(sc[4 * npp + 2 * j + 1], qh[ks], &kl2[j][ks][2]);
                }
            }
        }

        uint32_t mw0[4], mw1[4];
        int woff = k0 >> 5;
        if (r0 < NQ_) *(uint4*)mw0 = *(const uint4*)(bits + (size_t)(bB * 100 + r0) * 128 + woff);
        else { mw0[0] = mw0[1] = mw0[2] = mw0[3] = 0xffffffffu; }
        if (r1 < NQ_) *(uint4*)mw1 = *(const uint4*)(bits + (size_t)(bB * 100 + r1) * 128 + woff);
        else { mw1[0] = mw1[1] = mw1[2] = mw1[3] = 0xffffffffu; }

        float mx0 = -INFINITY, mx1 = -INFINITY;
#pragma unroll
        for (int nt = 0; nt < 16; nt++) {
            int sh = (nt & 3) * 8 + 2 * t2;
            uint32_t wr0 = mw0[nt >> 2] >> sh;
            uint32_t wr1 = mw1[nt >> 2] >> sh;
            float s0 = (wr0 & 1u) ? sc[nt][0] * 0.125f : NEG_;
            float s1 = (wr0 & 2u) ? sc[nt][1] * 0.125f : NEG_;
            float s2 = (wr1 & 1u) ? sc[nt][2] * 0.125f : NEG_;
            float s3 = (wr1 & 2u) ? sc[nt][3] * 0.125f : NEG_;
            sc[nt][0] = s0; sc[nt][1] = s1; sc[nt][2] = s2; sc[nt][3] = s3;
            mx0 = fmaxf(mx0, fmaxf(s0, s1));
            mx1 = fmaxf(mx1, fmaxf(s2, s3));
        }
        mx0 = fmaxf(mx0, __shfl_xor_sync(0xffffffffu, mx0, 1));
        mx0 = fmaxf(mx0, __shfl_xor_sync(0xffffffffu, mx0, 2));
        mx1 = fmaxf(mx1, __shfl_xor_sync(0xffffffffu, mx1, 1));
        mx1 = fmaxf(mx1, __shfl_xor_sync(0xffffffffu, mx1, 2));

        float nm0 = fmaxf(rm0, mx0), nm1 = fmaxf(rm1, mx1);
        float a0 = __expf(rm0 - nm0), a1 = __expf(rm1 - nm1);
        rm0 = nm0; rm1 = nm1;

        float sum0 = 0.f, sum1 = 0.f;
#pragma unroll
        for (int nt = 0; nt < 16; nt++) {
            float p0 = __expf(sc[nt][0] - nm0);
            float p1 = __expf(sc[nt][1] - nm0);
            float p2 = __expf(sc[nt][2] - nm1);
            float p3 = __expf(sc[nt][3] - nm1);
            sc[nt][0] = p0; sc[nt][1] = p1; sc[nt][2] = p2; sc[nt][3] = p3;
            sum0 += p0 + p1; sum1 += p2 + p3;
        }
        sum0 += __shfl_xor_sync(0xffffffffu, sum0, 1);
        sum0 += __shfl_xor_sync(0xffffffffu, sum0, 2);
        sum1 += __shfl_xor_sync(0xffffffffu, sum1, 1);
        sum1 += __shfl_xor_sync(0xffffffffu, sum1, 2);
        rl0 = rl0 * a0 + sum0;
        rl1 = rl1 * a1 + sum1;

#pragma unroll
        for (int dt = 0; dt < 8; dt++) {
            O[dt][0] *= a0; O[dt][1] *= a0;
            O[dt][2] *= a1; O[dt][3] *= a1;
        }

        uint32_t ph[8][4];
#pragma unroll
        for (int ks = 0; ks < 8; ks++) {
            int n0 = 2 * ks, n1 = 2 * ks + 1;
            ph[ks][0] = pack_f16x2(sc[n0][0], sc[n0][1]);
            ph[ks][1] = pack_f16x2(sc[n0][2], sc[n0][3]);
            ph[ks][2] = pack_f16x2(sc[n1][0], sc[n1][1]);
            ph[ks][3] = pack_f16x2(sc[n1][2], sc[n1][3]);
        }

#pragma unroll
        for (int ks = 0; ks < 8; ks++) {
            uint32_t vh4[4][4], vl4[4][4];
#pragma unroll
            for (int dt2 = 0; dt2 < 4; dt2++) {
                int row = ks * 16 + (g & 1) * 8 + ln;
                int col = dt2 * 16 + (g >> 1) * 8;
                uint32_t a = bb + SVH + (uint32_t)(row * 144 + col * 2);
                LDMX4T(vh4[dt2][0], vh4[dt2][1], vh4[dt2][2], vh4[dt2][3], a);
                LDMX4T(vl4[dt2][0], vl4[dt2][1], vl4[dt2][2], vl4[dt2][3], a + (SVL - SVH));
            }
#pragma unroll
            for (int dt2 = 0; dt2 < 4; dt2++) {
                MMA16816(O[2 * dt2],     ph[ks], &vh4[dt2][0]);
                MMA16816(O[2 * dt2 + 1], ph[ks], &vh4[dt2][2]);
            }
#pragma unroll
            for (int dt2 = 0; dt2 < 4; dt2++) {
                MMA16816(O[2 * dt2],     ph[ks], &vl4[dt2][0]);
                MMA16816(O[2 * dt2 + 1], ph[ks], &vl4[dt2][2]);
            }
        }
        __syncthreads();
    }

    size_t pbase = ((size_t)(split * 64 + bh)) * 128;
    if (t2 == 0) {
        pm[pbase + r0] = rm0; pm[pbase + r1] = rm1;
        pl[pbase + r0] = rl0; pl[pbase + r1] = rl1;
    }
#pragma unroll
    for (int dt = 0; dt < 8; dt++) {
        int d = dt * 8 + 2 * t2;
        float2 o0; o0.x = O[dt][0]; o0.y = O[dt][1];
        float2 o1; o1.x = O[dt][2]; o1.y = O[dt][3];
        *(float2*)(pO + (pbase + r0) * 64 + d) = o0;
        *(float2*)(pO + (pbase + r1) * 64 + d) = o1;
    }
}

// ---------------- merge split-K partials -> ctx fp16 hi ----------------
__global__ __launch_bounds__(256) void merge_kernel(
    const float* __restrict__ pm, const float* __restrict__ pl,
    const float* __restrict__ pO, __half* __restrict__ cxhi)
{
    int idx = blockIdx.x * 256 + threadIdx.x;
    if (idx >= 400 * 1024) return;
    int row = idx >> 10;
    int col = idx & 1023;
    int b = row / 100, q = row - b * 100;
    int h = col >> 6, d = col & 63;
    size_t p0 = ((size_t)(0 * 64 + b * 16 + h)) * 128 + q;
    size_t p1 = ((size_t)(1 * 64 + b * 16 + h)) * 128 + q;
    float m0 = pm[p0], m1 = pm[p1];
    float M = fmaxf(m0, m1);
    float w0 = __expf(m0 - M), w1 = __expf(m1 - M);
    float L = pl[p0] * w0 + pl[p1] * w1;
    float val = (pO[p0 * 64 + d] * w0 + pO[p1 * 64 + d] * w1) / L;
    cxhi[idx] = __float2half(val);
}

// ---------------- launch ----------------
extern "C" void kernel_launch(void* const* d_in, const int* in_sizes, int n_in,
                              void* d_out, int out_size)
{
    const float* q    = (const float*)d_in[0];
    const float* kv   = (const float*)d_in[1];
    const int*   mask = (const int*)  d_in[2];
    const float* ipw  = (const float*)d_in[3];
    const float* ipb  = (const float*)d_in[4];
    const float* ow   = (const float*)d_in[5];
    const float* ob   = (const float*)d_in[6];
    const float* gq   = (const float*)d_in[7];
    const float* bq   = (const float*)d_in[8];
    const float* gkv  = (const float*)d_in[9];
    const float* bkv  = (const float*)d_in[10];
    float* out = (float*)d_out;

    __half *p_qn_hi, *p_kvn_hi, *p_w_hi, *p_w_lo, *p_ow_hi, *p_ow_lo, *p_cx_hi;
    __half *p_qhi, *p_khi, *p_klo, *p_vhi, *p_vlo;
    float *p_pm, *p_pl, *p_pO;
    uint32_t* p_bits;
    cudaGetSymbolAddress((void**)&p_qn_hi,  g_qn_hi);
    cudaGetSymbolAddress((void**)&p_kvn_hi, g_kvn_hi);
    cudaGetSymbolAddress((void**)&p_w_hi,   g_w_hi);
    cudaGetSymbolAddress((void**)&p_w_lo,   g_w_lo);
    cudaGetSymbolAddress((void**)&p_ow_hi,  g_ow_hi);
    cudaGetSymbolAddress((void**)&p_ow_lo,  g_ow_lo);
    cudaGetSymbolAddress((void**)&p_cx_hi,  g_cx_hi);
    cudaGetSymbolAddress((void**)&p_qhi, g_qhi);
    cudaGetSymbolAddress((void**)&p_khi, g_khi);
    cudaGetSymbolAddress((void**)&p_klo, g_klo);
    cudaGetSymbolAddress((void**)&p_vhi, g_vhi);
    cudaGetSymbolAddress((void**)&p_vlo, g_vlo);
    cudaGetSymbolAddress((void**)&p_bits, g_bits);
    cudaGetSymbolAddress((void**)&p_pm, g_pm);
    cudaGetSymbolAddress((void**)&p_pl, g_pl);
    cudaGetSymbolAddress((void**)&p_pO, g_pO);

    // small gemms: BM=128/BN=64, 256 thr, 2-pass
    const int SMEM_S = 2 * (128 * 80 + 2 * 64 * 80);    // 40960
    // kv gemm: BM=256/BN=128, 512 thr, 1-pass
    const int SMEM_K = 2 * (256 * 80 + 1 * 128 * 80);   // 61440
    cudaFuncSetAttribute((const void*)gemm_mma<0, 2, 4, 4, 2, 2>,
                         cudaFuncAttributeMaxDynamicSharedMemorySize, SMEM_S);
    cudaFuncSetAttribute((const void*)gemm_mma<1, 2, 4, 4, 2, 2>,
                         cudaFuncAttributeMaxDynamicSharedMemorySize, SMEM_S);
    cudaFuncSetAttribute((const void*)gemm_mma<2, 4, 4, 4, 4, 1>,
                         cudaFuncAttributeMaxDynamicSharedMemorySize, SMEM_K);
    cudaFuncSetAttribute(attn_mma, cudaFuncAttributeMaxDynamicSharedMemorySize, ATTN_SMEM);

    // layernorm (fp16 hi only)
    ln_half_kernel<<<B_ * NQ_, 256>>>(q, gq, bq, p_qn_hi);
    ln_half_kernel<<<B_ * HW_, 256>>>(kv, gkv, bkv, p_kvn_hi);
    maskpack_kernel<<<B_ * NQ_, 128>>>(mask, p_bits);

    // weight splits (fp16 hi/lo; lo used by small gemms only)
    split_kernel<<<(3072 * 1024 / 4 + 255) / 256, 256>>>(ipw, p_w_hi, p_w_lo, 3072 * 1024 / 4);
    split_kernel<<<(1024 * 1024 / 4 + 255) / 256, 256>>>(ow, p_ow_hi, p_ow_lo, 1024 * 1024 / 4);

    // q projection -> head-major hi (2-pass)
    gemm_mma<1, 2, 4, 4, 2, 2><<<dim3(16, 4), 256, SMEM_S>>>(
        p_qn_hi, p_w_hi, p_w_lo, ipb, nullptr,
        p_qhi, nullptr, nullptr, nullptr, B_ * NQ_, 1024);

    // kv projection -> head-major hi/lo K and V (single-pass, BM=256/BN=128, 512 thr)
    gemm_mma<2, 4, 4, 4, 4, 1><<<dim3(16, 64), 512, SMEM_K>>>(
        p_kvn_hi,
        p_w_hi + (size_t)1024 * 1024, nullptr,
        ipb + 1024, nullptr,
        p_khi, p_klo, p_vhi, p_vlo, B_ * HW_, 2048);

    // attention (split-K, 2-pass)
    attn_mma<<<dim3(64, ASPLIT), 256, ATTN_SMEM>>>(
        p_qhi, p_khi, p_klo, p_vhi, p_vlo, p_bits, p_pm, p_pl, p_pO);

    // merge -> ctx fp16 hi
    merge_kernel<<<(400 * 1024 + 255) / 256, 256>>>(p_pm, p_pl, p_pO, p_cx_hi);

    // output projection (2-pass)
    gemm_mma<0, 2, 4, 4, 2, 2><<<dim3(16, 4), 256, SMEM_S>>>(
        p_cx_hi, p_ow_hi, p_ow_lo, ob, out,
        nullptr, nullptr, nullptr, nullptr, B_ * NQ_, 1024);
}

// round 17
// speedup vs baseline: 6.6670x; 1.1063x over previous
#include <cuda_runtime.h>
#include <cuda_fp16.h>
#include <math.h>
#include <stdint.h>

#define B_  4
#define NQ_ 100
#define HW_ 4096
#define D_  1024
#define H_  16
#define HD_ 64
#define NEG_ (-1e9f)
#define ASPLIT 2
#define KEYS_PER_SPLIT (HW_ / ASPLIT)   // 2048
#define NT_PER_SPLIT   (KEYS_PER_SPLIT / 128)  // 16

// ---------------- scratch (device globals; no runtime allocation) ----------------
__device__ __half g_qn_hi [400  * 1024];
__device__ __half g_kvn_hi[16384 * 1024];
__device__ __half g_w_hi  [3072 * 1024];
__device__ __half g_w_lo  [3072 * 1024];
__device__ __half g_ow_hi [1024 * 1024];
__device__ __half g_ow_lo [1024 * 1024];
// head-major projections: [b*16+h][rows][64]
__device__ __half g_qhi[64 * 128 * 64];
__device__ __half g_khi[(size_t)64 * 4096 * 64];
__device__ __half g_vhi[(size_t)64 * 4096 * 64];
__device__ __half g_cx_hi[400 * 1024];
__device__ uint32_t g_bits[400 * 128];
__device__ float g_pm[ASPLIT * 64 * 128];
__device__ float g_pl[ASPLIT * 64 * 128];
__device__ float g_pO[(size_t)ASPLIT * 64 * 128 * 64];

// ---------------- helpers ----------------
__device__ __forceinline__ uint32_t smem_u32(const void* p) {
    uint32_t a;
    asm("{ .reg .u64 t; cvta.to.shared.u64 t, %1; cvt.u32.u64 %0, t; }" : "=r"(a) : "l"(p));
    return a;
}
__device__ __forceinline__ void cp16(uint32_t dst, const void* src, int nbytes) {
    asm volatile("cp.async.cg.shared.global [%0], [%1], 16, %2;"
                 :: "r"(dst), "l"(src), "r"(nbytes));
}
#define CP_COMMIT() asm volatile("cp.async.commit_group;" ::: "memory")
#define CP_WAIT1()  asm volatile("cp.async.wait_group 1;" ::: "memory")
#define CP_WAIT0()  asm volatile("cp.async.wait_group 0;" ::: "memory")

#define LDMX4(r0, r1, r2, r3, addr) \
    asm volatile("ldmatrix.sync.aligned.m8n8.x4.shared.b16 {%0,%1,%2,%3}, [%4];" \
                 : "=r"(r0), "=r"(r1), "=r"(r2), "=r"(r3) : "r"(addr))
#define LDMX4T(r0, r1, r2, r3, addr) \
    asm volatile("ldmatrix.sync.aligned.m8n8.x4.trans.shared.b16 {%0,%1,%2,%3}, [%4];" \
                 : "=r"(r0), "=r"(r1), "=r"(r2), "=r"(r3) : "r"(addr))

#define MMA16816(c, a, b) \
    asm volatile("mma.sync.aligned.m16n8k16.row.col.f32.f16.f16.f32 " \
                 "{%0,%1,%2,%3}, {%4,%5,%6,%7}, {%8,%9}, {%0,%1,%2,%3};" \
                 : "+f"((c)[0]), "+f"((c)[1]), "+f"((c)[2]), "+f"((c)[3]) \
                 : "r"((a)[0]), "r"((a)[1]), "r"((a)[2]), "r"((a)[3]), \
                   "r"((b)[0]), "r"((b)[1]))

__device__ __forceinline__ uint32_t pack_f16x2(float lo_el, float hi_el) {
    uint32_t r;
    asm("cvt.rn.f16x2.f32 %0, %1, %2;" : "=r"(r) : "f"(hi_el), "f"(lo_el));
    return r;
}

// ---------------- layernorm -> fp16 hi ----------------
__global__ __launch_bounds__(256) void ln_half_kernel(
    const float* __restrict__ x, const float* __restrict__ g,
    const float* __restrict__ b, __half* __restrict__ hi)
{
    __shared__ float red[32];
    int row = blockIdx.x;
    int tid = threadIdx.x;
    const float* xr = x + (size_t)row * D_;

    float v[4];
#pragma unroll
    for (int i = 0; i < 4; i++) v[i] = xr[tid + 256 * i];

    float s = v[0] + v[1] + v[2] + v[3];
#pragma unroll
    for (int o = 16; o > 0; o >>= 1) s += __shfl_xor_sync(0xffffffffu, s, o);
    if ((tid & 31) == 0) red[tid >> 5] = s;
    __syncthreads();
    float t = (tid < 8) ? red[tid] : 0.f;
    if (tid < 32) {
#pragma unroll
        for (int o = 4; o > 0; o >>= 1) t += __shfl_xor_sync(0xffffffffu, t, o);
        if (tid == 0) red[0] = t;
    }
    __syncthreads();
    float mu = red[0] * (1.0f / D_);
    __syncthreads();

    float sq = 0.f;
#pragma unroll
    for (int i = 0; i < 4; i++) { float d = v[i] - mu; sq += d * d; }
#pragma unroll
    for (int o = 16; o > 0; o >>= 1) sq += __shfl_xor_sync(0xffffffffu, sq, o);
    if ((tid & 31) == 0) red[tid >> 5] = sq;
    __syncthreads();
    float t2 = (tid < 8) ? red[tid] : 0.f;
    if (tid < 32) {
#pragma unroll
        for (int o = 4; o > 0; o >>= 1) t2 += __shfl_xor_sync(0xffffffffu, t2, o);
        if (tid == 0) red[0] = t2;
    }
    __syncthreads();
    float var = red[0] * (1.0f / D_);
    float inv = rsqrtf(var + 1e-5f);

#pragma unroll
    for (int i = 0; i < 4; i++) {
        int c = tid + 256 * i;
        float y = (v[i] - mu) * inv * g[c] + b[c];
        hi[(size_t)row * D_ + c] = __float2half(y);
    }
}

// ---------------- fp32 -> fp16 hi/lo split (weights) ----------------
__global__ __launch_bounds__(256) void split_kernel(
    const float* __restrict__ x,
    __half* __restrict__ hi, __half* __restrict__ lo, int n4)
{
    int i = blockIdx.x * 256 + threadIdx.x;
    if (i >= n4) return;
    float4 v = ((const float4*)x)[i];
    __half h0 = __float2half(v.x);
    __half h1 = __float2half(v.y);
    __half h2 = __float2half(v.z);
    __half h3 = __float2half(v.w);
    __half2 hp0; hp0.x = h0; hp0.y = h1;
    __half2 hp1; hp1.x = h2; hp1.y = h3;
    __half2 lp0;
    lp0.x = __float2half(v.x - __half2float(h0));
    lp0.y = __float2half(v.y - __half2float(h1));
    __half2 lp1;
    lp1.x = __float2half(v.z - __half2float(h2));
    lp1.y = __float2half(v.w - __half2float(h3));
    ((__half2*)hi)[i * 2]     = hp0;
    ((__half2*)hi)[i * 2 + 1] = hp1;
    ((__half2*)lo)[i * 2]     = lp0;
    ((__half2*)lo)[i * 2 + 1] = lp1;
}

// ---------------- mask -> bitmask ----------------
__global__ __launch_bounds__(128) void maskpack_kernel(
    const int* __restrict__ mask, uint32_t* __restrict__ bits)
{
    int row = blockIdx.x;
    int tid = threadIdx.x;
    int wid = tid >> 5, lane = tid & 31;
    __shared__ uint32_t ws[128];
    const int* mr = mask + (size_t)row * HW_;
    int any = 0;
#pragma unroll
    for (int j = 0; j < 32; j++) {
        int v = mr[j * 128 + tid] != 0;
        any |= v;
        uint32_t bal = __ballot_sync(0xffffffffu, v);
        if (lane == 0) ws[j * 4 + wid] = bal;
    }
    int has = __syncthreads_or(any);
    bits[(size_t)row * 128 + tid] = has ? ws[tid] : 0xffffffffu;
}

// ---------------- mma.sync GEMM, generalized tiles, BPASS in {1,2} ----------------
// MODE 0: C fp32 + bias.  MODE 1: q head-split hi.  MODE 2: kv head-split hi (no lo).
#define NCHUNK 32

template<int MODE, int MTT, int NTT, int WMW, int WNW, int BPASS>
__global__ __launch_bounds__(WMW * WNW * 32) void gemm_mma(
    const __half* __restrict__ Ahi,
    const __half* __restrict__ Bhi, const __half* __restrict__ Blo,
    const float* __restrict__ bias, float* __restrict__ C,
    __half* __restrict__ ohi, __half* __restrict__ vhi,
    int M, int Ntot)
{
    constexpr int THREADS = WMW * WNW * 32;
    constexpr int BM = WMW * MTT * 16;
    constexpr int BN = WNW * NTT * 8;
    constexpr int A_SZT = BM * 80;
    constexpr int B_SZT = BN * 80;
    constexpr int BUF = A_SZT + BPASS * B_SZT;

    extern __shared__ char sm[];
    uint32_t smb = smem_u32(sm);
    int tid = threadIdx.x;
    int wid = tid >> 5, lane = tid & 31;
    int wm = wid % WMW, wn = wid / WMW;
    int row0 = blockIdx.y * BM;
    int col0 = blockIdx.x * BN;

    float acc[MTT][NTT][4];
#pragma unroll
    for (int a = 0; a < MTT; a++)
#pragma unroll
        for (int b = 0; b < NTT; b++)
#pragma unroll
            for (int c = 0; c < 4; c++) acc[a][b][c] = 0.f;

    int r_a = tid >> 2, seg = (tid & 3);

    auto load_chunk = [&](int c, int buf) {
        uint32_t base = smb + buf * BUF;
#pragma unroll
        for (int it = 0; it < BM / (THREADS / 4); it++) {
            int r = r_a + it * (THREADS / 4);
            int gr = row0 + r;
            int nb = (gr < M) ? 16 : 0;
            cp16(base + (uint32_t)(r * 80 + seg * 16),
                 Ahi + (size_t)gr * 1024 + c * 32 + seg * 8, nb);
        }
#pragma unroll
        for (int it = 0; it < BN / (THREADS / 4); it++) {
            int r = r_a + it * (THREADS / 4);
            int gr = col0 + r;
            uint32_t dst = base + A_SZT + (uint32_t)(r * 80 + seg * 16);
            cp16(dst, Bhi + (size_t)gr * 1024 + c * 32 + seg * 8, 16);
            if (BPASS == 2)
                cp16(dst + B_SZT, Blo + (size_t)gr * 1024 + c * 32 + seg * 8, 16);
        }
    };

    load_chunk(0, 0);
    CP_COMMIT();

    for (int c = 0; c < NCHUNK; c++) {
        if (c + 1 < NCHUNK) {
            load_chunk(c + 1, (c + 1) & 1);
            CP_COMMIT();
            CP_WAIT1();
        } else {
            CP_WAIT0();
        }
        __syncthreads();

        uint32_t aBase = smb + (c & 1) * BUF;
        uint32_t bBase = aBase + A_SZT;
        int g = lane >> 3, ln = lane & 7;

#pragma unroll
        for (int s = 0; s < 2; s++) {
            int kc = s * 16;
            uint32_t ah[MTT][4], bh[NTT][2], bl[NTT][2];
#pragma unroll
            for (int mt = 0; mt < MTT; mt++) {
                int row = wm * (MTT * 16) + mt * 16 + (g & 1) * 8 + ln;
                int col = kc + (g >> 1) * 8;
                uint32_t addr = aBase + (uint32_t)(row * 80 + col * 2);
                LDMX4(ah[mt][0], ah[mt][1], ah[mt][2], ah[mt][3], addr);
            }
#pragma unroll
            for (int np = 0; np < NTT / 2; np++) {
                int nrow = wn * (NTT * 8) + np * 16 + (g >> 1) * 8 + ln;
                int col = kc + (g & 1) * 8;
                uint32_t addr = bBase + (uint32_t)(nrow * 80 + col * 2);
                LDMX4(bh[np * 2][0], bh[np * 2][1], bh[np * 2 + 1][0], bh[np * 2 + 1][1], addr);
                if (BPASS == 2)
                    LDMX4(bl[np * 2][0], bl[np * 2][1], bl[np * 2 + 1][0], bl[np * 2 + 1][1], addr + B_SZT);
            }
            // pass-outer ordering
#pragma unroll
            for (int mt = 0; mt < MTT; mt++)
#pragma unroll
                for (int nt = 0; nt < NTT; nt++)
                    MMA16816(acc[mt][nt], ah[mt], bh[nt]);
            if (BPASS == 2) {
#pragma unroll
                for (int mt = 0; mt < MTT; mt++)
#pragma unroll
                    for (int nt = 0; nt < NTT; nt++)
                        MMA16816(acc[mt][nt], ah[mt], bl[nt]);
            }
        }
        __syncthreads();
    }

    // epilogue
    int qrow = lane >> 2, qcol = (lane & 3) * 2;
    int cbase = col0 + wn * (NTT * 8);
#pragma unroll
    for (int mt = 0; mt < MTT; mt++) {
#pragma unroll
        for (int half = 0; half < 2; half++) {
            int r = row0 + wm * (MTT * 16) + mt * 16 + qrow + half * 8;
            if (r >= M) continue;
#pragma unroll
            for (int nt = 0; nt < NTT; nt++) {
                int cix = nt * 8 + qcol;
                int cglob = cbase + cix;
                float2 bv = *(const float2*)&bias[cglob];
                float vx = acc[mt][nt][half * 2 + 0] + bv.x;
                float vy = acc[mt][nt][half * 2 + 1] + bv.y;
                if (MODE == 0) {
                    float2 o; o.x = vx; o.y = vy;
                    *(float2*)(C + (size_t)r * Ntot + cglob) = o;
                } else if (MODE == 1) {
                    __half2 hp; hp.x = __float2half(vx); hp.y = __float2half(vy);
                    int bb = r / 100, qq = r - bb * 100;
                    int hh = cglob >> 6;
                    size_t di = (((size_t)(bb * 16 + hh)) * 128 + qq) * 64 + (cglob & 63);
                    *(__half2*)(ohi + di) = hp;
                } else {
                    __half2 hp; hp.x = __float2half(vx); hp.y = __float2half(vy);
                    int bb = r >> 12, kp = r & 4095;
                    int hh = (cglob >> 6) & 15;
                    size_t di = (((size_t)(bb * 16 + hh)) * 4096 + kp) * 64 + (cglob & 63);
                    if (cglob < 1024) *(__half2*)(ohi + di) = hp;
                    else              *(__half2*)(vhi + di) = hp;
                }
            }
        }
    }
}

// ---------------- flash attention via mma.sync (single-pass fp16) ----------------
// smem: QH (18432) | 2 x (KH 18432 | VH 18432)
#define SQH 0
#define SBUF0 18432
#define SBUFSZ 36864
#define SKH 0
#define SVH 18432
#define ATTN_SMEM (SBUF0 + 2 * SBUFSZ)   // 92160

__global__ __launch_bounds__(256) void attn_mma(
    const __half* __restrict__ qhi,
    const __half* __restrict__ khi, const __half* __restrict__ vhi,
    const uint32_t* __restrict__ bits,
    float* __restrict__ pm, float* __restrict__ pl, float* __restrict__ pO)
{
    extern __shared__ char sm[];
    uint32_t smb = smem_u32(sm);
    int tid = threadIdx.x;
    int wid = tid >> 5, lane = tid & 31;
    int bh = blockIdx.x;
    int split = blockIdx.y;
    int bB = bh >> 4;
    int wr = wid * 16;
    int g = lane >> 3, ln = lane & 7;

#pragma unroll
    for (int it = 0; it < 4; it++) {
        int i = tid + it * 256;
        int r = i >> 3, sg = i & 7;
        size_t goff = ((size_t)bh * 128 + r) * 64 + sg * 8;
        int nb = (r < NQ_) ? 16 : 0;
        uint32_t so = (uint32_t)(r * 144 + sg * 16);
        cp16(smb + SQH + so, qhi + goff, nb);
    }
    CP_COMMIT();

    auto load_tile = [&](int kt, int buf) {
        int k0 = split * KEYS_PER_SPLIT + kt * 128;
        uint32_t base = smb + SBUF0 + buf * SBUFSZ;
#pragma unroll
        for (int it = 0; it < 4; it++) {
            int i = tid + it * 256;
            int r = i >> 3, sg = i & 7;
            size_t goff = ((size_t)bh * 4096 + k0 + r) * 64 + sg * 8;
            uint32_t so = (uint32_t)(r * 144 + sg * 16);
            cp16(base + SKH + so, khi + goff, 16);
            cp16(base + SVH + so, vhi + goff, 16);
        }
    };

    load_tile(0, 0);
    CP_COMMIT();
    CP_WAIT1();
    __syncthreads();

    uint32_t qh[4][4];
#pragma unroll
    for (int ks = 0; ks < 4; ks++) {
        int row = wr + (g & 1) * 8 + ln;
        int col = ks * 16 + (g >> 1) * 8;
        uint32_t a = smb + SQH + (uint32_t)(row * 144 + col * 2);
        LDMX4(qh[ks][0], qh[ks][1], qh[ks][2], qh[ks][3], a);
    }

    int r0 = wr + (lane >> 2);
    int r1 = r0 + 8;
    int t2 = lane & 3;

    float rm0 = -INFINITY, rm1 = -INFINITY, rl0 = 0.f, rl1 = 0.f;
    float O[8][4];
#pragma unroll
    for (int dt = 0; dt < 8; dt++)
#pragma unroll
        for (int j = 0; j < 4; j++) O[dt][j] = 0.f;

    for (int kt = 0; kt < NT_PER_SPLIT; kt++) {
        if (kt + 1 < NT_PER_SPLIT) {
            load_tile(kt + 1, (kt + 1) & 1);
            CP_COMMIT();
            CP_WAIT1();
        } else {
            CP_WAIT0();
        }
        __syncthreads();

        uint32_t bb = smb + SBUF0 + (kt & 1) * SBUFSZ;
        int k0 = split * KEYS_PER_SPLIT + kt * 128;

        // ---- scores S = Q K^T (single pass) ----
        float sc[16][4];
#pragma unroll
        for (int nt = 0; nt < 16; nt++)
#pragma unroll
            for (int j = 0; j < 4; j++) sc[nt][j] = 0.f;

#pragma unroll
        for (int npp = 0; npp < 4; npp++) {
            uint32_t kh2[2][4][4];
#pragma unroll
            for (int j = 0; j < 2; j++) {
                int np = npp * 2 + j;
#pragma unroll
                for (int ks = 0; ks < 4; ks++) {
                    int row = np * 16 + (g >> 1) * 8 + ln;
                    int col = ks * 16 + (g & 1) * 8;
                    uint32_t a = bb + SKH + (uint32_t)(row * 144 + col * 2);
                    LDMX4(kh2[j][ks][0], kh2[j][ks][1], kh2[j][ks][2], kh2[j][ks][3], a);
                }
            }
#pragma unroll
            for (int ks = 0; ks < 4; ks++) {
#pragma unroll
                for (int j = 0; j < 2; j++) {
                    MMA16816(sc[4 * npp + 2 * j],     qh[ks], &kh2[j][ks][0]);
                    MMA16816(sc[4 * npp + 2 * j + 1], qh[ks], &kh2[j][ks][2]);
                }
            }
        }

        // ---- mask + scale ----
        uint32_t mw0[4], mw1[4];
        int woff = k0 >> 5;
        if (r0 < NQ_) *(uint4*)mw0 = *(const uint4*)(bits + (size_t)(bB * 100 + r0) * 128 + woff);
        else { mw0[0] = mw0[1] = mw0[2] = mw0[3] = 0xffffffffu; }
        if (r1 < NQ_) *(uint4*)mw1 = *(const uint4*)(bits + (size_t)(bB * 100 + r1) * 128 + woff);
        else { mw1[0] = mw1[1] = mw1[2] = mw1[3] = 0xffffffffu; }

        float mx0 = -INFINITY, mx1 = -INFINITY;
#pragma unroll
        for (int nt = 0; nt < 16; nt++) {
            int sh = (nt & 3) * 8 + 2 * t2;
            uint32_t wr0 = mw0[nt >> 2] >> sh;
            uint32_t wr1 = mw1[nt >> 2] >> sh;
            float s0 = (wr0 & 1u) ? sc[nt][0] * 0.125f : NEG_;
            float s1 = (wr0 & 2u) ? sc[nt][1] * 0.125f : NEG_;
            float s2 = (wr1 & 1u) ? sc[nt][2] * 0.125f : NEG_;
            float s3 = (wr1 & 2u) ? sc[nt][3] * 0.125f : NEG_;
            sc[nt][0] = s0; sc[nt][1] = s1; sc[nt][2] = s2; sc[nt][3] = s3;
            mx0 = fmaxf(mx0, fmaxf(s0, s1));
            mx1 = fmaxf(mx1, fmaxf(s2, s3));
        }
        mx0 = fmaxf(mx0, __shfl_xor_sync(0xffffffffu, mx0, 1));
        mx0 = fmaxf(mx0, __shfl_xor_sync(0xffffffffu, mx0, 2));
        mx1 = fmaxf(mx1, __shfl_xor_sync(0xffffffffu, mx1, 1));
        mx1 = fmaxf(mx1, __shfl_xor_sync(0xffffffffu, mx1, 2));

        float nm0 = fmaxf(rm0, mx0), nm1 = fmaxf(rm1, mx1);
        float a0 = __expf(rm0 - nm0), a1 = __expf(rm1 - nm1);
        rm0 = nm0; rm1 = nm1;

        float sum0 = 0.f, sum1 = 0.f;
#pragma unroll
        for (int nt = 0; nt < 16; nt++) {
            float p0 = __expf(sc[nt][0] - nm0);
            float p1 = __expf(sc[nt][1] - nm0);
            float p2 = __expf(sc[nt][2] - nm1);
            float p3 = __expf(sc[nt][3] - nm1);
            sc[nt][0] = p0; sc[nt][1] = p1; sc[nt][2] = p2; sc[nt][3] = p3;
            sum0 += p0 + p1; sum1 += p2 + p3;
        }
        sum0 += __shfl_xor_sync(0xffffffffu, sum0, 1);
        sum0 += __shfl_xor_sync(0xffffffffu, sum0, 2);
        sum1 += __shfl_xor_sync(0xffffffffu, sum1, 1);
        sum1 += __shfl_xor_sync(0xffffffffu, sum1, 2);
        rl0 = rl0 * a0 + sum0;
        rl1 = rl1 * a1 + sum1;

#pragma unroll
        for (int dt = 0; dt < 8; dt++) {
            O[dt][0] *= a0; O[dt][1] *= a0;
            O[dt][2] *= a1; O[dt][3] *= a1;
        }

        uint32_t ph[8][4];
#pragma unroll
        for (int ks = 0; ks < 8; ks++) {
            int n0 = 2 * ks, n1 = 2 * ks + 1;
            ph[ks][0] = pack_f16x2(sc[n0][0], sc[n0][1]);
            ph[ks][1] = pack_f16x2(sc[n0][2], sc[n0][3]);
            ph[ks][2] = pack_f16x2(sc[n1][0], sc[n1][1]);
            ph[ks][3] = pack_f16x2(sc[n1][2], sc[n1][3]);
        }

        // ---- O += P V (single pass) ----
#pragma unroll
        for (int ks = 0; ks < 8; ks++) {
            uint32_t vh4[4][4];
#pragma unroll
            for (int dt2 = 0; dt2 < 4; dt2++) {
                int row = ks * 16 + (g & 1) * 8 + ln;
                int col = dt2 * 16 + (g >> 1) * 8;
                uint32_t a = bb + SVH + (uint32_t)(row * 144 + col * 2);
                LDMX4T(vh4[dt2][0], vh4[dt2][1], vh4[dt2][2], vh4[dt2][3], a);
            }
#pragma unroll
            for (int dt2 = 0; dt2 < 4; dt2++) {
                MMA16816(O[2 * dt2],     ph[ks], &vh4[dt2][0]);
                MMA16816(O[2 * dt2 + 1], ph[ks], &vh4[dt2][2]);
            }
        }
        __syncthreads();
    }

    size_t pbase = ((size_t)(split * 64 + bh)) * 128;
    if (t2 == 0) {
        pm[pbase + r0] = rm0; pm[pbase + r1] = rm1;
        pl[pbase + r0] = rl0; pl[pbase + r1] = rl1;
    }
#pragma unroll
    for (int dt = 0; dt < 8; dt++) {
        int d = dt * 8 + 2 * t2;
        float2 o0; o0.x = O[dt][0]; o0.y = O[dt][1];
        float2 o1; o1.x = O[dt][2]; o1.y = O[dt][3];
        *(float2*)(pO + (pbase + r0) * 64 + d) = o0;
        *(float2*)(pO + (pbase + r1) * 64 + d) = o1;
    }
}

// ---------------- merge split-K partials -> ctx fp16 hi ----------------
__global__ __launch_bounds__(256) void merge_kernel(
    const float* __restrict__ pm, const float* __restrict__ pl,
    const float* __restrict__ pO, __half* __restrict__ cxhi)
{
    int idx = blockIdx.x * 256 + threadIdx.x;
    if (idx >= 400 * 1024) return;
    int row = idx >> 10;
    int col = idx & 1023;
    int b = row / 100, q = row - b * 100;
    int h = col >> 6, d = col & 63;
    size_t p0 = ((size_t)(0 * 64 + b * 16 + h)) * 128 + q;
    size_t p1 = ((size_t)(1 * 64 + b * 16 + h)) * 128 + q;
    float m0 = pm[p0], m1 = pm[p1];
    float M = fmaxf(m0, m1);
    float w0 = __expf(m0 - M), w1 = __expf(m1 - M);
    float L = pl[p0] * w0 + pl[p1] * w1;
    float val = (pO[p0 * 64 + d] * w0 + pO[p1 * 64 + d] * w1) / L;
    cxhi[idx] = __float2half(val);
}

// ---------------- launch ----------------
extern "C" void kernel_launch(void* const* d_in, const int* in_sizes, int n_in,
                              void* d_out, int out_size)
{
    const float* q    = (const float*)d_in[0];
    const float* kv   = (const float*)d_in[1];
    const int*   mask = (const int*)  d_in[2];
    const float* ipw  = (const float*)d_in[3];
    const float* ipb  = (const float*)d_in[4];
    const float* ow   = (const float*)d_in[5];
    const float* ob   = (const float*)d_in[6];
    const float* gq   = (const float*)d_in[7];
    const float* bq   = (const float*)d_in[8];
    const float* gkv  = (const float*)d_in[9];
    const float* bkv  = (const float*)d_in[10];
    float* out = (float*)d_out;

    __half *p_qn_hi, *p_kvn_hi, *p_w_hi, *p_w_lo, *p_ow_hi, *p_ow_lo, *p_cx_hi;
    __half *p_qhi, *p_khi, *p_vhi;
    float *p_pm, *p_pl, *p_pO;
    uint32_t* p_bits;
    cudaGetSymbolAddress((void**)&p_qn_hi,  g_qn_hi);
    cudaGetSymbolAddress((void**)&p_kvn_hi, g_kvn_hi);
    cudaGetSymbolAddress((void**)&p_w_hi,   g_w_hi);
    cudaGetSymbolAddress((void**)&p_w_lo,   g_w_lo);
    cudaGetSymbolAddress((void**)&p_ow_hi,  g_ow_hi);
    cudaGetSymbolAddress((void**)&p_ow_lo,  g_ow_lo);
    cudaGetSymbolAddress((void**)&p_cx_hi,  g_cx_hi);
    cudaGetSymbolAddress((void**)&p_qhi, g_qhi);
    cudaGetSymbolAddress((void**)&p_khi, g_khi);
    cudaGetSymbolAddress((void**)&p_vhi, g_vhi);
    cudaGetSymbolAddress((void**)&p_bits, g_bits);
    cudaGetSymbolAddress((void**)&p_pm, g_pm);
    cudaGetSymbolAddress((void**)&p_pl, g_pl);
    cudaGetSymbolAddress((void**)&p_pO, g_pO);

    // small gemms: BM=128/BN=64, 256 thr, 2-pass
    const int SMEM_S = 2 * (128 * 80 + 2 * 64 * 80);    // 40960
    // kv gemm: BM=256/BN=128, 512 thr, 1-pass
    const int SMEM_K = 2 * (256 * 80 + 1 * 128 * 80);   // 61440
    cudaFuncSetAttribute((const void*)gemm_mma<0, 2, 4, 4, 2, 2>,
                         cudaFuncAttributeMaxDynamicSharedMemorySize, SMEM_S);
    cudaFuncSetAttribute((const void*)gemm_mma<1, 2, 4, 4, 2, 2>,
                         cudaFuncAttributeMaxDynamicSharedMemorySize, SMEM_S);
    cudaFuncSetAttribute((const void*)gemm_mma<2, 4, 4, 4, 4, 1>,
                         cudaFuncAttributeMaxDynamicSharedMemorySize, SMEM_K);
    cudaFuncSetAttribute(attn_mma, cudaFuncAttributeMaxDynamicSharedMemorySize, ATTN_SMEM);

    // layernorm (fp16 hi only)
    ln_half_kernel<<<B_ * NQ_, 256>>>(q, gq, bq, p_qn_hi);
    ln_half_kernel<<<B_ * HW_, 256>>>(kv, gkv, bkv, p_kvn_hi);
    maskpack_kernel<<<B_ * NQ_, 128>>>(mask, p_bits);

    // weight splits (fp16 hi/lo; lo used by small gemms only)
    split_kernel<<<(3072 * 1024 / 4 + 255) / 256, 256>>>(ipw, p_w_hi, p_w_lo, 3072 * 1024 / 4);
    split_kernel<<<(1024 * 1024 / 4 + 255) / 256, 256>>>(ow, p_ow_hi, p_ow_lo, 1024 * 1024 / 4);

    // q projection -> head-major hi (2-pass)
    gemm_mma<1, 2, 4, 4, 2, 2><<<dim3(16, 4), 256, SMEM_S>>>(
        p_qn_hi, p_w_hi, p_w_lo, ipb, nullptr,
        p_qhi, nullptr, B_ * NQ_, 1024);

    // kv projection -> head-major hi K and V (single-pass, BM=256/BN=128, 512 thr)
    gemm_mma<2, 4, 4, 4, 4, 1><<<dim3(16, 64), 512, SMEM_K>>>(
        p_kvn_hi,
        p_w_hi + (size_t)1024 * 1024, nullptr,
        ipb + 1024, nullptr,
        p_khi, p_vhi, B_ * HW_, 2048);

    // attention (split-K, single-pass)
    attn_mma<<<dim3(64, ASPLIT), 256, ATTN_SMEM>>>(
        p_qhi, p_khi, p_vhi, p_bits, p_pm, p_pl, p_pO);

    // merge -> ctx fp16 hi
    merge_kernel<<<(400 * 1024 + 255) / 256, 256>>>(p_pm, p_pl, p_pO, p_cx_hi);

    // output projection (2-pass)
    gemm_mma<0, 2, 4, 4, 2, 2><<<dim3(16, 4), 256, SMEM_S>>>(
        p_cx_hi, p_ow_hi, p_ow_lo, ob, out,
        nullptr, nullptr, B_ * NQ_, 1024);
}